// round 5
// baseline (speedup 1.0000x reference)
#include <cuda_runtime.h>
#include <cuda_fp16.h>
#include <math.h>

#define NATOMS 50000
#define NPAD   50048          // 64-node tiles
#define NEDGE  1600000
#define HDIM   128
#define FDIM   64
#define GDIM   50
#define NLAY   3
#define NGRAPH 256
#define TABN   4096
#define DMAXV  8.6603f        // > 5*sqrt(3) = max possible distance
#define TSTEP  (DMAXV / (TABN - 1))
#define TINV   ((TABN - 1) / DMAXV)

#define SCAN_B 512
#define NCHUNK ((NPAD + SCAN_B - 1) / SCAN_B)   // 98

typedef unsigned long long ull;

// ---- scratch (device globals; no allocation allowed) ----
__device__ float   g_h    [NPAD * HDIM];
__device__ float   g_xt   [NPAD * FDIM];
__device__ __half2 g_xth  [NPAD * FDIM / 2];
__device__ float   g_agg  [NPAD * FDIM];
__device__ float   g_tbuf [NPAD * HDIM];
__device__ float   g_u    [NEDGE];
__device__ __half2 g_tabh [NLAY * TABN * FDIM / 2];
__device__ uint2   g_tabp [NLAY * TABN * FDIM / 2];   // {row i, row i+1} per lane
__device__ int     g_deg  [NPAD];
__device__ int     g_rowptr[NPAD + 1];
__device__ int     g_cursor[NPAD];
__device__ int     g_part [NCHUNK];
__device__ float2  g_erec [NEDGE];     // {src_as_float, u}

__device__ __forceinline__ float sspf(float x) {
    float sp = fmaxf(x, 0.0f) + log1pf(__expf(-fabsf(x)));
    return sp - 0.69314718055994531f;
}

// ---- bit reinterpret helpers (register-level, no-op) ----
__device__ __forceinline__ unsigned h2_as_u(__half2 h) {
    return *reinterpret_cast<unsigned*>(&h);
}
__device__ __forceinline__ __half2 u_as_h2(unsigned u) {
    return *reinterpret_cast<__half2*>(&u);
}

// ---- packed f32x2 helpers (FFMA2 is PTX-only on sm_103a) ----
__device__ __forceinline__ ull ffma2(ull a, ull b, ull c) {
    ull d;
    asm("fma.rn.f32x2 %0, %1, %2, %3;" : "=l"(d) : "l"(a), "l"(b), "l"(c));
    return d;
}
__device__ __forceinline__ ull pack2(float x, float y) {
    ull r;
    asm("mov.b64 %0, {%1, %2};" : "=l"(r) : "f"(x), "f"(y));
    return r;
}
__device__ __forceinline__ float2 unpack2(ull v) {
    float2 r;
    asm("mov.b64 {%0, %1}, %2;" : "=f"(r.x), "=f"(r.y) : "l"(v));
    return r;
}

// ---------------- h = emb[z] (pad rows zeroed) ----------------
__global__ void h_init_kernel(const int* __restrict__ z,
                              const float* __restrict__ emb) {
    int i = blockIdx.x * blockDim.x + threadIdx.x;
    if (i >= NPAD * 32) return;
    int n = i >> 5;
    int c = i & 31;
    float4 v = make_float4(0.f, 0.f, 0.f, 0.f);
    if (n < NATOMS) v = ((const float4*)emb)[__ldg(z + n) * 32 + c];
    ((float4*)g_h)[i] = v;
}

// ---------------- per-edge table coordinate u = d * TINV, + degree ------
__global__ void edge_d_kernel(const int* __restrict__ ei,
                              const float* __restrict__ pos) {
    int e = blockIdx.x * blockDim.x + threadIdx.x;
    if (e >= NEDGE) return;
    int s = __ldg(ei + e);
    int t = __ldg(ei + NEDGE + e);
    float dx = __ldg(pos + s * 3 + 0) - __ldg(pos + t * 3 + 0);
    float dy = __ldg(pos + s * 3 + 1) - __ldg(pos + t * 3 + 1);
    float dz = __ldg(pos + s * 3 + 2) - __ldg(pos + t * 3 + 2);
    g_u[e] = sqrtf(dx * dx + dy * dy + dz * dz) * TINV;
    atomicAdd(&g_deg[t], 1);
}

// ---------------- CSR scan: per-chunk partial sums ----------------------
__global__ void __launch_bounds__(SCAN_B) part_sum_kernel() {
    __shared__ int sh[SCAN_B];
    int idx = blockIdx.x * SCAN_B + threadIdx.x;
    int v = (idx < NPAD) ? g_deg[idx] : 0;
    sh[threadIdx.x] = v;
    __syncthreads();
    for (int s = SCAN_B / 2; s > 0; s >>= 1) {
        if (threadIdx.x < s) sh[threadIdx.x] += sh[threadIdx.x + s];
        __syncthreads();
    }
    if (threadIdx.x == 0) g_part[blockIdx.x] = sh[0];
}

// ---------------- CSR scan: parallel spine (98 values, 1 block) ---------
__global__ void spine_kernel() {
    __shared__ int swp[4];
    int t = threadIdx.x;
    int lane = t & 31, w = t >> 5;
    int v = (t < NCHUNK) ? g_part[t] : 0;
    int s = v;
#pragma unroll
    for (int off = 1; off < 32; off <<= 1) {
        int n = __shfl_up_sync(0xffffffffu, s, off);
        if (lane >= off) s += n;
    }
    if (lane == 31) swp[w] = s;
    __syncthreads();
    if (t < 4) {
        int x = swp[t];
#pragma unroll
        for (int off = 1; off < 4; off <<= 1) {
            int n = __shfl_up_sync(0xfu, x, off);
            if (t >= off) x += n;
        }
        swp[t] = x;
    }
    __syncthreads();
    int excl = s - v + (w > 0 ? swp[w - 1] : 0);
    if (t < NCHUNK) g_part[t] = excl;
    if (t == 0) g_rowptr[NPAD] = NEDGE;
}

// ---------------- CSR scan: write rowptr + cursor -----------------------
__global__ void __launch_bounds__(SCAN_B) scan_write_kernel() {
    __shared__ int sh[SCAN_B];
    int idx = blockIdx.x * SCAN_B + threadIdx.x;
    int own = (idx < NPAD) ? g_deg[idx] : 0;
    sh[threadIdx.x] = own;
    __syncthreads();
    for (int s = 1; s < SCAN_B; s <<= 1) {
        int v = (threadIdx.x >= s) ? sh[threadIdx.x - s] : 0;
        __syncthreads();
        sh[threadIdx.x] += v;
        __syncthreads();
    }
    if (idx < NPAD) {
        int excl = g_part[blockIdx.x] + sh[threadIdx.x] - own;
        g_rowptr[idx] = excl;
        g_cursor[idx] = excl;
    }
}

// ---------------- CSR scatter: pack {src, u} records --------------------
__global__ void scatter_kernel(const int* __restrict__ ei) {
    int e = blockIdx.x * blockDim.x + threadIdx.x;
    if (e >= NEDGE) return;
    int s = __ldg(ei + e);
    int t = __ldg(ei + NEDGE + e);
    int slot = atomicAdd(&g_cursor[t], 1);
    g_erec[slot] = make_float2(__int_as_float(s), g_u[e]);
}

// ---------------- filter lookup tables (shared-mem weights, fp16 out) ---
__global__ void __launch_bounds__(256) build_tab_kernel(
    const float* __restrict__ mw1, const float* __restrict__ mb1,
    const float* __restrict__ mw2, const float* __restrict__ mb2) {
    int layer = blockIdx.y;
    __shared__ float s_w1[GDIM * FDIM];
    __shared__ float s_w2[FDIM * FDIM];
    __shared__ float s_b1[FDIM], s_b2[FDIM];
    __shared__ float s_g[8][64];
    __shared__ float s_act[8][FDIM];

    int t = threadIdx.x;
    for (int i = t; i < GDIM * FDIM; i += 256)
        s_w1[i] = __ldg(mw1 + layer * GDIM * FDIM + i);
    for (int i = t; i < FDIM * FDIM; i += 256)
        s_w2[i] = __ldg(mw2 + layer * FDIM * FDIM + i);
    if (t < FDIM) {
        s_b1[t] = __ldg(mb1 + layer * FDIM + t);
        s_b2[t] = __ldg(mb2 + layer * FDIM + t);
    }
    __syncthreads();

    int wl = t >> 5, lane = t & 31;
    const float offstep = 10.0f / 49.0f;
    const float coeff   = -0.5f / (offstep * offstep);

    for (int ti = blockIdx.x * 8 + wl; ti < TABN; ti += gridDim.x * 8) {
        float dv = ti * TSTEP;
        for (int g = lane; g < GDIM; g += 32) {
            float x = dv - g * offstep;
            s_g[wl][g] = expf(coeff * x * x);
        }
        __syncwarp();

        ull acc = pack2(s_b1[2 * lane], s_b1[2 * lane + 1]);
        for (int g = 0; g < GDIM; g++) {
            float e = s_g[wl][g];
            ull wv = ((const ull*)(s_w1 + g * FDIM))[lane];
            acc = ffma2(pack2(e, e), wv, acc);
        }
        float2 a = unpack2(acc);
        s_act[wl][2 * lane]     = sspf(a.x);
        s_act[wl][2 * lane + 1] = sspf(a.y);
        __syncwarp();

        ull acc2 = pack2(s_b2[2 * lane], s_b2[2 * lane + 1]);
        for (int f = 0; f < FDIM; f++) {
            float tv = s_act[wl][f];
            ull wv = ((const ull*)(s_w2 + f * FDIM))[lane];
            acc2 = ffma2(pack2(tv, tv), wv, acc2);
        }
        float C = 0.5f * (cosf(dv * 3.14159265358979323846f / 10.0f) + 1.0f);
        float2 c2 = unpack2(acc2);
        g_tabh[(layer * TABN + ti) * 32 + lane] =
            __floats2half2_rn(c2.x * C, c2.y * C);
        __syncwarp();
    }
}

// ---------------- pack table rows i and i+1 into uint2 ------------------
__global__ void pack_tab_kernel() {
    int i = blockIdx.x * blockDim.x + threadIdx.x;   // (layer*TABN + row)*32 + lane
    if (i >= NLAY * TABN * 32) return;
    int row  = (i >> 5) % TABN;
    uint2 v;
    v.x = h2_as_u(g_tabh[i]);
    v.y = (row < TABN - 1) ? h2_as_u(g_tabh[i + 32]) : v.x;
    g_tabp[i] = v;
}

// ---------------- zero helper (float4) ----------------
__global__ void zero_kernel(float4* __restrict__ p, int n4) {
    for (int i = blockIdx.x * blockDim.x + threadIdx.x; i < n4;
         i += gridDim.x * blockDim.x)
        p[i] = make_float4(0.f, 0.f, 0.f, 0.f);
}

// ---------------- node GEMM with packed FFMA2, vectorized LDS -----------
template <int IN, int OUT, bool ACT, bool RESID, bool HOUT>
__global__ void __launch_bounds__(256) node_gemm(
    const float* __restrict__ in, const float* __restrict__ w,
    const float* __restrict__ b, float* __restrict__ out) {
    constexpr int TILE = 64;
    constexpr int KT   = 32;
    constexpr int OPT  = OUT / 16;
    constexpr int OP2  = OPT / 2;
    constexpr int NCH  = IN / KT;
    constexpr int SIN_STR = IN + 4;

    __shared__ float sw[KT * OUT];
    __shared__ float sin_[TILE * SIN_STR];

    int t  = threadIdx.x;
    int og = t & 15;
    int np = t >> 4;

    ull bias[OP2];
#pragma unroll
    for (int o = 0; o < OP2; o++)
        bias[o] = b ? pack2(__ldg(b + og * OPT + 2 * o),
                            __ldg(b + og * OPT + 2 * o + 1))
                    : 0ull;

    int tile = blockIdx.x;
    const float* inb = in + tile * TILE * IN;
    for (int i = t; i < TILE * IN / 4; i += 256) {
        int n  = i / (IN / 4);
        int k4 = i % (IN / 4);
        ((float4*)(sin_ + n * SIN_STR))[k4] = ((const float4*)inb)[i];
    }

    ull acc[4][OP2];
#pragma unroll
    for (int i = 0; i < 4; i++)
#pragma unroll
        for (int o = 0; o < OP2; o++) acc[i][o] = bias[o];

#pragma unroll 1
    for (int ch = 0; ch < NCH; ch++) {
        __syncthreads();
        for (int i = t; i < KT * OUT / 4; i += 256)
            ((float4*)sw)[i] = ((const float4*)(w + ch * KT * OUT))[i];
        __syncthreads();
#pragma unroll
        for (int k4 = 0; k4 < KT / 4; k4++) {
            float4 a4[4];
#pragma unroll
            for (int i = 0; i < 4; i++)
                a4[i] = *(const float4*)(sin_ + (np * 4 + i) * SIN_STR +
                                         ch * KT + k4 * 4);
#pragma unroll
            for (int kk = 0; kk < 4; kk++) {
                const longlong2* wr = (const longlong2*)
                    ((const ull*)(sw + (k4 * 4 + kk) * OUT) + og * OP2);
                ull wv[OP2];
#pragma unroll
                for (int o2 = 0; o2 < OP2 / 2; o2++) {
                    longlong2 p = wr[o2];
                    wv[2 * o2]     = (ull)p.x;
                    wv[2 * o2 + 1] = (ull)p.y;
                }
#pragma unroll
                for (int i = 0; i < 4; i++) {
                    float a = (kk == 0) ? a4[i].x : (kk == 1) ? a4[i].y
                            : (kk == 2) ? a4[i].z : a4[i].w;
                    ull pa = pack2(a, a);
#pragma unroll
                    for (int o = 0; o < OP2; o++)
                        acc[i][o] = ffma2(pa, wv[o], acc[i][o]);
                }
            }
        }
    }

#pragma unroll
    for (int i = 0; i < 4; i++) {
        int node = tile * TILE + np * 4 + i;
#pragma unroll
        for (int o = 0; o < OP2; o++) {
            float2 v = unpack2(acc[i][o]);
            if (ACT)  { v.x = sspf(v.x); v.y = sspf(v.y); }
            if (RESID){
                float2 p = ((const float2*)(out + node * OUT + og * OPT))[o];
                v.x += p.x; v.y += p.y;
            }
            if (HOUT) {
                ((__half2*)out)[node * (OUT / 2) + og * OP2 + o] =
                    __floats2half2_rn(v.x, v.y);
            } else {
                ((float2*)(out + node * OUT + og * OPT))[o] = v;
            }
        }
    }
}

// ---------------- gather aggregation: warp per node ---------------------
// Records fetched coalesced (one per lane), broadcast via shfl.
__global__ void __launch_bounds__(256) gather_kernel(
    const uint2* __restrict__ tab) {
    int gw   = (blockIdx.x * blockDim.x + threadIdx.x) >> 5;
    int lane = threadIdx.x & 31;
    if (gw >= NPAD) return;

    int beg = g_rowptr[gw];
    int end = g_rowptr[gw + 1];

    float2 acc = make_float2(0.f, 0.f);
    for (int base = beg; base < end; base += 32) {
        int cnt = min(32, end - base);
        float2 myrec = make_float2(0.f, 0.f);
        if (lane < cnt) myrec = __ldg(&g_erec[base + lane]);
        int   ms = __float_as_int(myrec.x);
        float mu = myrec.y;
#pragma unroll 4
        for (int j = 0; j < cnt; j++) {
            int   s = __shfl_sync(0xffffffffu, ms, j);
            float u = __shfl_sync(0xffffffffu, mu, j);
            int   i0 = min((int)u, TABN - 2);
            float fr = u - (float)i0;

            uint2 tv = __ldg(tab + i0 * 32 + lane);
            float2 fa = __half22float2(u_as_h2(tv.x));
            float2 fb = __half22float2(u_as_h2(tv.y));
            float2 fx = __half22float2(__ldg(&g_xth[s * 32 + lane]));

            acc.x = fmaf(fx.x, fmaf(fr, fb.x - fa.x, fa.x), acc.x);
            acc.y = fmaf(fx.y, fmaf(fr, fb.y - fa.y, fa.y), acc.y);
        }
    }
    ((float2*)g_agg)[gw * 32 + lane] = acc;
}

// ---------------- readout: per-node scalar + per-graph atomic sum -------
__global__ void readout_kernel(const float* __restrict__ ow2,
                               const float* __restrict__ ob2,
                               const int* __restrict__ batch,
                               float* __restrict__ out) {
    int gt   = blockIdx.x * blockDim.x + threadIdx.x;
    int n    = gt >> 5;
    int lane = gt & 31;
    if (n >= NATOMS) return;
    float2 v = ((const float2*)g_xt)[n * 32 + lane];
    float2 w = ((const float2*)ow2)[lane];
    float s = v.x * w.x + v.y * w.y;
#pragma unroll
    for (int off = 16; off; off >>= 1)
        s += __shfl_down_sync(0xffffffffu, s, off);
    if (lane == 0)
        atomicAdd(out + __ldg(batch + n), s + __ldg(ob2));
}

extern "C" void kernel_launch(void* const* d_in, const int* in_sizes, int n_in,
                              void* d_out, int out_size) {
    const int*   z     = (const int*)  d_in[0];
    const float* pos   = (const float*)d_in[1];
    const int*   batch = (const int*)  d_in[2];
    const int*   eidx  = (const int*)  d_in[3];
    const float* emb   = (const float*)d_in[4];
    const float* mw1   = (const float*)d_in[5];
    const float* mb1   = (const float*)d_in[6];
    const float* mw2   = (const float*)d_in[7];
    const float* mb2   = (const float*)d_in[8];
    const float* l1w   = (const float*)d_in[9];
    const float* l2w   = (const float*)d_in[10];
    const float* l2b   = (const float*)d_in[11];
    const float* lw    = (const float*)d_in[12];
    const float* lb    = (const float*)d_in[13];
    const float* ow1   = (const float*)d_in[14];
    const float* ob1   = (const float*)d_in[15];
    const float* ow2   = (const float*)d_in[16];
    const float* ob2   = (const float*)d_in[17];
    float* out = (float*)d_out;

    float *ph, *pxt, *pagg, *ptb, *pdeg;
    __half2 *pxth;
    uint2 *ptabp;
    cudaGetSymbolAddress((void**)&ph,    g_h);
    cudaGetSymbolAddress((void**)&pxt,   g_xt);
    cudaGetSymbolAddress((void**)&pxth,  g_xth);
    cudaGetSymbolAddress((void**)&pagg,  g_agg);
    cudaGetSymbolAddress((void**)&ptb,   g_tbuf);
    cudaGetSymbolAddress((void**)&ptabp, g_tabp);
    cudaGetSymbolAddress((void**)&pdeg,  g_deg);

    // prologue
    zero_kernel<<<1, 64>>>((float4*)out, NGRAPH / 4);
    zero_kernel<<<64, 256>>>((float4*)pdeg, NPAD / 4);
    h_init_kernel<<<(NPAD * 32 + 255) / 256, 256>>>(z, emb);
    edge_d_kernel<<<(NEDGE + 255) / 256, 256>>>(eidx, pos);
    // CSR build
    part_sum_kernel<<<NCHUNK, SCAN_B>>>();
    spine_kernel<<<1, 128>>>();
    scan_write_kernel<<<NCHUNK, SCAN_B>>>();
    scatter_kernel<<<(NEDGE + 255) / 256, 256>>>(eidx);
    // filter tables
    {
        dim3 g(192, NLAY);
        build_tab_kernel<<<g, 256>>>(mw1, mb1, mw2, mb2);
    }
    pack_tab_kernel<<<(NLAY * TABN * 32 + 255) / 256, 256>>>();

    const int NTILES = NPAD / 64;                        // 782
    const int GATHER_BLOCKS = (NPAD * 32 + 255) / 256;   // 6256

    for (int l = 0; l < NLAY; l++) {
        // xth = h @ l1w[l]  (fp16 output for gather)
        node_gemm<128, 64, false, false, true><<<NTILES, 256>>>(
            ph, l1w + l * HDIM * FDIM, nullptr, (float*)pxth);
        // agg[n] = sum over incoming edges (CSR gather, no atomics)
        gather_kernel<<<GATHER_BLOCKS, 256>>>(ptabp + l * TABN * 32);
        // tbuf = ssp(agg @ l2w[l] + l2b[l])
        node_gemm<64, 128, true, false, false><<<NTILES, 256>>>(
            pagg, l2w + l * FDIM * HDIM, l2b + l * HDIM, ptb);
        // h += tbuf @ lw[l] + lb[l]
        node_gemm<128, 128, false, true, false><<<NTILES, 256>>>(
            ptb, lw + l * HDIM * HDIM, lb + l * HDIM, ph);
    }

    // output MLP stage 1: xt = ssp(h @ ow1 + ob1)
    node_gemm<128, 64, true, false, false><<<NTILES, 256>>>(ph, ow1, ob1, pxt);
    // stage 2 + per-graph segment sum
    readout_kernel<<<(NATOMS * 32 + 255) / 256, 256>>>(ow2, ob2, batch, out);
}

// round 6
// speedup vs baseline: 1.8393x; 1.8393x over previous
#include <cuda_runtime.h>
#include <cuda_fp16.h>
#include <math.h>

#define NATOMS 50000
#define NPAD   50048          // 64-node tiles (782 tiles)
#define NTILES (NPAD / 64)
#define NEDGE  1600000
#define HDIM   128
#define FDIM   64
#define GDIM   50
#define NLAY   3
#define NGRAPH 256
#define TABN   4096
#define DMAXV  8.6603f        // > 5*sqrt(3) = max possible distance
#define TSTEP  (DMAXV / (TABN - 1))
#define TINV   ((TABN - 1) / DMAXV)

#define SCAN_B 512
#define NCHUNK ((NPAD + SCAN_B - 1) / SCAN_B)   // 98

typedef unsigned long long ull;

// ---- scratch (device globals; no allocation allowed) ----
__device__ float   g_h    [NPAD * HDIM];
__device__ float   g_xt   [NPAD * FDIM];
__device__ __half2 g_xth  [NPAD * FDIM / 2];
__device__ float   g_agg  [NPAD * FDIM];
__device__ float   g_tbuf [NPAD * HDIM];
__device__ float   g_u    [NEDGE];
__device__ __half2 g_tabh [NLAY * TABN * FDIM / 2];
__device__ uint2   g_tabp [NLAY * TABN * FDIM / 2];
__device__ int     g_deg  [NPAD];
__device__ int     g_rowptr[NPAD + 1];
__device__ int     g_cursor[NPAD];
__device__ int     g_part [NCHUNK];
__device__ float2  g_erec [NEDGE];     // {src_as_float, u}
// weight fragments (fp16, mma B-fragment order):
// layer l at l*32768: w1(0, 8192), w2(8192, 8192), w3(16384, 16384); ow1 at 98304
__device__ __half  g_wfrag[106496];

__device__ __forceinline__ float sspf(float x) {
    float sp = fmaxf(x, 0.0f) + log1pf(__expf(-fabsf(x)));
    return sp - 0.69314718055994531f;
}
__device__ __forceinline__ unsigned h2_as_u(__half2 h) {
    return *reinterpret_cast<unsigned*>(&h);
}
__device__ __forceinline__ __half2 u_as_h2(unsigned u) {
    return *reinterpret_cast<__half2*>(&u);
}
__device__ __forceinline__ unsigned smem_u32(const void* p) {
    return (unsigned)__cvta_generic_to_shared(p);
}

// ---- packed f32x2 helpers (FFMA2 is PTX-only on sm_103a) ----
__device__ __forceinline__ ull ffma2(ull a, ull b, ull c) {
    ull d;
    asm("fma.rn.f32x2 %0, %1, %2, %3;" : "=l"(d) : "l"(a), "l"(b), "l"(c));
    return d;
}
__device__ __forceinline__ ull pack2(float x, float y) {
    ull r;
    asm("mov.b64 %0, {%1, %2};" : "=l"(r) : "f"(x), "f"(y));
    return r;
}
__device__ __forceinline__ float2 unpack2(ull v) {
    float2 r;
    asm("mov.b64 {%0, %1}, %2;" : "=f"(r.x), "=f"(r.y) : "l"(v));
    return r;
}

// ---------------- h = emb[z] (pad rows zeroed) ----------------
__global__ void h_init_kernel(const int* __restrict__ z,
                              const float* __restrict__ emb) {
    int i = blockIdx.x * blockDim.x + threadIdx.x;
    if (i >= NPAD * 32) return;
    int n = i >> 5;
    int c = i & 31;
    float4 v = make_float4(0.f, 0.f, 0.f, 0.f);
    if (n < NATOMS) v = ((const float4*)emb)[__ldg(z + n) * 32 + c];
    ((float4*)g_h)[i] = v;
}

// ---------------- per-edge table coordinate u, + degree -----------------
__global__ void edge_d_kernel(const int* __restrict__ ei,
                              const float* __restrict__ pos) {
    int e = blockIdx.x * blockDim.x + threadIdx.x;
    if (e >= NEDGE) return;
    int s = __ldg(ei + e);
    int t = __ldg(ei + NEDGE + e);
    float dx = __ldg(pos + s * 3 + 0) - __ldg(pos + t * 3 + 0);
    float dy = __ldg(pos + s * 3 + 1) - __ldg(pos + t * 3 + 1);
    float dz = __ldg(pos + s * 3 + 2) - __ldg(pos + t * 3 + 2);
    g_u[e] = sqrtf(dx * dx + dy * dy + dz * dz) * TINV;
    atomicAdd(&g_deg[t], 1);
}

// ---------------- CSR scan pieces ----------------
__global__ void __launch_bounds__(SCAN_B) part_sum_kernel() {
    __shared__ int sh[SCAN_B];
    int idx = blockIdx.x * SCAN_B + threadIdx.x;
    int v = (idx < NPAD) ? g_deg[idx] : 0;
    sh[threadIdx.x] = v;
    __syncthreads();
    for (int s = SCAN_B / 2; s > 0; s >>= 1) {
        if (threadIdx.x < s) sh[threadIdx.x] += sh[threadIdx.x + s];
        __syncthreads();
    }
    if (threadIdx.x == 0) g_part[blockIdx.x] = sh[0];
}

__global__ void spine_kernel() {
    __shared__ int swp[4];
    int t = threadIdx.x;
    int lane = t & 31, w = t >> 5;
    int v = (t < NCHUNK) ? g_part[t] : 0;
    int s = v;
#pragma unroll
    for (int off = 1; off < 32; off <<= 1) {
        int n = __shfl_up_sync(0xffffffffu, s, off);
        if (lane >= off) s += n;
    }
    if (lane == 31) swp[w] = s;
    __syncthreads();
    if (t < 4) {
        int x = swp[t];
#pragma unroll
        for (int off = 1; off < 4; off <<= 1) {
            int n = __shfl_up_sync(0xfu, x, off);
            if (t >= off) x += n;
        }
        swp[t] = x;
    }
    __syncthreads();
    int excl = s - v + (w > 0 ? swp[w - 1] : 0);
    if (t < NCHUNK) g_part[t] = excl;
    if (t == 0) g_rowptr[NPAD] = NEDGE;
}

__global__ void __launch_bounds__(SCAN_B) scan_write_kernel() {
    __shared__ int sh[SCAN_B];
    int idx = blockIdx.x * SCAN_B + threadIdx.x;
    int own = (idx < NPAD) ? g_deg[idx] : 0;
    sh[threadIdx.x] = own;
    __syncthreads();
    for (int s = 1; s < SCAN_B; s <<= 1) {
        int v = (threadIdx.x >= s) ? sh[threadIdx.x - s] : 0;
        __syncthreads();
        sh[threadIdx.x] += v;
        __syncthreads();
    }
    if (idx < NPAD) {
        int excl = g_part[blockIdx.x] + sh[threadIdx.x] - own;
        g_rowptr[idx] = excl;
        g_cursor[idx] = excl;
    }
}

__global__ void scatter_kernel(const int* __restrict__ ei) {
    int e = blockIdx.x * blockDim.x + threadIdx.x;
    if (e >= NEDGE) return;
    int s = __ldg(ei + e);
    int t = __ldg(ei + NEDGE + e);
    int slot = atomicAdd(&g_cursor[t], 1);
    g_erec[slot] = make_float2(__int_as_float(s), g_u[e]);
}

// ---------------- filter lookup tables ----------------------------------
__global__ void __launch_bounds__(256) build_tab_kernel(
    const float* __restrict__ mw1, const float* __restrict__ mb1,
    const float* __restrict__ mw2, const float* __restrict__ mb2) {
    int layer = blockIdx.y;
    __shared__ float s_w1[GDIM * FDIM];
    __shared__ float s_w2[FDIM * FDIM];
    __shared__ float s_b1[FDIM], s_b2[FDIM];
    __shared__ float s_g[8][64];
    __shared__ float s_act[8][FDIM];

    int t = threadIdx.x;
    for (int i = t; i < GDIM * FDIM; i += 256)
        s_w1[i] = __ldg(mw1 + layer * GDIM * FDIM + i);
    for (int i = t; i < FDIM * FDIM; i += 256)
        s_w2[i] = __ldg(mw2 + layer * FDIM * FDIM + i);
    if (t < FDIM) {
        s_b1[t] = __ldg(mb1 + layer * FDIM + t);
        s_b2[t] = __ldg(mb2 + layer * FDIM + t);
    }
    __syncthreads();

    int wl = t >> 5, lane = t & 31;
    const float offstep = 10.0f / 49.0f;
    const float coeff   = -0.5f / (offstep * offstep);

    for (int ti = blockIdx.x * 8 + wl; ti < TABN; ti += gridDim.x * 8) {
        float dv = ti * TSTEP;
        for (int g = lane; g < GDIM; g += 32) {
            float x = dv - g * offstep;
            s_g[wl][g] = expf(coeff * x * x);
        }
        __syncwarp();

        ull acc = pack2(s_b1[2 * lane], s_b1[2 * lane + 1]);
        for (int g = 0; g < GDIM; g++) {
            float e = s_g[wl][g];
            ull wv = ((const ull*)(s_w1 + g * FDIM))[lane];
            acc = ffma2(pack2(e, e), wv, acc);
        }
        float2 a = unpack2(acc);
        s_act[wl][2 * lane]     = sspf(a.x);
        s_act[wl][2 * lane + 1] = sspf(a.y);
        __syncwarp();

        ull acc2 = pack2(s_b2[2 * lane], s_b2[2 * lane + 1]);
        for (int f = 0; f < FDIM; f++) {
            float tv = s_act[wl][f];
            ull wv = ((const ull*)(s_w2 + f * FDIM))[lane];
            acc2 = ffma2(pack2(tv, tv), wv, acc2);
        }
        float C = 0.5f * (cosf(dv * 3.14159265358979323846f / 10.0f) + 1.0f);
        float2 c2 = unpack2(acc2);
        g_tabh[(layer * TABN + ti) * 32 + lane] =
            __floats2half2_rn(c2.x * C, c2.y * C);
        __syncwarp();
    }
}

__global__ void pack_tab_kernel() {
    int i = blockIdx.x * blockDim.x + threadIdx.x;
    if (i >= NLAY * TABN * 32) return;
    int row  = (i >> 5) % TABN;
    uint2 v;
    v.x = h2_as_u(g_tabh[i]);
    v.y = (row < TABN - 1) ? h2_as_u(g_tabh[i + 32]) : v.x;
    g_tabp[i] = v;
}

// ---------------- weight -> mma B-fragment converter --------------------
struct WConvDesc { const float* src; int ind; int outd; int dstoff; };
struct WConvPack { WConvDesc d[10]; };

__global__ void wconv_kernel(WConvPack p) {
    WConvDesc dd = p.d[blockIdx.y];
    int total = dd.ind * dd.outd / 4;
    int u = blockIdx.x * blockDim.x + threadIdx.x;
    if (u >= total) return;
    int lane = u & 31;
    int ot8  = dd.outd >> 3;
    int nt   = (u >> 5) % ot8;
    int ks   = (u >> 5) / ot8;
    int n  = nt * 8 + (lane >> 2);
    int k0 = ks * 16 + (lane & 3) * 2;
    const float* s = dd.src;
    __half2 lo = __floats2half2_rn(s[k0 * dd.outd + n], s[(k0 + 1) * dd.outd + n]);
    __half2 hi = __floats2half2_rn(s[(k0 + 8) * dd.outd + n], s[(k0 + 9) * dd.outd + n]);
    __half2* dst = (__half2*)(g_wfrag + dd.dstoff + u * 4);
    dst[0] = lo;
    dst[1] = hi;
}

// ---------------- zero helper ----------------
__global__ void zero_kernel(float4* __restrict__ p, int n4) {
    for (int i = blockIdx.x * blockDim.x + threadIdx.x; i < n4;
         i += gridDim.x * blockDim.x)
        p[i] = make_float4(0.f, 0.f, 0.f, 0.f);
}

// ---------------- tensor-core node GEMM ---------------------------------
// Block = 256 thr (8 warps), 64-node tiles (grid-stride).
// Warp (ng, mg): ng covers 32 output cols (4 n-tiles), mg covers rows.
// B fragments loaded once from pre-shuffled g_wfrag, live in registers.
template <int IN, int OUT, bool ACT, bool RESID, bool FOUT, bool HOUT>
__global__ void __launch_bounds__(256, 2) mma_gemm(
    const float* __restrict__ in, const __half* __restrict__ wfrag,
    const float* __restrict__ bias_p, float* __restrict__ out,
    __half2* __restrict__ outh) {
    constexpr int NG  = OUT / 32;      // 2 or 4 n-groups
    constexpr int MT  = NG / 2;        // m-tiles per warp (1 or 2)
    constexpr int KS  = IN / 16;
    constexpr int STR = IN + 8;        // halfs per smem row
    __shared__ __half sA[64 * STR];

    int t = threadIdx.x, lane = t & 31, w = t >> 5;
    int ng = w % NG, mg = w / NG;

    // B fragments: [ntile][kstep][2]
    unsigned bf[4 * KS * 2];
    {
        const ull* wf = (const ull*)wfrag;
#pragma unroll
        for (int nt = 0; nt < 4; nt++)
#pragma unroll
            for (int ks = 0; ks < KS; ks++) {
                ull v = __ldg(wf + (ks * (OUT / 8) + ng * 4 + nt) * 32 + lane);
                bf[(nt * KS + ks) * 2]     = (unsigned)(v & 0xffffffffu);
                bf[(nt * KS + ks) * 2 + 1] = (unsigned)(v >> 32);
            }
    }
    float2 bs[4];
#pragma unroll
    for (int nt = 0; nt < 4; nt++) {
        int c = ng * 32 + nt * 8 + (lane & 3) * 2;
        bs[nt] = bias_p ? make_float2(__ldg(bias_p + c), __ldg(bias_p + c + 1))
                        : make_float2(0.f, 0.f);
    }

    int grp    = lane >> 3;
    int arow_l = (lane & 7) + ((grp & 1) << 3);
    int acolh  = (grp >> 1) << 3;

    for (int tile = blockIdx.x; tile < NTILES; tile += gridDim.x) {
        // stage + convert fp32 -> fp16
        const float4* src = (const float4*)(in + tile * 64 * IN);
        for (int i = t; i < 64 * IN / 4; i += 256) {
            int m = i / (IN / 4), k4 = i % (IN / 4);
            float4 v = src[i];
            __half2* d = (__half2*)(sA + m * STR + k4 * 4);
            d[0] = __floats2half2_rn(v.x, v.y);
            d[1] = __floats2half2_rn(v.z, v.w);
        }
        __syncthreads();

#pragma unroll
        for (int mt = 0; mt < MT; mt++) {
            int mrow = (NG == 4) ? (mg * 32 + mt * 16) : (mg * 16);
            float acc[4][4];
#pragma unroll
            for (int nt = 0; nt < 4; nt++) {
                acc[nt][0] = bs[nt].x; acc[nt][1] = bs[nt].y;
                acc[nt][2] = bs[nt].x; acc[nt][3] = bs[nt].y;
            }
            unsigned abase = smem_u32(sA + (mrow + arow_l) * STR + acolh);
#pragma unroll
            for (int ks = 0; ks < KS; ks++) {
                unsigned a0, a1, a2, a3;
                asm volatile(
                    "ldmatrix.sync.aligned.m8n8.x4.shared.b16 {%0,%1,%2,%3}, [%4];"
                    : "=r"(a0), "=r"(a1), "=r"(a2), "=r"(a3)
                    : "r"(abase + ks * 32));
#pragma unroll
                for (int nt = 0; nt < 4; nt++) {
                    asm volatile(
                        "mma.sync.aligned.m16n8k16.row.col.f32.f16.f16.f32 "
                        "{%0,%1,%2,%3}, {%4,%5,%6,%7}, {%8,%9}, {%0,%1,%2,%3};"
                        : "+f"(acc[nt][0]), "+f"(acc[nt][1]),
                          "+f"(acc[nt][2]), "+f"(acc[nt][3])
                        : "r"(a0), "r"(a1), "r"(a2), "r"(a3),
                          "r"(bf[(nt * KS + ks) * 2]),
                          "r"(bf[(nt * KS + ks) * 2 + 1]));
                }
            }
            // epilogue: thread owns rows r0, r0+8, cols (c, c+1) per n-tile
            int r0 = tile * 64 + mrow + (lane >> 2);
            int cb = ng * 32 + (lane & 3) * 2;
#pragma unroll
            for (int nt = 0; nt < 4; nt++) {
                int col = cb + nt * 8;
                float2 v0 = make_float2(acc[nt][0], acc[nt][1]);
                float2 v1 = make_float2(acc[nt][2], acc[nt][3]);
                if (ACT) {
                    v0.x = sspf(v0.x); v0.y = sspf(v0.y);
                    v1.x = sspf(v1.x); v1.y = sspf(v1.y);
                }
                if (RESID) {
                    float2 p0 = *(const float2*)(out + r0 * OUT + col);
                    float2 p1 = *(const float2*)(out + (r0 + 8) * OUT + col);
                    v0.x += p0.x; v0.y += p0.y;
                    v1.x += p1.x; v1.y += p1.y;
                }
                if (FOUT) {
                    *(float2*)(out + r0 * OUT + col)       = v0;
                    *(float2*)(out + (r0 + 8) * OUT + col) = v1;
                }
                if (HOUT) {
                    outh[r0 * (OUT / 2) + col / 2]       = __floats2half2_rn(v0.x, v0.y);
                    outh[(r0 + 8) * (OUT / 2) + col / 2] = __floats2half2_rn(v1.x, v1.y);
                }
            }
        }
        __syncthreads();
    }
}

// ---------------- gather aggregation: warp per node ---------------------
__global__ void __launch_bounds__(256) gather_kernel(
    const uint2* __restrict__ tab) {
    int gw   = (blockIdx.x * blockDim.x + threadIdx.x) >> 5;
    int lane = threadIdx.x & 31;
    if (gw >= NPAD) return;

    int beg = g_rowptr[gw];
    int end = g_rowptr[gw + 1];

    float2 acc = make_float2(0.f, 0.f);
    for (int base = beg; base < end; base += 32) {
        int cnt = min(32, end - base);
        float2 myrec = make_float2(0.f, 0.f);
        if (lane < cnt) myrec = __ldg(&g_erec[base + lane]);
        int   ms = __float_as_int(myrec.x);
        float mu = myrec.y;
#pragma unroll 4
        for (int j = 0; j < cnt; j++) {
            int   s = __shfl_sync(0xffffffffu, ms, j);
            float u = __shfl_sync(0xffffffffu, mu, j);
            int   i0 = min((int)u, TABN - 2);
            float fr = u - (float)i0;

            uint2 tv = __ldg(tab + i0 * 32 + lane);
            float2 fa = __half22float2(u_as_h2(tv.x));
            float2 fb = __half22float2(u_as_h2(tv.y));
            float2 fx = __half22float2(__ldg(&g_xth[s * 32 + lane]));

            acc.x = fmaf(fx.x, fmaf(fr, fb.x - fa.x, fa.x), acc.x);
            acc.y = fmaf(fx.y, fmaf(fr, fb.y - fa.y, fa.y), acc.y);
        }
    }
    ((float2*)g_agg)[gw * 32 + lane] = acc;
}

// ---------------- readout ----------------
__global__ void readout_kernel(const float* __restrict__ ow2,
                               const float* __restrict__ ob2,
                               const int* __restrict__ batch,
                               float* __restrict__ out) {
    int gt   = blockIdx.x * blockDim.x + threadIdx.x;
    int n    = gt >> 5;
    int lane = gt & 31;
    if (n >= NATOMS) return;
    float2 v = ((const float2*)g_xt)[n * 32 + lane];
    float2 w = ((const float2*)ow2)[lane];
    float s = v.x * w.x + v.y * w.y;
#pragma unroll
    for (int off = 16; off; off >>= 1)
        s += __shfl_down_sync(0xffffffffu, s, off);
    if (lane == 0)
        atomicAdd(out + __ldg(batch + n), s + __ldg(ob2));
}

extern "C" void kernel_launch(void* const* d_in, const int* in_sizes, int n_in,
                              void* d_out, int out_size) {
    const int*   z     = (const int*)  d_in[0];
    const float* pos   = (const float*)d_in[1];
    const int*   batch = (const int*)  d_in[2];
    const int*   eidx  = (const int*)  d_in[3];
    const float* emb   = (const float*)d_in[4];
    const float* mw1   = (const float*)d_in[5];
    const float* mb1   = (const float*)d_in[6];
    const float* mw2   = (const float*)d_in[7];
    const float* mb2   = (const float*)d_in[8];
    const float* l1w   = (const float*)d_in[9];
    const float* l2w   = (const float*)d_in[10];
    const float* l2b   = (const float*)d_in[11];
    const float* lw    = (const float*)d_in[12];
    const float* lb    = (const float*)d_in[13];
    const float* ow1   = (const float*)d_in[14];
    const float* ob1   = (const float*)d_in[15];
    const float* ow2   = (const float*)d_in[16];
    const float* ob2   = (const float*)d_in[17];
    float* out = (float*)d_out;

    float *ph, *pxt, *pagg, *ptb, *pdeg;
    __half2 *pxth;
    uint2 *ptabp;
    __half *pwf;
    cudaGetSymbolAddress((void**)&ph,    g_h);
    cudaGetSymbolAddress((void**)&pxt,   g_xt);
    cudaGetSymbolAddress((void**)&pxth,  g_xth);
    cudaGetSymbolAddress((void**)&pagg,  g_agg);
    cudaGetSymbolAddress((void**)&ptb,   g_tbuf);
    cudaGetSymbolAddress((void**)&ptabp, g_tabp);
    cudaGetSymbolAddress((void**)&pdeg,  g_deg);
    cudaGetSymbolAddress((void**)&pwf,   g_wfrag);

    // prologue
    zero_kernel<<<1, 64>>>((float4*)out, NGRAPH / 4);
    zero_kernel<<<64, 256>>>((float4*)pdeg, NPAD / 4);
    h_init_kernel<<<(NPAD * 32 + 255) / 256, 256>>>(z, emb);
    edge_d_kernel<<<(NEDGE + 255) / 256, 256>>>(eidx, pos);
    // CSR build
    part_sum_kernel<<<NCHUNK, SCAN_B>>>();
    spine_kernel<<<1, 128>>>();
    scan_write_kernel<<<NCHUNK, SCAN_B>>>();
    scatter_kernel<<<(NEDGE + 255) / 256, 256>>>(eidx);
    // filter tables
    {
        dim3 g(192, NLAY);
        build_tab_kernel<<<g, 256>>>(mw1, mb1, mw2, mb2);
    }
    pack_tab_kernel<<<(NLAY * TABN * 32 + 255) / 256, 256>>>();
    // weight fragment conversion (all 10 matrices at once)
    {
        WConvPack p;
        for (int l = 0; l < NLAY; l++) {
            p.d[l]     = { l1w + l * HDIM * FDIM, HDIM, FDIM, l * 32768 };
            p.d[3 + l] = { l2w + l * FDIM * HDIM, FDIM, HDIM, l * 32768 + 8192 };
            p.d[6 + l] = { lw  + l * HDIM * HDIM, HDIM, HDIM, l * 32768 + 16384 };
        }
        p.d[9] = { ow1, HDIM, FDIM, 98304 };
        dim3 g(16, 10);
        wconv_kernel<<<g, 256>>>(p);
    }

    const int GB = 296;                                  // mma_gemm grid
    const int GATHER_BLOCKS = (NPAD * 32 + 255) / 256;   // 6256

    for (int l = 0; l < NLAY; l++) {
        // xth = h @ l1w[l]   (fp16 out only)
        mma_gemm<128, 64, false, false, false, true><<<GB, 256>>>(
            ph, pwf + l * 32768, nullptr, pxt, pxth);
        // agg[n] = CSR gather
        gather_kernel<<<GATHER_BLOCKS, 256>>>(ptabp + l * TABN * 32);
        // tbuf = ssp(agg @ l2w[l] + l2b[l])
        mma_gemm<64, 128, true, false, true, false><<<GB, 256>>>(
            pagg, pwf + l * 32768 + 8192, l2b + l * HDIM, ptb, pxth);
        // h += tbuf @ lw[l] + lb[l]
        mma_gemm<128, 128, false, true, true, false><<<GB, 256>>>(
            ptb, pwf + l * 32768 + 16384, lb + l * HDIM, ph, pxth);
    }

    // output MLP stage 1: xt = ssp(h @ ow1 + ob1)
    mma_gemm<128, 64, true, false, true, false><<<GB, 256>>>(
        ph, pwf + 98304, ob1, pxt, pxth);
    // stage 2 + per-graph segment sum
    readout_kernel<<<(NATOMS * 32 + 255) / 256, 256>>>(ow2, ob2, batch, out);
}

// round 7
// speedup vs baseline: 1.8769x; 1.0205x over previous
#include <cuda_runtime.h>
#include <cuda_fp16.h>
#include <math.h>

#define NATOMS 50000
#define NPAD   50048          // 64-node tiles (782 tiles)
#define NTILES (NPAD / 64)
#define NEDGE  1600000
#define HDIM   128
#define FDIM   64
#define GDIM   50
#define NLAY   3
#define NGRAPH 256
#define TABN   1024           // 1024 rows x 64ch fp16 = 128 KB (fits smem)
#define DMAXV  8.6603f        // > 5*sqrt(3) = max possible distance
#define TSTEP  (DMAXV / (TABN - 1))
#define TINV   ((TABN - 1) / DMAXV)

#define SCAN_B 512
#define NCHUNK ((NPAD + SCAN_B - 1) / SCAN_B)   // 98

#define GT_THREADS 1024
#define TAB_BYTES (TABN * FDIM * 2)             // 131072

typedef unsigned long long ull;

// ---- scratch (device globals; no allocation allowed) ----
__device__ float   g_h    [NPAD * HDIM];
__device__ float   g_xt   [NPAD * FDIM];
__device__ __half2 g_xth  [NPAD * FDIM / 2];
__device__ float   g_agg  [NPAD * FDIM];
__device__ float   g_tbuf [NPAD * HDIM];
__device__ __half2 g_tabh [NLAY * TABN * FDIM / 2];
__device__ int     g_deg  [NPAD];
__device__ int     g_rowptr[NPAD + 1];
__device__ int     g_cursor[NPAD];
__device__ int     g_part [NCHUNK];
__device__ float2  g_erec [NEDGE];     // {src_as_float, u}
// weight fragments (fp16, mma B-fragment order):
// layer l at l*32768: w1(0, 8192), w2(8192, 8192), w3(16384, 16384); ow1 at 98304
__device__ __half  g_wfrag[106496];

__device__ __forceinline__ float sspf(float x) {
    float sp = fmaxf(x, 0.0f) + log1pf(__expf(-fabsf(x)));
    return sp - 0.69314718055994531f;
}
__device__ __forceinline__ __half2 u_as_h2(unsigned u) {
    return *reinterpret_cast<__half2*>(&u);
}
__device__ __forceinline__ unsigned smem_u32(const void* p) {
    return (unsigned)__cvta_generic_to_shared(p);
}

// ---- packed f32x2 helpers (FFMA2 is PTX-only on sm_103a) ----
__device__ __forceinline__ ull ffma2(ull a, ull b, ull c) {
    ull d;
    asm("fma.rn.f32x2 %0, %1, %2, %3;" : "=l"(d) : "l"(a), "l"(b), "l"(c));
    return d;
}
__device__ __forceinline__ ull pack2(float x, float y) {
    ull r;
    asm("mov.b64 %0, {%1, %2};" : "=l"(r) : "f"(x), "f"(y));
    return r;
}
__device__ __forceinline__ float2 unpack2(ull v) {
    float2 r;
    asm("mov.b64 {%0, %1}, %2;" : "=f"(r.x), "=f"(r.y) : "l"(v));
    return r;
}

// ---------------- h = emb[z] (pad rows zeroed) ----------------
__global__ void h_init_kernel(const int* __restrict__ z,
                              const float* __restrict__ emb) {
    int i = blockIdx.x * blockDim.x + threadIdx.x;
    if (i >= NPAD * 32) return;
    int n = i >> 5;
    int c = i & 31;
    float4 v = make_float4(0.f, 0.f, 0.f, 0.f);
    if (n < NATOMS) v = ((const float4*)emb)[__ldg(z + n) * 32 + c];
    ((float4*)g_h)[i] = v;
}

// ---------------- degree count ----------------
__global__ void degree_kernel(const int* __restrict__ ei) {
    int e = blockIdx.x * blockDim.x + threadIdx.x;
    if (e >= NEDGE) return;
    atomicAdd(&g_deg[__ldg(ei + NEDGE + e)], 1);
}

// ---------------- CSR scan pieces ----------------
__global__ void __launch_bounds__(SCAN_B) part_sum_kernel() {
    __shared__ int sh[SCAN_B];
    int idx = blockIdx.x * SCAN_B + threadIdx.x;
    int v = (idx < NPAD) ? g_deg[idx] : 0;
    sh[threadIdx.x] = v;
    __syncthreads();
    for (int s = SCAN_B / 2; s > 0; s >>= 1) {
        if (threadIdx.x < s) sh[threadIdx.x] += sh[threadIdx.x + s];
        __syncthreads();
    }
    if (threadIdx.x == 0) g_part[blockIdx.x] = sh[0];
}

__global__ void spine_kernel() {
    __shared__ int swp[4];
    int t = threadIdx.x;
    int lane = t & 31, w = t >> 5;
    int v = (t < NCHUNK) ? g_part[t] : 0;
    int s = v;
#pragma unroll
    for (int off = 1; off < 32; off <<= 1) {
        int n = __shfl_up_sync(0xffffffffu, s, off);
        if (lane >= off) s += n;
    }
    if (lane == 31) swp[w] = s;
    __syncthreads();
    if (t < 4) {
        int x = swp[t];
#pragma unroll
        for (int off = 1; off < 4; off <<= 1) {
            int n = __shfl_up_sync(0xfu, x, off);
            if (t >= off) x += n;
        }
        swp[t] = x;
    }
    __syncthreads();
    int excl = s - v + (w > 0 ? swp[w - 1] : 0);
    if (t < NCHUNK) g_part[t] = excl;
    if (t == 0) g_rowptr[NPAD] = NEDGE;
}

__global__ void __launch_bounds__(SCAN_B) scan_write_kernel() {
    __shared__ int sh[SCAN_B];
    int idx = blockIdx.x * SCAN_B + threadIdx.x;
    int own = (idx < NPAD) ? g_deg[idx] : 0;
    sh[threadIdx.x] = own;
    __syncthreads();
    for (int s = 1; s < SCAN_B; s <<= 1) {
        int v = (threadIdx.x >= s) ? sh[threadIdx.x - s] : 0;
        __syncthreads();
        sh[threadIdx.x] += v;
        __syncthreads();
    }
    if (idx < NPAD) {
        int excl = g_part[blockIdx.x] + sh[threadIdx.x] - own;
        g_rowptr[idx] = excl;
        g_cursor[idx] = excl;
    }
}

// ---------------- CSR scatter: compute u, pack {src, u} -----------------
__global__ void scatter_kernel(const int* __restrict__ ei,
                               const float* __restrict__ pos) {
    int e = blockIdx.x * blockDim.x + threadIdx.x;
    if (e >= NEDGE) return;
    int s = __ldg(ei + e);
    int t = __ldg(ei + NEDGE + e);
    float dx = __ldg(pos + s * 3 + 0) - __ldg(pos + t * 3 + 0);
    float dy = __ldg(pos + s * 3 + 1) - __ldg(pos + t * 3 + 1);
    float dz = __ldg(pos + s * 3 + 2) - __ldg(pos + t * 3 + 2);
    float u = sqrtf(dx * dx + dy * dy + dz * dz) * TINV;
    int slot = atomicAdd(&g_cursor[t], 1);
    g_erec[slot] = make_float2(__int_as_float(s), u);
}

// ---------------- filter lookup tables ----------------------------------
__global__ void __launch_bounds__(256) build_tab_kernel(
    const float* __restrict__ mw1, const float* __restrict__ mb1,
    const float* __restrict__ mw2, const float* __restrict__ mb2) {
    int layer = blockIdx.y;
    __shared__ float s_w1[GDIM * FDIM];
    __shared__ float s_w2[FDIM * FDIM];
    __shared__ float s_b1[FDIM], s_b2[FDIM];
    __shared__ float s_g[8][64];
    __shared__ float s_act[8][FDIM];

    int t = threadIdx.x;
    for (int i = t; i < GDIM * FDIM; i += 256)
        s_w1[i] = __ldg(mw1 + layer * GDIM * FDIM + i);
    for (int i = t; i < FDIM * FDIM; i += 256)
        s_w2[i] = __ldg(mw2 + layer * FDIM * FDIM + i);
    if (t < FDIM) {
        s_b1[t] = __ldg(mb1 + layer * FDIM + t);
        s_b2[t] = __ldg(mb2 + layer * FDIM + t);
    }
    __syncthreads();

    int wl = t >> 5, lane = t & 31;
    const float offstep = 10.0f / 49.0f;
    const float coeff   = -0.5f / (offstep * offstep);

    for (int ti = blockIdx.x * 8 + wl; ti < TABN; ti += gridDim.x * 8) {
        float dv = ti * TSTEP;
        for (int g = lane; g < GDIM; g += 32) {
            float x = dv - g * offstep;
            s_g[wl][g] = expf(coeff * x * x);
        }
        __syncwarp();

        ull acc = pack2(s_b1[2 * lane], s_b1[2 * lane + 1]);
        for (int g = 0; g < GDIM; g++) {
            float e = s_g[wl][g];
            ull wv = ((const ull*)(s_w1 + g * FDIM))[lane];
            acc = ffma2(pack2(e, e), wv, acc);
        }
        float2 a = unpack2(acc);
        s_act[wl][2 * lane]     = sspf(a.x);
        s_act[wl][2 * lane + 1] = sspf(a.y);
        __syncwarp();

        ull acc2 = pack2(s_b2[2 * lane], s_b2[2 * lane + 1]);
        for (int f = 0; f < FDIM; f++) {
            float tv = s_act[wl][f];
            ull wv = ((const ull*)(s_w2 + f * FDIM))[lane];
            acc2 = ffma2(pack2(tv, tv), wv, acc2);
        }
        float C = 0.5f * (cosf(dv * 3.14159265358979323846f / 10.0f) + 1.0f);
        float2 c2 = unpack2(acc2);
        g_tabh[(layer * TABN + ti) * 32 + lane] =
            __floats2half2_rn(c2.x * C, c2.y * C);
        __syncwarp();
    }
}

// ---------------- weight -> mma B-fragment converter --------------------
struct WConvDesc { const float* src; int ind; int outd; int dstoff; };
struct WConvPack { WConvDesc d[10]; };

__global__ void wconv_kernel(WConvPack p) {
    WConvDesc dd = p.d[blockIdx.y];
    int total = dd.ind * dd.outd / 4;
    int u = blockIdx.x * blockDim.x + threadIdx.x;
    if (u >= total) return;
    int lane = u & 31;
    int ot8  = dd.outd >> 3;
    int nt   = (u >> 5) % ot8;
    int ks   = (u >> 5) / ot8;
    int n  = nt * 8 + (lane >> 2);
    int k0 = ks * 16 + (lane & 3) * 2;
    const float* s = dd.src;
    __half2 lo = __floats2half2_rn(s[k0 * dd.outd + n], s[(k0 + 1) * dd.outd + n]);
    __half2 hi = __floats2half2_rn(s[(k0 + 8) * dd.outd + n], s[(k0 + 9) * dd.outd + n]);
    __half2* dst = (__half2*)(g_wfrag + dd.dstoff + u * 4);
    dst[0] = lo;
    dst[1] = hi;
}

// ---------------- zero helper ----------------
__global__ void zero_kernel(float4* __restrict__ p, int n4) {
    for (int i = blockIdx.x * blockDim.x + threadIdx.x; i < n4;
         i += gridDim.x * blockDim.x)
        p[i] = make_float4(0.f, 0.f, 0.f, 0.f);
}

// ---------------- tensor-core node GEMM ---------------------------------
template <int IN, int OUT, bool ACT, bool RESID, bool FOUT, bool HOUT>
__global__ void __launch_bounds__(256, 2) mma_gemm(
    const float* __restrict__ in, const __half* __restrict__ wfrag,
    const float* __restrict__ bias_p, float* __restrict__ out,
    __half2* __restrict__ outh) {
    constexpr int NG  = OUT / 32;      // 2 or 4 n-groups
    constexpr int MT  = NG / 2;        // m-tiles per warp (1 or 2)
    constexpr int KS  = IN / 16;
    constexpr int STR = IN + 8;        // halfs per smem row
    __shared__ __half sA[64 * STR];

    int t = threadIdx.x, lane = t & 31, w = t >> 5;
    int ng = w % NG, mg = w / NG;

    unsigned bf[4 * KS * 2];
    {
        const ull* wf = (const ull*)wfrag;
#pragma unroll
        for (int nt = 0; nt < 4; nt++)
#pragma unroll
            for (int ks = 0; ks < KS; ks++) {
                ull v = __ldg(wf + (ks * (OUT / 8) + ng * 4 + nt) * 32 + lane);
                bf[(nt * KS + ks) * 2]     = (unsigned)(v & 0xffffffffu);
                bf[(nt * KS + ks) * 2 + 1] = (unsigned)(v >> 32);
            }
    }
    float2 bs[4];
#pragma unroll
    for (int nt = 0; nt < 4; nt++) {
        int c = ng * 32 + nt * 8 + (lane & 3) * 2;
        bs[nt] = bias_p ? make_float2(__ldg(bias_p + c), __ldg(bias_p + c + 1))
                        : make_float2(0.f, 0.f);
    }

    int grp    = lane >> 3;
    int arow_l = (lane & 7) + ((grp & 1) << 3);
    int acolh  = (grp >> 1) << 3;

    for (int tile = blockIdx.x; tile < NTILES; tile += gridDim.x) {
        const float4* src = (const float4*)(in + tile * 64 * IN);
        for (int i = t; i < 64 * IN / 4; i += 256) {
            int m = i / (IN / 4), k4 = i % (IN / 4);
            float4 v = src[i];
            __half2* d = (__half2*)(sA + m * STR + k4 * 4);
            d[0] = __floats2half2_rn(v.x, v.y);
            d[1] = __floats2half2_rn(v.z, v.w);
        }
        __syncthreads();

#pragma unroll
        for (int mt = 0; mt < MT; mt++) {
            int mrow = (NG == 4) ? (mg * 32 + mt * 16) : (mg * 16);
            float acc[4][4];
#pragma unroll
            for (int nt = 0; nt < 4; nt++) {
                acc[nt][0] = bs[nt].x; acc[nt][1] = bs[nt].y;
                acc[nt][2] = bs[nt].x; acc[nt][3] = bs[nt].y;
            }
            unsigned abase = smem_u32(sA + (mrow + arow_l) * STR + acolh);
#pragma unroll
            for (int ks = 0; ks < KS; ks++) {
                unsigned a0, a1, a2, a3;
                asm volatile(
                    "ldmatrix.sync.aligned.m8n8.x4.shared.b16 {%0,%1,%2,%3}, [%4];"
                    : "=r"(a0), "=r"(a1), "=r"(a2), "=r"(a3)
                    : "r"(abase + ks * 32));
#pragma unroll
                for (int nt = 0; nt < 4; nt++) {
                    asm volatile(
                        "mma.sync.aligned.m16n8k16.row.col.f32.f16.f16.f32 "
                        "{%0,%1,%2,%3}, {%4,%5,%6,%7}, {%8,%9}, {%0,%1,%2,%3};"
                        : "+f"(acc[nt][0]), "+f"(acc[nt][1]),
                          "+f"(acc[nt][2]), "+f"(acc[nt][3])
                        : "r"(a0), "r"(a1), "r"(a2), "r"(a3),
                          "r"(bf[(nt * KS + ks) * 2]),
                          "r"(bf[(nt * KS + ks) * 2 + 1]));
                }
            }
            int r0 = tile * 64 + mrow + (lane >> 2);
            int cb = ng * 32 + (lane & 3) * 2;
#pragma unroll
            for (int nt = 0; nt < 4; nt++) {
                int col = cb + nt * 8;
                float2 v0 = make_float2(acc[nt][0], acc[nt][1]);
                float2 v1 = make_float2(acc[nt][2], acc[nt][3]);
                if (ACT) {
                    v0.x = sspf(v0.x); v0.y = sspf(v0.y);
                    v1.x = sspf(v1.x); v1.y = sspf(v1.y);
                }
                if (RESID) {
                    float2 p0 = *(const float2*)(out + r0 * OUT + col);
                    float2 p1 = *(const float2*)(out + (r0 + 8) * OUT + col);
                    v0.x += p0.x; v0.y += p0.y;
                    v1.x += p1.x; v1.y += p1.y;
                }
                if (FOUT) {
                    *(float2*)(out + r0 * OUT + col)       = v0;
                    *(float2*)(out + (r0 + 8) * OUT + col) = v1;
                }
                if (HOUT) {
                    outh[r0 * (OUT / 2) + col / 2]       = __floats2half2_rn(v0.x, v0.y);
                    outh[(r0 + 8) * (OUT / 2) + col / 2] = __floats2half2_rn(v1.x, v1.y);
                }
            }
        }
        __syncthreads();
    }
}

// ---------------- gather: smem-resident table, warp per node ------------
// 16 lanes/edge x 4 channels, 2 edges per warp iteration.
__global__ void __launch_bounds__(GT_THREADS) gather_smem_kernel(
    const __half2* __restrict__ tab) {
    extern __shared__ __align__(16) __half s_tab[];   // TABN*64 halfs = 128 KB

    // cooperative table load
    {
        const float4* src = (const float4*)tab;
        float4* dst = (float4*)s_tab;
        for (int i = threadIdx.x; i < TAB_BYTES / 16; i += GT_THREADS)
            dst[i] = src[i];
    }
    __syncthreads();

    int lane = threadIdx.x & 31;
    int hw   = lane >> 4;          // half-warp: which edge of the pair
    int c    = lane & 15;          // channel group (4 channels)
    int warp = threadIdx.x >> 5;
    int gw0  = blockIdx.x * (GT_THREADS / 32) + warp;
    int nw   = gridDim.x * (GT_THREADS / 32);
    const __half* xth = (const __half*)g_xth;

    for (int node = gw0; node < NPAD; node += nw) {
        int beg = g_rowptr[node];
        int end = g_rowptr[node + 1];
        float4 acc = make_float4(0.f, 0.f, 0.f, 0.f);

        for (int base = beg; base < end; base += 32) {
            int cnt = min(32, end - base);
            float2 rec = make_float2(0.f, 0.f);
            if (lane < cnt) rec = __ldg(&g_erec[base + lane]);
            int   ms = __float_as_int(rec.x);
            float mu = rec.y;

#pragma unroll 2
            for (int j = 0; j < cnt; j += 2) {
                int  sl    = j + hw;
                int  s     = __shfl_sync(0xffffffffu, ms, sl);
                float u    = __shfl_sync(0xffffffffu, mu, sl);
                bool valid = sl < cnt;
                int  i0    = min((int)u, TABN - 2);
                float fr   = u - (float)i0;

                uint2 t0 = *(const uint2*)(s_tab + i0 * 64 + c * 4);
                uint2 t1 = *(const uint2*)(s_tab + (i0 + 1) * 64 + c * 4);
                uint2 xv = *(const uint2*)(xth + s * 64 + c * 4);

                float2 a0 = __half22float2(u_as_h2(t0.x));
                float2 a1 = __half22float2(u_as_h2(t0.y));
                float2 b0 = __half22float2(u_as_h2(t1.x));
                float2 b1 = __half22float2(u_as_h2(t1.y));
                float2 x0 = __half22float2(u_as_h2(xv.x));
                float2 x1 = __half22float2(u_as_h2(xv.y));

                if (valid) {
                    acc.x = fmaf(x0.x, fmaf(fr, b0.x - a0.x, a0.x), acc.x);
                    acc.y = fmaf(x0.y, fmaf(fr, b0.y - a0.y, a0.y), acc.y);
                    acc.z = fmaf(x1.x, fmaf(fr, b1.x - a1.x, a1.x), acc.z);
                    acc.w = fmaf(x1.y, fmaf(fr, b1.y - a1.y, a1.y), acc.w);
                }
            }
        }
        // combine the two half-warps (same channels, different edges)
        acc.x += __shfl_xor_sync(0xffffffffu, acc.x, 16);
        acc.y += __shfl_xor_sync(0xffffffffu, acc.y, 16);
        acc.z += __shfl_xor_sync(0xffffffffu, acc.z, 16);
        acc.w += __shfl_xor_sync(0xffffffffu, acc.w, 16);
        if (hw == 0)
            ((float4*)g_agg)[node * 16 + c] = acc;
    }
}

// ---------------- readout ----------------
__global__ void readout_kernel(const float* __restrict__ ow2,
                               const float* __restrict__ ob2,
                               const int* __restrict__ batch,
                               float* __restrict__ out) {
    int gt   = blockIdx.x * blockDim.x + threadIdx.x;
    int n    = gt >> 5;
    int lane = gt & 31;
    if (n >= NATOMS) return;
    float2 v = ((const float2*)g_xt)[n * 32 + lane];
    float2 w = ((const float2*)ow2)[lane];
    float s = v.x * w.x + v.y * w.y;
#pragma unroll
    for (int off = 16; off; off >>= 1)
        s += __shfl_down_sync(0xffffffffu, s, off);
    if (lane == 0)
        atomicAdd(out + __ldg(batch + n), s + __ldg(ob2));
}

extern "C" void kernel_launch(void* const* d_in, const int* in_sizes, int n_in,
                              void* d_out, int out_size) {
    const int*   z     = (const int*)  d_in[0];
    const float* pos   = (const float*)d_in[1];
    const int*   batch = (const int*)  d_in[2];
    const int*   eidx  = (const int*)  d_in[3];
    const float* emb   = (const float*)d_in[4];
    const float* mw1   = (const float*)d_in[5];
    const float* mb1   = (const float*)d_in[6];
    const float* mw2   = (const float*)d_in[7];
    const float* mb2   = (const float*)d_in[8];
    const float* l1w   = (const float*)d_in[9];
    const float* l2w   = (const float*)d_in[10];
    const float* l2b   = (const float*)d_in[11];
    const float* lw    = (const float*)d_in[12];
    const float* lb    = (const float*)d_in[13];
    const float* ow1   = (const float*)d_in[14];
    const float* ob1   = (const float*)d_in[15];
    const float* ow2   = (const float*)d_in[16];
    const float* ob2   = (const float*)d_in[17];
    float* out = (float*)d_out;

    float *ph, *pxt, *pagg, *ptb, *pdeg;
    __half2 *pxth, *ptabh;
    __half *pwf;
    cudaGetSymbolAddress((void**)&ph,    g_h);
    cudaGetSymbolAddress((void**)&pxt,   g_xt);
    cudaGetSymbolAddress((void**)&pxth,  g_xth);
    cudaGetSymbolAddress((void**)&pagg,  g_agg);
    cudaGetSymbolAddress((void**)&ptb,   g_tbuf);
    cudaGetSymbolAddress((void**)&ptabh, g_tabh);
    cudaGetSymbolAddress((void**)&pdeg,  g_deg);
    cudaGetSymbolAddress((void**)&pwf,   g_wfrag);

    static bool attr_done = false;
    if (!attr_done) {
        cudaFuncSetAttribute(gather_smem_kernel,
                             cudaFuncAttributeMaxDynamicSharedMemorySize,
                             TAB_BYTES);
        attr_done = true;
    }

    // prologue
    zero_kernel<<<1, 64>>>((float4*)out, NGRAPH / 4);
    zero_kernel<<<64, 256>>>((float4*)pdeg, NPAD / 4);
    h_init_kernel<<<(NPAD * 32 + 255) / 256, 256>>>(z, emb);
    degree_kernel<<<(NEDGE + 255) / 256, 256>>>(eidx);
    // CSR build
    part_sum_kernel<<<NCHUNK, SCAN_B>>>();
    spine_kernel<<<1, 128>>>();
    scan_write_kernel<<<NCHUNK, SCAN_B>>>();
    scatter_kernel<<<(NEDGE + 255) / 256, 256>>>(eidx, pos);
    // filter tables
    {
        dim3 g(TABN / 8, NLAY);
        build_tab_kernel<<<g, 256>>>(mw1, mb1, mw2, mb2);
    }
    // weight fragment conversion
    {
        WConvPack p;
        for (int l = 0; l < NLAY; l++) {
            p.d[l]     = { l1w + l * HDIM * FDIM, HDIM, FDIM, l * 32768 };
            p.d[3 + l] = { l2w + l * FDIM * HDIM, FDIM, HDIM, l * 32768 + 8192 };
            p.d[6 + l] = { lw  + l * HDIM * HDIM, HDIM, HDIM, l * 32768 + 16384 };
        }
        p.d[9] = { ow1, HDIM, FDIM, 98304 };
        dim3 g(16, 10);
        wconv_kernel<<<g, 256>>>(p);
    }

    const int GB = 296;     // mma_gemm grid
    const int GGB = 148;    // gather grid (1 block/SM, 128KB smem each)

    for (int l = 0; l < NLAY; l++) {
        // xth = h @ l1w[l]   (fp16 out only)
        mma_gemm<128, 64, false, false, false, true><<<GB, 256>>>(
            ph, pwf + l * 32768, nullptr, pxt, pxth);
        // agg[n] = CSR gather with smem table
        gather_smem_kernel<<<GGB, GT_THREADS, TAB_BYTES>>>(ptabh + l * TABN * 32);
        // tbuf = ssp(agg @ l2w[l] + l2b[l])
        mma_gemm<64, 128, true, false, true, false><<<GB, 256>>>(
            pagg, pwf + l * 32768 + 8192, l2b + l * HDIM, ptb, pxth);
        // h += tbuf @ lw[l] + lb[l]
        mma_gemm<128, 128, false, true, true, false><<<GB, 256>>>(
            ptb, pwf + l * 32768 + 16384, lb + l * HDIM, ph, pxth);
    }

    // output MLP stage 1: xt = ssp(h @ ow1 + ob1)
    mma_gemm<128, 64, true, false, true, false><<<GB, 256>>>(
        ph, pwf + 98304, ob1, pxt, pxth);
    // stage 2 + per-graph segment sum
    readout_kernel<<<(NATOMS * 32 + 255) / 256, 256>>>(ow2, ob2, batch, out);
}

// round 8
// speedup vs baseline: 1.8818x; 1.0026x over previous
#include <cuda_runtime.h>
#include <cuda_fp16.h>
#include <math.h>

#define NATOMS 50000
#define NPAD   50048          // 64-node tiles (782 tiles)
#define NTILES (NPAD / 64)
#define NEDGE  1600000
#define HDIM   128
#define FDIM   64
#define GDIM   50
#define NLAY   3
#define NGRAPH 256
#define TABN   1024           // 1024 rows x 64ch fp16 = 128 KB (fits smem)
#define DMAXV  8.6603f        // > 5*sqrt(3) = max possible distance
#define TSTEP  (DMAXV / (TABN - 1))
#define TINV   ((TABN - 1) / DMAXV)

#define SCAN_B 512
#define NCHUNK ((NPAD + SCAN_B - 1) / SCAN_B)   // 98

#define GT_THREADS 1024
#define TAB_BYTES (TABN * FDIM * 2)             // 131072

typedef unsigned long long ull;

// ---- scratch (device globals; no allocation allowed) ----
__device__ float   g_h    [NPAD * HDIM];
__device__ float   g_xt   [NPAD * FDIM];
__device__ __half2 g_xth  [NPAD * FDIM / 2];
__device__ float   g_agg  [NPAD * FDIM];
__device__ float   g_tbuf [NPAD * HDIM];
__device__ __half2 g_tabh [NLAY * TABN * FDIM / 2];
__device__ int     g_deg  [NPAD];
__device__ int     g_rowptr[NPAD + 1];
__device__ int     g_cursor[NPAD];
__device__ int     g_part [NCHUNK];
__device__ float2  g_erec [NEDGE];     // {src_as_float, u}
// weight fragments (fp16, mma B-fragment order):
// layer l at l*32768: w1(0, 8192), w2(8192, 8192), w3(16384, 16384); ow1 at 98304
__device__ __half  g_wfrag[106496];

__device__ __forceinline__ float sspf(float x) {
    float sp = fmaxf(x, 0.0f) + log1pf(__expf(-fabsf(x)));
    return sp - 0.69314718055994531f;
}
__device__ __forceinline__ __half2 u_as_h2(unsigned u) {
    return *reinterpret_cast<__half2*>(&u);
}
__device__ __forceinline__ unsigned smem_u32(const void* p) {
    return (unsigned)__cvta_generic_to_shared(p);
}

// ---- packed f32x2 helpers (FFMA2 is PTX-only on sm_103a) ----
__device__ __forceinline__ ull ffma2(ull a, ull b, ull c) {
    ull d;
    asm("fma.rn.f32x2 %0, %1, %2, %3;" : "=l"(d) : "l"(a), "l"(b), "l"(c));
    return d;
}
__device__ __forceinline__ ull pack2(float x, float y) {
    ull r;
    asm("mov.b64 %0, {%1, %2};" : "=l"(r) : "f"(x), "f"(y));
    return r;
}
__device__ __forceinline__ float2 unpack2(ull v) {
    float2 r;
    asm("mov.b64 {%0, %1}, %2;" : "=f"(r.x), "=f"(r.y) : "l"(v));
    return r;
}

// ---------------- h = emb[z] (pad rows zeroed) ----------------
__global__ void h_init_kernel(const int* __restrict__ z,
                              const float* __restrict__ emb) {
    int i = blockIdx.x * blockDim.x + threadIdx.x;
    if (i >= NPAD * 32) return;
    int n = i >> 5;
    int c = i & 31;
    float4 v = make_float4(0.f, 0.f, 0.f, 0.f);
    if (n < NATOMS) v = ((const float4*)emb)[__ldg(z + n) * 32 + c];
    ((float4*)g_h)[i] = v;
}

// ---------------- degree count ----------------
__global__ void degree_kernel(const int* __restrict__ ei) {
    int e = blockIdx.x * blockDim.x + threadIdx.x;
    if (e >= NEDGE) return;
    atomicAdd(&g_deg[__ldg(ei + NEDGE + e)], 1);
}

// ---------------- CSR scan pieces ----------------
__global__ void __launch_bounds__(SCAN_B) part_sum_kernel() {
    __shared__ int sh[SCAN_B];
    int idx = blockIdx.x * SCAN_B + threadIdx.x;
    int v = (idx < NPAD) ? g_deg[idx] : 0;
    sh[threadIdx.x] = v;
    __syncthreads();
    for (int s = SCAN_B / 2; s > 0; s >>= 1) {
        if (threadIdx.x < s) sh[threadIdx.x] += sh[threadIdx.x + s];
        __syncthreads();
    }
    if (threadIdx.x == 0) g_part[blockIdx.x] = sh[0];
}

__global__ void spine_kernel() {
    __shared__ int swp[4];
    int t = threadIdx.x;
    int lane = t & 31, w = t >> 5;
    int v = (t < NCHUNK) ? g_part[t] : 0;
    int s = v;
#pragma unroll
    for (int off = 1; off < 32; off <<= 1) {
        int n = __shfl_up_sync(0xffffffffu, s, off);
        if (lane >= off) s += n;
    }
    if (lane == 31) swp[w] = s;
    __syncthreads();
    if (t < 4) {
        int x = swp[t];
#pragma unroll
        for (int off = 1; off < 4; off <<= 1) {
            int n = __shfl_up_sync(0xfu, x, off);
            if (t >= off) x += n;
        }
        swp[t] = x;
    }
    __syncthreads();
    int excl = s - v + (w > 0 ? swp[w - 1] : 0);
    if (t < NCHUNK) g_part[t] = excl;
    if (t == 0) g_rowptr[NPAD] = NEDGE;
}

__global__ void __launch_bounds__(SCAN_B) scan_write_kernel() {
    __shared__ int sh[SCAN_B];
    int idx = blockIdx.x * SCAN_B + threadIdx.x;
    int own = (idx < NPAD) ? g_deg[idx] : 0;
    sh[threadIdx.x] = own;
    __syncthreads();
    for (int s = 1; s < SCAN_B; s <<= 1) {
        int v = (threadIdx.x >= s) ? sh[threadIdx.x - s] : 0;
        __syncthreads();
        sh[threadIdx.x] += v;
        __syncthreads();
    }
    if (idx < NPAD) {
        int excl = g_part[blockIdx.x] + sh[threadIdx.x] - own;
        g_rowptr[idx] = excl;
        g_cursor[idx] = excl;
    }
}

// ---------------- CSR scatter: compute u, pack {src, u} -----------------
__global__ void scatter_kernel(const int* __restrict__ ei,
                               const float* __restrict__ pos) {
    int e = blockIdx.x * blockDim.x + threadIdx.x;
    if (e >= NEDGE) return;
    int s = __ldg(ei + e);
    int t = __ldg(ei + NEDGE + e);
    float dx = __ldg(pos + s * 3 + 0) - __ldg(pos + t * 3 + 0);
    float dy = __ldg(pos + s * 3 + 1) - __ldg(pos + t * 3 + 1);
    float dz = __ldg(pos + s * 3 + 2) - __ldg(pos + t * 3 + 2);
    float u = sqrtf(dx * dx + dy * dy + dz * dz) * TINV;
    int slot = atomicAdd(&g_cursor[t], 1);
    g_erec[slot] = make_float2(__int_as_float(s), u);
}

// ---------------- filter lookup tables ----------------------------------
__global__ void __launch_bounds__(256) build_tab_kernel(
    const float* __restrict__ mw1, const float* __restrict__ mb1,
    const float* __restrict__ mw2, const float* __restrict__ mb2) {
    int layer = blockIdx.y;
    __shared__ float s_w1[GDIM * FDIM];
    __shared__ float s_w2[FDIM * FDIM];
    __shared__ float s_b1[FDIM], s_b2[FDIM];
    __shared__ float s_g[8][64];
    __shared__ float s_act[8][FDIM];

    int t = threadIdx.x;
    for (int i = t; i < GDIM * FDIM; i += 256)
        s_w1[i] = __ldg(mw1 + layer * GDIM * FDIM + i);
    for (int i = t; i < FDIM * FDIM; i += 256)
        s_w2[i] = __ldg(mw2 + layer * FDIM * FDIM + i);
    if (t < FDIM) {
        s_b1[t] = __ldg(mb1 + layer * FDIM + t);
        s_b2[t] = __ldg(mb2 + layer * FDIM + t);
    }
    __syncthreads();

    int wl = t >> 5, lane = t & 31;
    const float offstep = 10.0f / 49.0f;
    const float coeff   = -0.5f / (offstep * offstep);

    for (int ti = blockIdx.x * 8 + wl; ti < TABN; ti += gridDim.x * 8) {
        float dv = ti * TSTEP;
        for (int g = lane; g < GDIM; g += 32) {
            float x = dv - g * offstep;
            s_g[wl][g] = expf(coeff * x * x);
        }
        __syncwarp();

        ull acc = pack2(s_b1[2 * lane], s_b1[2 * lane + 1]);
        for (int g = 0; g < GDIM; g++) {
            float e = s_g[wl][g];
            ull wv = ((const ull*)(s_w1 + g * FDIM))[lane];
            acc = ffma2(pack2(e, e), wv, acc);
        }
        float2 a = unpack2(acc);
        s_act[wl][2 * lane]     = sspf(a.x);
        s_act[wl][2 * lane + 1] = sspf(a.y);
        __syncwarp();

        ull acc2 = pack2(s_b2[2 * lane], s_b2[2 * lane + 1]);
        for (int f = 0; f < FDIM; f++) {
            float tv = s_act[wl][f];
            ull wv = ((const ull*)(s_w2 + f * FDIM))[lane];
            acc2 = ffma2(pack2(tv, tv), wv, acc2);
        }
        float C = 0.5f * (cosf(dv * 3.14159265358979323846f / 10.0f) + 1.0f);
        float2 c2 = unpack2(acc2);
        g_tabh[(layer * TABN + ti) * 32 + lane] =
            __floats2half2_rn(c2.x * C, c2.y * C);
        __syncwarp();
    }
}

// ---------------- weight -> mma B-fragment converter --------------------
struct WConvDesc { const float* src; int ind; int outd; int dstoff; };
struct WConvPack { WConvDesc d[10]; };

__global__ void wconv_kernel(WConvPack p) {
    WConvDesc dd = p.d[blockIdx.y];
    int total = dd.ind * dd.outd / 4;
    int u = blockIdx.x * blockDim.x + threadIdx.x;
    if (u >= total) return;
    int lane = u & 31;
    int ot8  = dd.outd >> 3;
    int nt   = (u >> 5) % ot8;
    int ks   = (u >> 5) / ot8;
    int n  = nt * 8 + (lane >> 2);
    int k0 = ks * 16 + (lane & 3) * 2;
    const float* s = dd.src;
    __half2 lo = __floats2half2_rn(s[k0 * dd.outd + n], s[(k0 + 1) * dd.outd + n]);
    __half2 hi = __floats2half2_rn(s[(k0 + 8) * dd.outd + n], s[(k0 + 9) * dd.outd + n]);
    __half2* dst = (__half2*)(g_wfrag + dd.dstoff + u * 4);
    dst[0] = lo;
    dst[1] = hi;
}

// ---------------- zero helper ----------------
__global__ void zero_kernel(float4* __restrict__ p, int n4) {
    for (int i = blockIdx.x * blockDim.x + threadIdx.x; i < n4;
         i += gridDim.x * blockDim.x)
        p[i] = make_float4(0.f, 0.f, 0.f, 0.f);
}

// ---------------- tensor-core node GEMM ---------------------------------
template <int IN, int OUT, bool ACT, bool RESID, bool FOUT, bool HOUT>
__global__ void __launch_bounds__(256, 2) mma_gemm(
    const float* __restrict__ in, const __half* __restrict__ wfrag,
    const float* __restrict__ bias_p, float* __restrict__ out,
    __half2* __restrict__ outh) {
    constexpr int NG  = OUT / 32;      // 2 or 4 n-groups
    constexpr int MT  = NG / 2;        // m-tiles per warp (1 or 2)
    constexpr int KS  = IN / 16;
    constexpr int STR = IN + 8;        // halfs per smem row
    __shared__ __half sA[64 * STR];

    int t = threadIdx.x, lane = t & 31, w = t >> 5;
    int ng = w % NG, mg = w / NG;

    unsigned bf[4 * KS * 2];
    {
        const ull* wf = (const ull*)wfrag;
#pragma unroll
        for (int nt = 0; nt < 4; nt++)
#pragma unroll
            for (int ks = 0; ks < KS; ks++) {
                ull v = __ldg(wf + (ks * (OUT / 8) + ng * 4 + nt) * 32 + lane);
                bf[(nt * KS + ks) * 2]     = (unsigned)(v & 0xffffffffu);
                bf[(nt * KS + ks) * 2 + 1] = (unsigned)(v >> 32);
            }
    }
    float2 bs[4];
#pragma unroll
    for (int nt = 0; nt < 4; nt++) {
        int c = ng * 32 + nt * 8 + (lane & 3) * 2;
        bs[nt] = bias_p ? make_float2(__ldg(bias_p + c), __ldg(bias_p + c + 1))
                        : make_float2(0.f, 0.f);
    }

    int grp    = lane >> 3;
    int arow_l = (lane & 7) + ((grp & 1) << 3);
    int acolh  = (grp >> 1) << 3;

    for (int tile = blockIdx.x; tile < NTILES; tile += gridDim.x) {
        const float4* src = (const float4*)(in + tile * 64 * IN);
        for (int i = t; i < 64 * IN / 4; i += 256) {
            int m = i / (IN / 4), k4 = i % (IN / 4);
            float4 v = src[i];
            __half2* d = (__half2*)(sA + m * STR + k4 * 4);
            d[0] = __floats2half2_rn(v.x, v.y);
            d[1] = __floats2half2_rn(v.z, v.w);
        }
        __syncthreads();

#pragma unroll
        for (int mt = 0; mt < MT; mt++) {
            int mrow = (NG == 4) ? (mg * 32 + mt * 16) : (mg * 16);
            float acc[4][4];
#pragma unroll
            for (int nt = 0; nt < 4; nt++) {
                acc[nt][0] = bs[nt].x; acc[nt][1] = bs[nt].y;
                acc[nt][2] = bs[nt].x; acc[nt][3] = bs[nt].y;
            }
            unsigned abase = smem_u32(sA + (mrow + arow_l) * STR + acolh);
#pragma unroll
            for (int ks = 0; ks < KS; ks++) {
                unsigned a0, a1, a2, a3;
                asm volatile(
                    "ldmatrix.sync.aligned.m8n8.x4.shared.b16 {%0,%1,%2,%3}, [%4];"
                    : "=r"(a0), "=r"(a1), "=r"(a2), "=r"(a3)
                    : "r"(abase + ks * 32));
#pragma unroll
                for (int nt = 0; nt < 4; nt++) {
                    asm volatile(
                        "mma.sync.aligned.m16n8k16.row.col.f32.f16.f16.f32 "
                        "{%0,%1,%2,%3}, {%4,%5,%6,%7}, {%8,%9}, {%0,%1,%2,%3};"
                        : "+f"(acc[nt][0]), "+f"(acc[nt][1]),
                          "+f"(acc[nt][2]), "+f"(acc[nt][3])
                        : "r"(a0), "r"(a1), "r"(a2), "r"(a3),
                          "r"(bf[(nt * KS + ks) * 2]),
                          "r"(bf[(nt * KS + ks) * 2 + 1]));
                }
            }
            int r0 = tile * 64 + mrow + (lane >> 2);
            int cb = ng * 32 + (lane & 3) * 2;
#pragma unroll
            for (int nt = 0; nt < 4; nt++) {
                int col = cb + nt * 8;
                float2 v0 = make_float2(acc[nt][0], acc[nt][1]);
                float2 v1 = make_float2(acc[nt][2], acc[nt][3]);
                if (ACT) {
                    v0.x = sspf(v0.x); v0.y = sspf(v0.y);
                    v1.x = sspf(v1.x); v1.y = sspf(v1.y);
                }
                if (RESID) {
                    float2 p0 = *(const float2*)(out + r0 * OUT + col);
                    float2 p1 = *(const float2*)(out + (r0 + 8) * OUT + col);
                    v0.x += p0.x; v0.y += p0.y;
                    v1.x += p1.x; v1.y += p1.y;
                }
                if (FOUT) {
                    *(float2*)(out + r0 * OUT + col)       = v0;
                    *(float2*)(out + (r0 + 8) * OUT + col) = v1;
                }
                if (HOUT) {
                    outh[r0 * (OUT / 2) + col / 2]       = __floats2half2_rn(v0.x, v0.y);
                    outh[(r0 + 8) * (OUT / 2) + col / 2] = __floats2half2_rn(v1.x, v1.y);
                }
            }
        }
        __syncthreads();
    }
}

// ---------------- gather: smem-resident table, warp per node ------------
// 16 lanes/edge x 4 channels, 2 edges per warp iteration.
__global__ void __launch_bounds__(GT_THREADS) gather_smem_kernel(
    const __half2* __restrict__ tab) {
    extern __shared__ __align__(16) __half s_tab[];   // TABN*64 halfs = 128 KB

    // cooperative table load
    {
        const float4* src = (const float4*)tab;
        float4* dst = (float4*)s_tab;
        for (int i = threadIdx.x; i < TAB_BYTES / 16; i += GT_THREADS)
            dst[i] = src[i];
    }
    __syncthreads();

    int lane = threadIdx.x & 31;
    int hw   = lane >> 4;          // half-warp: which edge of the pair
    int c    = lane & 15;          // channel group (4 channels)
    int warp = threadIdx.x >> 5;
    int gw0  = blockIdx.x * (GT_THREADS / 32) + warp;
    int nw   = gridDim.x * (GT_THREADS / 32);
    const __half* xth = (const __half*)g_xth;

    for (int node = gw0; node < NPAD; node += nw) {
        int beg = g_rowptr[node];
        int end = g_rowptr[node + 1];
        float4 acc = make_float4(0.f, 0.f, 0.f, 0.f);

        for (int base = beg; base < end; base += 32) {
            int cnt = min(32, end - base);
            float2 rec = make_float2(0.f, 0.f);
            if (lane < cnt) rec = __ldg(&g_erec[base + lane]);
            int   ms = __float_as_int(rec.x);
            float mu = rec.y;

#pragma unroll 2
            for (int j = 0; j < cnt; j += 2) {
                int  sl    = j + hw;
                int  s     = __shfl_sync(0xffffffffu, ms, sl);
                float u    = __shfl_sync(0xffffffffu, mu, sl);
                bool valid = sl < cnt;
                int  i0    = min((int)u, TABN - 2);
                float fr   = u - (float)i0;

                uint2 t0 = *(const uint2*)(s_tab + i0 * 64 + c * 4);
                uint2 t1 = *(const uint2*)(s_tab + (i0 + 1) * 64 + c * 4);
                uint2 xv = *(const uint2*)(xth + s * 64 + c * 4);

                float2 a0 = __half22float2(u_as_h2(t0.x));
                float2 a1 = __half22float2(u_as_h2(t0.y));
                float2 b0 = __half22float2(u_as_h2(t1.x));
                float2 b1 = __half22float2(u_as_h2(t1.y));
                float2 x0 = __half22float2(u_as_h2(xv.x));
                float2 x1 = __half22float2(u_as_h2(xv.y));

                if (valid) {
                    acc.x = fmaf(x0.x, fmaf(fr, b0.x - a0.x, a0.x), acc.x);
                    acc.y = fmaf(x0.y, fmaf(fr, b0.y - a0.y, a0.y), acc.y);
                    acc.z = fmaf(x1.x, fmaf(fr, b1.x - a1.x, a1.x), acc.z);
                    acc.w = fmaf(x1.y, fmaf(fr, b1.y - a1.y, a1.y), acc.w);
                }
            }
        }
        // combine the two half-warps (same channels, different edges)
        acc.x += __shfl_xor_sync(0xffffffffu, acc.x, 16);
        acc.y += __shfl_xor_sync(0xffffffffu, acc.y, 16);
        acc.z += __shfl_xor_sync(0xffffffffu, acc.z, 16);
        acc.w += __shfl_xor_sync(0xffffffffu, acc.w, 16);
        if (hw == 0)
            ((float4*)g_agg)[node * 16 + c] = acc;
    }
}

// ---------------- readout ----------------
__global__ void readout_kernel(const float* __restrict__ ow2,
                               const float* __restrict__ ob2,
                               const int* __restrict__ batch,
                               float* __restrict__ out) {
    int gt   = blockIdx.x * blockDim.x + threadIdx.x;
    int n    = gt >> 5;
    int lane = gt & 31;
    if (n >= NATOMS) return;
    float2 v = ((const float2*)g_xt)[n * 32 + lane];
    float2 w = ((const float2*)ow2)[lane];
    float s = v.x * w.x + v.y * w.y;
#pragma unroll
    for (int off = 16; off; off >>= 1)
        s += __shfl_down_sync(0xffffffffu, s, off);
    if (lane == 0)
        atomicAdd(out + __ldg(batch + n), s + __ldg(ob2));
}

extern "C" void kernel_launch(void* const* d_in, const int* in_sizes, int n_in,
                              void* d_out, int out_size) {
    const int*   z     = (const int*)  d_in[0];
    const float* pos   = (const float*)d_in[1];
    const int*   batch = (const int*)  d_in[2];
    const int*   eidx  = (const int*)  d_in[3];
    const float* emb   = (const float*)d_in[4];
    const float* mw1   = (const float*)d_in[5];
    const float* mb1   = (const float*)d_in[6];
    const float* mw2   = (const float*)d_in[7];
    const float* mb2   = (const float*)d_in[8];
    const float* l1w   = (const float*)d_in[9];
    const float* l2w   = (const float*)d_in[10];
    const float* l2b   = (const float*)d_in[11];
    const float* lw    = (const float*)d_in[12];
    const float* lb    = (const float*)d_in[13];
    const float* ow1   = (const float*)d_in[14];
    const float* ob1   = (const float*)d_in[15];
    const float* ow2   = (const float*)d_in[16];
    const float* ob2   = (const float*)d_in[17];
    float* out = (float*)d_out;

    float *ph, *pxt, *pagg, *ptb, *pdeg;
    __half2 *pxth, *ptabh;
    __half *pwf;
    cudaGetSymbolAddress((void**)&ph,    g_h);
    cudaGetSymbolAddress((void**)&pxt,   g_xt);
    cudaGetSymbolAddress((void**)&pxth,  g_xth);
    cudaGetSymbolAddress((void**)&pagg,  g_agg);
    cudaGetSymbolAddress((void**)&ptb,   g_tbuf);
    cudaGetSymbolAddress((void**)&ptabh, g_tabh);
    cudaGetSymbolAddress((void**)&pdeg,  g_deg);
    cudaGetSymbolAddress((void**)&pwf,   g_wfrag);

    static bool attr_done = false;
    if (!attr_done) {
        cudaFuncSetAttribute(gather_smem_kernel,
                             cudaFuncAttributeMaxDynamicSharedMemorySize,
                             TAB_BYTES);
        attr_done = true;
    }

    // prologue
    zero_kernel<<<1, 64>>>((float4*)out, NGRAPH / 4);
    zero_kernel<<<64, 256>>>((float4*)pdeg, NPAD / 4);
    h_init_kernel<<<(NPAD * 32 + 255) / 256, 256>>>(z, emb);
    degree_kernel<<<(NEDGE + 255) / 256, 256>>>(eidx);
    // CSR build
    part_sum_kernel<<<NCHUNK, SCAN_B>>>();
    spine_kernel<<<1, 128>>>();
    scan_write_kernel<<<NCHUNK, SCAN_B>>>();
    scatter_kernel<<<(NEDGE + 255) / 256, 256>>>(eidx, pos);
    // filter tables
    {
        dim3 g(TABN / 8, NLAY);
        build_tab_kernel<<<g, 256>>>(mw1, mb1, mw2, mb2);
    }
    // weight fragment conversion
    {
        WConvPack p;
        for (int l = 0; l < NLAY; l++) {
            p.d[l]     = { l1w + l * HDIM * FDIM, HDIM, FDIM, l * 32768 };
            p.d[3 + l] = { l2w + l * FDIM * HDIM, FDIM, HDIM, l * 32768 + 8192 };
            p.d[6 + l] = { lw  + l * HDIM * HDIM, HDIM, HDIM, l * 32768 + 16384 };
        }
        p.d[9] = { ow1, HDIM, FDIM, 98304 };
        dim3 g(16, 10);
        wconv_kernel<<<g, 256>>>(p);
    }

    const int GB = 296;     // mma_gemm grid
    const int GGB = 148;    // gather grid (1 block/SM, 128KB smem each)

    for (int l = 0; l < NLAY; l++) {
        // xth = h @ l1w[l]   (fp16 out only)
        mma_gemm<128, 64, false, false, false, true><<<GB, 256>>>(
            ph, pwf + l * 32768, nullptr, pxt, pxth);
        // agg[n] = CSR gather with smem table
        gather_smem_kernel<<<GGB, GT_THREADS, TAB_BYTES>>>(ptabh + l * TABN * 32);
        // tbuf = ssp(agg @ l2w[l] + l2b[l])
        mma_gemm<64, 128, true, false, true, false><<<GB, 256>>>(
            pagg, pwf + l * 32768 + 8192, l2b + l * HDIM, ptb, pxth);
        // h += tbuf @ lw[l] + lb[l]
        mma_gemm<128, 128, false, true, true, false><<<GB, 256>>>(
            ptb, pwf + l * 32768 + 16384, lb + l * HDIM, ph, pxth);
    }

    // output MLP stage 1: xt = ssp(h @ ow1 + ob1)
    mma_gemm<128, 64, true, false, true, false><<<GB, 256>>>(
        ph, pwf + 98304, ob1, pxt, pxth);
    // stage 2 + per-graph segment sum
    readout_kernel<<<(NATOMS * 32 + 255) / 256, 256>>>(ow2, ob2, batch, out);
}

// round 11
// speedup vs baseline: 2.1600x; 1.1478x over previous
#include <cuda_runtime.h>
#include <cuda_fp16.h>
#include <math.h>

#define NATOMS 50000
#define NPAD   50048          // 64-node tiles (782 tiles)
#define NTILES (NPAD / 64)
#define NEDGE  1600000
#define HDIM   128
#define FDIM   64
#define GDIM   50
#define NLAY   3
#define NGRAPH 256
#define TABN   1024           // 1024 rows x 64ch fp16 = 128 KB (fits smem)
#define DMAXV  8.6603f
#define TSTEP  (DMAXV / (TABN - 1))
#define TINV   ((TABN - 1) / DMAXV)

#define SCAN_B 512
#define NCHUNK ((NPAD + SCAN_B - 1) / SCAN_B)   // 98

#define GT_THREADS 1024
#define TAB_BYTES (TABN * FDIM * 2)             // 131072

typedef unsigned long long ull;

// ---- scratch (device globals; no allocation allowed) ----
__device__ float   g_h    [NPAD * HDIM];
__device__ __half2 g_xth  [NPAD * FDIM / 2];
__device__ float   g_agg  [NPAD * FDIM];
__device__ __half2 g_tabh [NLAY * TABN * FDIM / 2];
__device__ int     g_deg  [NPAD];
__device__ int     g_rowptr[NPAD + 1];
__device__ int     g_cursor[NPAD];
__device__ int     g_part [NCHUNK];
__device__ float2  g_erec [NEDGE];     // {src_as_float, u}
// weight fragments (fp16, mma B-fragment order):
// layer l at l*32768: l1w(0), l2w(+8192), lw(+16384); ow1 at 98304
__device__ __half  g_wfrag[106496];

__device__ __forceinline__ float sspf(float x) {
    float sp = fmaxf(x, 0.0f) + log1pf(__expf(-fabsf(x)));
    return sp - 0.69314718055994531f;
}
__device__ __forceinline__ __half2 u_as_h2(unsigned u) {
    return *reinterpret_cast<__half2*>(&u);
}
__device__ __forceinline__ unsigned smem_u32(const void* p) {
    return (unsigned)__cvta_generic_to_shared(p);
}

// ---- packed f32x2 helpers ----
__device__ __forceinline__ ull ffma2(ull a, ull b, ull c) {
    ull d;
    asm("fma.rn.f32x2 %0, %1, %2, %3;" : "=l"(d) : "l"(a), "l"(b), "l"(c));
    return d;
}
__device__ __forceinline__ ull pack2(float x, float y) {
    ull r;
    asm("mov.b64 %0, {%1, %2};" : "=l"(r) : "f"(x), "f"(y));
    return r;
}
__device__ __forceinline__ float2 unpack2(ull v) {
    float2 r;
    asm("mov.b64 {%0, %1}, %2;" : "=f"(r.x), "=f"(r.y) : "l"(v));
    return r;
}

// ---------------- degree count ----------------
__global__ void degree_kernel(const int* __restrict__ ei) {
    int e = blockIdx.x * blockDim.x + threadIdx.x;
    if (e >= NEDGE) return;
    atomicAdd(&g_deg[__ldg(ei + NEDGE + e)], 1);
}

// ---------------- CSR scan pieces ----------------
__global__ void __launch_bounds__(SCAN_B) part_sum_kernel() {
    __shared__ int sh[SCAN_B];
    int idx = blockIdx.x * SCAN_B + threadIdx.x;
    int v = (idx < NPAD) ? g_deg[idx] : 0;
    sh[threadIdx.x] = v;
    __syncthreads();
    for (int s = SCAN_B / 2; s > 0; s >>= 1) {
        if (threadIdx.x < s) sh[threadIdx.x] += sh[threadIdx.x + s];
        __syncthreads();
    }
    if (threadIdx.x == 0) g_part[blockIdx.x] = sh[0];
}

__global__ void spine_kernel() {
    __shared__ int swp[4];
    int t = threadIdx.x;
    int lane = t & 31, w = t >> 5;
    int v = (t < NCHUNK) ? g_part[t] : 0;
    int s = v;
#pragma unroll
    for (int off = 1; off < 32; off <<= 1) {
        int n = __shfl_up_sync(0xffffffffu, s, off);
        if (lane >= off) s += n;
    }
    if (lane == 31) swp[w] = s;
    __syncthreads();
    if (t < 4) {
        int x = swp[t];
#pragma unroll
        for (int off = 1; off < 4; off <<= 1) {
            int n = __shfl_up_sync(0xfu, x, off);
            if (t >= off) x += n;
        }
        swp[t] = x;
    }
    __syncthreads();
    int excl = s - v + (w > 0 ? swp[w - 1] : 0);
    if (t < NCHUNK) g_part[t] = excl;
    if (t == 0) g_rowptr[NPAD] = NEDGE;
}

__global__ void __launch_bounds__(SCAN_B) scan_write_kernel() {
    __shared__ int sh[SCAN_B];
    int idx = blockIdx.x * SCAN_B + threadIdx.x;
    int own = (idx < NPAD) ? g_deg[idx] : 0;
    sh[threadIdx.x] = own;
    __syncthreads();
    for (int s = 1; s < SCAN_B; s <<= 1) {
        int v = (threadIdx.x >= s) ? sh[threadIdx.x - s] : 0;
        __syncthreads();
        sh[threadIdx.x] += v;
        __syncthreads();
    }
    if (idx < NPAD) {
        int excl = g_part[blockIdx.x] + sh[threadIdx.x] - own;
        g_rowptr[idx] = excl;
        g_cursor[idx] = excl;
    }
}

// ---------------- CSR scatter ----------------
__global__ void scatter_kernel(const int* __restrict__ ei,
                               const float* __restrict__ pos) {
    int e = blockIdx.x * blockDim.x + threadIdx.x;
    if (e >= NEDGE) return;
    int s = __ldg(ei + e);
    int t = __ldg(ei + NEDGE + e);
    float dx = __ldg(pos + s * 3 + 0) - __ldg(pos + t * 3 + 0);
    float dy = __ldg(pos + s * 3 + 1) - __ldg(pos + t * 3 + 1);
    float dz = __ldg(pos + s * 3 + 2) - __ldg(pos + t * 3 + 2);
    float u = sqrtf(dx * dx + dy * dy + dz * dz) * TINV;
    int slot = atomicAdd(&g_cursor[t], 1);
    g_erec[slot] = make_float2(__int_as_float(s), u);
}

// ---------------- filter lookup tables ----------------------------------
__global__ void __launch_bounds__(256) build_tab_kernel(
    const float* __restrict__ mw1, const float* __restrict__ mb1,
    const float* __restrict__ mw2, const float* __restrict__ mb2) {
    int layer = blockIdx.y;
    __shared__ float s_w1[GDIM * FDIM];
    __shared__ float s_w2[FDIM * FDIM];
    __shared__ float s_b1[FDIM], s_b2[FDIM];
    __shared__ float s_g[8][64];
    __shared__ float s_act[8][FDIM];

    int t = threadIdx.x;
    for (int i = t; i < GDIM * FDIM; i += 256)
        s_w1[i] = __ldg(mw1 + layer * GDIM * FDIM + i);
    for (int i = t; i < FDIM * FDIM; i += 256)
        s_w2[i] = __ldg(mw2 + layer * FDIM * FDIM + i);
    if (t < FDIM) {
        s_b1[t] = __ldg(mb1 + layer * FDIM + t);
        s_b2[t] = __ldg(mb2 + layer * FDIM + t);
    }
    __syncthreads();

    int wl = t >> 5, lane = t & 31;
    const float offstep = 10.0f / 49.0f;
    const float coeff   = -0.5f / (offstep * offstep);

    for (int ti = blockIdx.x * 8 + wl; ti < TABN; ti += gridDim.x * 8) {
        float dv = ti * TSTEP;
        for (int g = lane; g < GDIM; g += 32) {
            float x = dv - g * offstep;
            s_g[wl][g] = expf(coeff * x * x);
        }
        __syncwarp();

        ull acc = pack2(s_b1[2 * lane], s_b1[2 * lane + 1]);
        for (int g = 0; g < GDIM; g++) {
            float e = s_g[wl][g];
            ull wv = ((const ull*)(s_w1 + g * FDIM))[lane];
            acc = ffma2(pack2(e, e), wv, acc);
        }
        float2 a = unpack2(acc);
        s_act[wl][2 * lane]     = sspf(a.x);
        s_act[wl][2 * lane + 1] = sspf(a.y);
        __syncwarp();

        ull acc2 = pack2(s_b2[2 * lane], s_b2[2 * lane + 1]);
        for (int f = 0; f < FDIM; f++) {
            float tv = s_act[wl][f];
            ull wv = ((const ull*)(s_w2 + f * FDIM))[lane];
            acc2 = ffma2(pack2(tv, tv), wv, acc2);
        }
        float C = 0.5f * (cosf(dv * 3.14159265358979323846f / 10.0f) + 1.0f);
        float2 c2 = unpack2(acc2);
        g_tabh[(layer * TABN + ti) * 32 + lane] =
            __floats2half2_rn(c2.x * C, c2.y * C);
        __syncwarp();
    }
}

// ---------------- weight -> mma B-fragment converter --------------------
struct WConvDesc { const float* src; int ind; int outd; int dstoff; };
struct WConvPack { WConvDesc d[10]; };

__global__ void wconv_kernel(WConvPack p) {
    WConvDesc dd = p.d[blockIdx.y];
    int total = dd.ind * dd.outd / 4;
    int u = blockIdx.x * blockDim.x + threadIdx.x;
    if (u >= total) return;
    int lane = u & 31;
    int ot8  = dd.outd >> 3;
    int nt   = (u >> 5) % ot8;
    int ks   = (u >> 5) / ot8;
    int n  = nt * 8 + (lane >> 2);
    int k0 = ks * 16 + (lane & 3) * 2;
    const float* s = dd.src;
    __half2 lo = __floats2half2_rn(s[k0 * dd.outd + n], s[(k0 + 1) * dd.outd + n]);
    __half2 hi = __floats2half2_rn(s[(k0 + 8) * dd.outd + n], s[(k0 + 9) * dd.outd + n]);
    __half2* dst = (__half2*)(g_wfrag + dd.dstoff + u * 4);
    dst[0] = lo;
    dst[1] = hi;
}

// ---------------- zero helper ----------------
__global__ void zero_kernel(float4* __restrict__ p, int n4) {
    for (int i = blockIdx.x * blockDim.x + threadIdx.x; i < n4;
         i += gridDim.x * blockDim.x)
        p[i] = make_float4(0.f, 0.f, 0.f, 0.f);
}

// ---------------- one MMA stage (64-node tile) --------------------------
// sIn: fp16 smem input, stride IN+8. Outputs (any may be null):
//   sOut (fp16 smem, stride OUT+8), gF (fp32 gmem, resid in/out), gH (fp16 gmem)
template <int IN, int OUT, bool ACT, bool RESID>
__device__ __forceinline__ void stage_mma(
    const __half* sIn, __half* sOut, int tile,
    float* gF, __half2* gH, const ull* wf, const float* bias_p) {
    constexpr int NG   = OUT / 32;
    constexpr int MT   = (NG == 4) ? 2 : 1;
    constexpr int KS   = IN / 16;
    constexpr int ISTR = IN + 8;
    constexpr int OSTR = OUT + 8;

    int t = threadIdx.x, lane = t & 31, w = t >> 5;
    int ng = w % NG, mg = w / NG;

    unsigned bf[4 * KS * 2];
#pragma unroll
    for (int nt = 0; nt < 4; nt++)
#pragma unroll
        for (int ks = 0; ks < KS; ks++) {
            ull v = __ldg(wf + (ks * (OUT / 8) + ng * 4 + nt) * 32 + lane);
            bf[(nt * KS + ks) * 2]     = (unsigned)(v & 0xffffffffu);
            bf[(nt * KS + ks) * 2 + 1] = (unsigned)(v >> 32);
        }
    float2 bs[4];
#pragma unroll
    for (int nt = 0; nt < 4; nt++) {
        int c = ng * 32 + nt * 8 + (lane & 3) * 2;
        bs[nt] = bias_p ? make_float2(__ldg(bias_p + c), __ldg(bias_p + c + 1))
                        : make_float2(0.f, 0.f);
    }

    int grp    = lane >> 3;
    int arow_l = (lane & 7) + ((grp & 1) << 3);
    int acolh  = (grp >> 1) << 3;

#pragma unroll
    for (int mt = 0; mt < MT; mt++) {
        int mrow = mg * (MT * 16) + mt * 16;
        float acc[4][4];
#pragma unroll
        for (int nt = 0; nt < 4; nt++) {
            acc[nt][0] = bs[nt].x; acc[nt][1] = bs[nt].y;
            acc[nt][2] = bs[nt].x; acc[nt][3] = bs[nt].y;
        }
        unsigned abase = smem_u32(sIn + (mrow + arow_l) * ISTR + acolh);
#pragma unroll
        for (int ks = 0; ks < KS; ks++) {
            unsigned a0, a1, a2, a3;
            asm volatile(
                "ldmatrix.sync.aligned.m8n8.x4.shared.b16 {%0,%1,%2,%3}, [%4];"
                : "=r"(a0), "=r"(a1), "=r"(a2), "=r"(a3)
                : "r"(abase + ks * 32));
#pragma unroll
            for (int nt = 0; nt < 4; nt++) {
                asm volatile(
                    "mma.sync.aligned.m16n8k16.row.col.f32.f16.f16.f32 "
                    "{%0,%1,%2,%3}, {%4,%5,%6,%7}, {%8,%9}, {%0,%1,%2,%3};"
                    : "+f"(acc[nt][0]), "+f"(acc[nt][1]),
                      "+f"(acc[nt][2]), "+f"(acc[nt][3])
                    : "r"(a0), "r"(a1), "r"(a2), "r"(a3),
                      "r"(bf[(nt * KS + ks) * 2]),
                      "r"(bf[(nt * KS + ks) * 2 + 1]));
            }
        }
        int rl = mrow + (lane >> 2);       // local row
        int r0 = tile * 64 + rl;           // global row
        int cb = ng * 32 + (lane & 3) * 2;
#pragma unroll
        for (int nt = 0; nt < 4; nt++) {
            int col = cb + nt * 8;
            float2 v0 = make_float2(acc[nt][0], acc[nt][1]);
            float2 v1 = make_float2(acc[nt][2], acc[nt][3]);
            if (ACT) {
                v0.x = sspf(v0.x); v0.y = sspf(v0.y);
                v1.x = sspf(v1.x); v1.y = sspf(v1.y);
            }
            if (RESID) {
                float2 p0 = *(const float2*)(gF + r0 * OUT + col);
                float2 p1 = *(const float2*)(gF + (r0 + 8) * OUT + col);
                v0.x += p0.x; v0.y += p0.y;
                v1.x += p1.x; v1.y += p1.y;
            }
            if (gF) {
                *(float2*)(gF + r0 * OUT + col)       = v0;
                *(float2*)(gF + (r0 + 8) * OUT + col) = v1;
            }
            if (sOut) {
                *(__half2*)(sOut + rl * OSTR + col)       = __floats2half2_rn(v0.x, v0.y);
                *(__half2*)(sOut + (rl + 8) * OSTR + col) = __floats2half2_rn(v1.x, v1.y);
            }
            if (gH) {
                gH[r0 * (OUT / 2) + col / 2]       = __floats2half2_rn(v0.x, v0.y);
                gH[(r0 + 8) * (OUT / 2) + col / 2] = __floats2half2_rn(v1.x, v1.y);
            }
        }
    }
}

// ---------------- init: h = emb[z], xth = h @ l1w[0] --------------------
__global__ void __launch_bounds__(256, 2) init_xth_kernel(
    const int* __restrict__ z, const float* __restrict__ emb,
    const ull* __restrict__ wfC) {
    __shared__ __half bufH[64 * 136];
    int t = threadIdx.x;
    for (int tile = blockIdx.x; tile < NTILES; tile += gridDim.x) {
        for (int i = t; i < 64 * 32; i += 256) {
            int row = i >> 5, c = i & 31;
            int n = tile * 64 + row;
            float4 v = make_float4(0.f, 0.f, 0.f, 0.f);
            if (n < NATOMS) v = ((const float4*)emb)[__ldg(z + n) * 32 + c];
            ((float4*)g_h)[n * 32 + c] = v;
            __half2* d = (__half2*)(bufH + row * 136 + c * 4);
            d[0] = __floats2half2_rn(v.x, v.y);
            d[1] = __floats2half2_rn(v.z, v.w);
        }
        __syncthreads();
        stage_mma<128, 64, false, false>(bufH, nullptr, tile, nullptr,
                                         g_xth, wfC, nullptr);
        __syncthreads();
    }
}

// ---------------- node phase: agg -> tmp -> h -> xth/readout ------------
template <bool LAST>
__global__ void __launch_bounds__(256, 2) node_phase_kernel(
    const float* __restrict__ l2b_l, const float* __restrict__ lb_l,
    const ull* __restrict__ wfA, const ull* __restrict__ wfB,
    const ull* __restrict__ wfC,
    const float* __restrict__ ob1, const float* __restrict__ ow2,
    const float* __restrict__ ob2, const int* __restrict__ batch,
    float* __restrict__ out) {
    __shared__ __half bufA[64 * 72];    // agg in / xt out (LAST)
    __shared__ __half bufT[64 * 136];   // tmp
    __shared__ __half bufH[64 * 136];   // h fp16

    int t = threadIdx.x, lane = t & 31, w = t >> 5;
    float2 w2v = LAST ? *(const float2*)(ow2 + lane * 2) : make_float2(0.f, 0.f);
    float ob2v = LAST ? __ldg(ob2) : 0.f;

    for (int tile = blockIdx.x; tile < NTILES; tile += gridDim.x) {
        // load agg (fp32) -> bufA fp16
        const float4* src = (const float4*)(g_agg + tile * 64 * FDIM);
        for (int i = t; i < 64 * 16; i += 256) {
            int row = i >> 4, k4 = i & 15;
            float4 v = src[i];
            __half2* d = (__half2*)(bufA + row * 72 + k4 * 4);
            d[0] = __floats2half2_rn(v.x, v.y);
            d[1] = __floats2half2_rn(v.z, v.w);
        }
        __syncthreads();
        // tmp = ssp(agg @ l2w + l2b)
        stage_mma<64, 128, true, false>(bufA, bufT, tile, nullptr, nullptr,
                                        wfA, l2b_l);
        __syncthreads();
        // h += tmp @ lw + lb  (gmem fp32 resid; also fp16 smem copy)
        stage_mma<128, 128, false, true>(bufT, bufH, tile, g_h, nullptr,
                                         wfB, lb_l);
        __syncthreads();
        if (!LAST) {
            // xth = h @ l1w[l+1]
            stage_mma<128, 64, false, false>(bufH, nullptr, tile, nullptr,
                                             g_xth, wfC, nullptr);
        } else {
            // xt = ssp(h @ ow1 + ob1) -> bufA, then readout
            stage_mma<128, 64, true, false>(bufH, bufA, tile, nullptr,
                                            nullptr, wfC, ob1);
            __syncthreads();
#pragma unroll
            for (int i = 0; i < 8; i++) {
                int rl = w * 8 + i;
                int n  = tile * 64 + rl;
                if (n < NATOMS) {
                    float2 f = __half22float2(
                        *(const __half2*)(bufA + rl * 72 + lane * 2));
                    float s = f.x * w2v.x + f.y * w2v.y;
#pragma unroll
                    for (int off = 16; off; off >>= 1)
                        s += __shfl_down_sync(0xffffffffu, s, off);
                    if (lane == 0)
                        atomicAdd(out + __ldg(batch + n), s + ob2v);
                }
            }
        }
        __syncthreads();
    }
}

// ---------------- gather: smem-resident table, warp per node ------------
__global__ void __launch_bounds__(GT_THREADS) gather_smem_kernel(
    const __half2* __restrict__ tab) {
    extern __shared__ __align__(16) __half s_tab[];

    {
        const float4* src = (const float4*)tab;
        float4* dst = (float4*)s_tab;
        for (int i = threadIdx.x; i < TAB_BYTES / 16; i += GT_THREADS)
            dst[i] = src[i];
    }
    __syncthreads();

    int lane = threadIdx.x & 31;
    int hw   = lane >> 4;
    int c    = lane & 15;
    int warp = threadIdx.x >> 5;
    int gw0  = blockIdx.x * (GT_THREADS / 32) + warp;
    int nw   = gridDim.x * (GT_THREADS / 32);
    const __half* xth = (const __half*)g_xth;

    for (int node = gw0; node < NPAD; node += nw) {
        int beg = g_rowptr[node];
        int end = g_rowptr[node + 1];
        float4 acc = make_float4(0.f, 0.f, 0.f, 0.f);

        for (int base = beg; base < end; base += 32) {
            int cnt = min(32, end - base);
            float2 rec = make_float2(0.f, 0.f);
            if (lane < cnt) rec = __ldg(&g_erec[base + lane]);
            int   ms = __float_as_int(rec.x);
            float mu = rec.y;

#pragma unroll 2
            for (int j = 0; j < cnt; j += 2) {
                int  sl    = j + hw;
                int  s     = __shfl_sync(0xffffffffu, ms, sl);
                float u    = __shfl_sync(0xffffffffu, mu, sl);
                bool valid = sl < cnt;
                int  i0    = min((int)u, TABN - 2);
                float fr   = u - (float)i0;

                uint2 t0 = *(const uint2*)(s_tab + i0 * 64 + c * 4);
                uint2 t1 = *(const uint2*)(s_tab + (i0 + 1) * 64 + c * 4);
                uint2 xv = *(const uint2*)(xth + s * 64 + c * 4);

                float2 a0 = __half22float2(u_as_h2(t0.x));
                float2 a1 = __half22float2(u_as_h2(t0.y));
                float2 b0 = __half22float2(u_as_h2(t1.x));
                float2 b1 = __half22float2(u_as_h2(t1.y));
                float2 x0 = __half22float2(u_as_h2(xv.x));
                float2 x1 = __half22float2(u_as_h2(xv.y));

                if (valid) {
                    acc.x = fmaf(x0.x, fmaf(fr, b0.x - a0.x, a0.x), acc.x);
                    acc.y = fmaf(x0.y, fmaf(fr, b0.y - a0.y, a0.y), acc.y);
                    acc.z = fmaf(x1.x, fmaf(fr, b1.x - a1.x, a1.x), acc.z);
                    acc.w = fmaf(x1.y, fmaf(fr, b1.y - a1.y, a1.y), acc.w);
                }
            }
        }
        acc.x += __shfl_xor_sync(0xffffffffu, acc.x, 16);
        acc.y += __shfl_xor_sync(0xffffffffu, acc.y, 16);
        acc.z += __shfl_xor_sync(0xffffffffu, acc.z, 16);
        acc.w += __shfl_xor_sync(0xffffffffu, acc.w, 16);
        if (hw == 0)
            ((float4*)g_agg)[node * 16 + c] = acc;
    }
}

extern "C" void kernel_launch(void* const* d_in, const int* in_sizes, int n_in,
                              void* d_out, int out_size) {
    const int*   z     = (const int*)  d_in[0];
    const float* pos   = (const float*)d_in[1];
    const int*   batch = (const int*)  d_in[2];
    const int*   eidx  = (const int*)  d_in[3];
    const float* emb   = (const float*)d_in[4];
    const float* mw1   = (const float*)d_in[5];
    const float* mb1   = (const float*)d_in[6];
    const float* mw2   = (const float*)d_in[7];
    const float* mb2   = (const float*)d_in[8];
    const float* l1w   = (const float*)d_in[9];
    const float* l2w   = (const float*)d_in[10];
    const float* l2b   = (const float*)d_in[11];
    const float* lw    = (const float*)d_in[12];
    const float* lb    = (const float*)d_in[13];
    const float* ow1   = (const float*)d_in[14];
    const float* ob1   = (const float*)d_in[15];
    const float* ow2   = (const float*)d_in[16];
    const float* ob2   = (const float*)d_in[17];
    float* out = (float*)d_out;

    float *pdeg;
    __half2 *ptabh;
    __half *pwf;
    cudaGetSymbolAddress((void**)&ptabh, g_tabh);
    cudaGetSymbolAddress((void**)&pdeg,  g_deg);
    cudaGetSymbolAddress((void**)&pwf,   g_wfrag);

    static bool attr_done = false;
    if (!attr_done) {
        cudaFuncSetAttribute(gather_smem_kernel,
                             cudaFuncAttributeMaxDynamicSharedMemorySize,
                             TAB_BYTES);
        attr_done = true;
    }

    // prologue
    zero_kernel<<<1, 64>>>((float4*)out, NGRAPH / 4);
    zero_kernel<<<64, 256>>>((float4*)pdeg, NPAD / 4);
    degree_kernel<<<(NEDGE + 255) / 256, 256>>>(eidx);
    part_sum_kernel<<<NCHUNK, SCAN_B>>>();
    spine_kernel<<<1, 128>>>();
    scan_write_kernel<<<NCHUNK, SCAN_B>>>();
    scatter_kernel<<<(NEDGE + 255) / 256, 256>>>(eidx, pos);
    {
        dim3 g(TABN / 8, NLAY);
        build_tab_kernel<<<g, 256>>>(mw1, mb1, mw2, mb2);
    }
    {
        WConvPack p;
        for (int l = 0; l < NLAY; l++) {
            p.d[l]     = { l1w + l * HDIM * FDIM, HDIM, FDIM, l * 32768 };
            p.d[3 + l] = { l2w + l * FDIM * HDIM, FDIM, HDIM, l * 32768 + 8192 };
            p.d[6 + l] = { lw  + l * HDIM * HDIM, HDIM, HDIM, l * 32768 + 16384 };
        }
        p.d[9] = { ow1, HDIM, FDIM, 98304 };
        dim3 g(16, 10);
        wconv_kernel<<<g, 256>>>(p);
    }

    const int NB = 391;     // node-phase / init grid (2 tiles per block)
    const int GGB = 148;    // gather grid

    // h = emb[z]; xth = h @ l1w[0]
    init_xth_kernel<<<NB, 256>>>(z, emb, (const ull*)pwf);

    for (int l = 0; l < NLAY; l++) {
        gather_smem_kernel<<<GGB, GT_THREADS, TAB_BYTES>>>(ptabh + l * TABN * 32);
        const ull* wfA = (const ull*)(pwf + l * 32768 + 8192);
        const ull* wfB = (const ull*)(pwf + l * 32768 + 16384);
        if (l < NLAY - 1) {
            const ull* wfC = (const ull*)(pwf + (l + 1) * 32768);
            node_phase_kernel<false><<<NB, 256>>>(
                l2b + l * HDIM, lb + l * HDIM, wfA, wfB, wfC,
                nullptr, nullptr, nullptr, nullptr, nullptr);
        } else {
            const ull* wfC = (const ull*)(pwf + 98304);
            node_phase_kernel<true><<<NB, 256>>>(
                l2b + l * HDIM, lb + l * HDIM, wfA, wfB, wfC,
                ob1, ow2, ob2, batch, out);
        }
    }
}

// round 12
// speedup vs baseline: 2.3618x; 1.0934x over previous
#include <cuda_runtime.h>
#include <cuda_fp16.h>
#include <math.h>

#define NATOMS 50000
#define NPAD   50048          // 64-node tiles (782 tiles)
#define NTILES (NPAD / 64)
#define NEDGE  1600000
#define HDIM   128
#define FDIM   64
#define GDIM   50
#define NLAY   3
#define NGRAPH 256
#define TABN   1024           // 1024 rows x 64ch fp16 = 128 KB (fits smem)
#define DMAXV  8.6603f
#define TSTEP  (DMAXV / (TABN - 1))
#define TINV   ((TABN - 1) / DMAXV)

#define SCAN_B 512
#define NCHUNK ((NPAD + SCAN_B - 1) / SCAN_B)   // 98

#define GT_THREADS 1024
#define TAB_BYTES (TABN * FDIM * 2)             // 131072

typedef unsigned long long ull;

// ---- scratch (device globals; no allocation allowed) ----
__device__ float    g_h    [NPAD * HDIM];
__device__ __half2  g_xth  [NPAD * FDIM / 2];
__device__ float    g_agg  [NPAD * FDIM];
__device__ __half2  g_tabh [NLAY * TABN * FDIM / 2];
__device__ int      g_deg  [NPAD];
__device__ int      g_rowptr[NPAD + 1];
__device__ int      g_cursor[NPAD];
__device__ int      g_part [NCHUNK];
__device__ unsigned g_erec [NEDGE];    // src<<16 | u fixed-point (10.6)
// weight fragments (fp16, mma B-fragment order)
__device__ __half   g_wfrag[106496];

__device__ __forceinline__ float sspf(float x) {
    float sp = fmaxf(x, 0.0f) + log1pf(__expf(-fabsf(x)));
    return sp - 0.69314718055994531f;
}
__device__ __forceinline__ __half2 u_as_h2(unsigned u) {
    return *reinterpret_cast<__half2*>(&u);
}
__device__ __forceinline__ unsigned smem_u32(const void* p) {
    return (unsigned)__cvta_generic_to_shared(p);
}

// ---- packed f32x2 helpers ----
__device__ __forceinline__ ull ffma2(ull a, ull b, ull c) {
    ull d;
    asm("fma.rn.f32x2 %0, %1, %2, %3;" : "=l"(d) : "l"(a), "l"(b), "l"(c));
    return d;
}
__device__ __forceinline__ ull pack2(float x, float y) {
    ull r;
    asm("mov.b64 %0, {%1, %2};" : "=l"(r) : "f"(x), "f"(y));
    return r;
}
__device__ __forceinline__ float2 unpack2(ull v) {
    float2 r;
    asm("mov.b64 {%0, %1}, %2;" : "=f"(r.x), "=f"(r.y) : "l"(v));
    return r;
}

// ---------------- degree count ----------------
__global__ void degree_kernel(const int* __restrict__ ei) {
    int e = blockIdx.x * blockDim.x + threadIdx.x;
    if (e >= NEDGE) return;
    atomicAdd(&g_deg[__ldg(ei + NEDGE + e)], 1);
}

// ---------------- CSR scan pieces ----------------
__global__ void __launch_bounds__(SCAN_B) part_sum_kernel() {
    __shared__ int sh[SCAN_B];
    int idx = blockIdx.x * SCAN_B + threadIdx.x;
    int v = (idx < NPAD) ? g_deg[idx] : 0;
    sh[threadIdx.x] = v;
    __syncthreads();
    for (int s = SCAN_B / 2; s > 0; s >>= 1) {
        if (threadIdx.x < s) sh[threadIdx.x] += sh[threadIdx.x + s];
        __syncthreads();
    }
    if (threadIdx.x == 0) g_part[blockIdx.x] = sh[0];
}

__global__ void spine_kernel() {
    __shared__ int swp[4];
    int t = threadIdx.x;
    int lane = t & 31, w = t >> 5;
    int v = (t < NCHUNK) ? g_part[t] : 0;
    int s = v;
#pragma unroll
    for (int off = 1; off < 32; off <<= 1) {
        int n = __shfl_up_sync(0xffffffffu, s, off);
        if (lane >= off) s += n;
    }
    if (lane == 31) swp[w] = s;
    __syncthreads();
    if (t < 4) {
        int x = swp[t];
#pragma unroll
        for (int off = 1; off < 4; off <<= 1) {
            int n = __shfl_up_sync(0xfu, x, off);
            if (t >= off) x += n;
        }
        swp[t] = x;
    }
    __syncthreads();
    int excl = s - v + (w > 0 ? swp[w - 1] : 0);
    if (t < NCHUNK) g_part[t] = excl;
    if (t == 0) g_rowptr[NPAD] = NEDGE;
}

__global__ void __launch_bounds__(SCAN_B) scan_write_kernel() {
    __shared__ int sh[SCAN_B];
    int idx = blockIdx.x * SCAN_B + threadIdx.x;
    int own = (idx < NPAD) ? g_deg[idx] : 0;
    sh[threadIdx.x] = own;
    __syncthreads();
    for (int s = 1; s < SCAN_B; s <<= 1) {
        int v = (threadIdx.x >= s) ? sh[threadIdx.x - s] : 0;
        __syncthreads();
        sh[threadIdx.x] += v;
        __syncthreads();
    }
    if (idx < NPAD) {
        int excl = g_part[blockIdx.x] + sh[threadIdx.x] - own;
        g_rowptr[idx] = excl;
        g_cursor[idx] = excl;
    }
}

// ---------------- CSR scatter: pack src(16b) | u(10.6 fixed) ------------
__global__ void scatter_kernel(const int* __restrict__ ei,
                               const float* __restrict__ pos) {
    int e = blockIdx.x * blockDim.x + threadIdx.x;
    if (e >= NEDGE) return;
    int s = __ldg(ei + e);
    int t = __ldg(ei + NEDGE + e);
    float dx = __ldg(pos + s * 3 + 0) - __ldg(pos + t * 3 + 0);
    float dy = __ldg(pos + s * 3 + 1) - __ldg(pos + t * 3 + 1);
    float dz = __ldg(pos + s * 3 + 2) - __ldg(pos + t * 3 + 2);
    float u = sqrtf(dx * dx + dy * dy + dz * dz) * TINV;
    int uq = min((int)(u * 64.0f), (TABN - 1) * 64 - 1);   // i0 <= TABN-2
    int slot = atomicAdd(&g_cursor[t], 1);
    g_erec[slot] = ((unsigned)s << 16) | (unsigned)uq;
}

// ---------------- filter lookup tables ----------------------------------
__global__ void __launch_bounds__(256) build_tab_kernel(
    const float* __restrict__ mw1, const float* __restrict__ mb1,
    const float* __restrict__ mw2, const float* __restrict__ mb2) {
    int layer = blockIdx.y;
    __shared__ float s_w1[GDIM * FDIM];
    __shared__ float s_w2[FDIM * FDIM];
    __shared__ float s_b1[FDIM], s_b2[FDIM];
    __shared__ float s_g[8][64];
    __shared__ float s_act[8][FDIM];

    int t = threadIdx.x;
    for (int i = t; i < GDIM * FDIM; i += 256)
        s_w1[i] = __ldg(mw1 + layer * GDIM * FDIM + i);
    for (int i = t; i < FDIM * FDIM; i += 256)
        s_w2[i] = __ldg(mw2 + layer * FDIM * FDIM + i);
    if (t < FDIM) {
        s_b1[t] = __ldg(mb1 + layer * FDIM + t);
        s_b2[t] = __ldg(mb2 + layer * FDIM + t);
    }
    __syncthreads();

    int wl = t >> 5, lane = t & 31;
    const float offstep = 10.0f / 49.0f;
    const float coeff   = -0.5f / (offstep * offstep);

    for (int ti = blockIdx.x * 8 + wl; ti < TABN; ti += gridDim.x * 8) {
        float dv = ti * TSTEP;
        for (int g = lane; g < GDIM; g += 32) {
            float x = dv - g * offstep;
            s_g[wl][g] = expf(coeff * x * x);
        }
        __syncwarp();

        ull acc = pack2(s_b1[2 * lane], s_b1[2 * lane + 1]);
        for (int g = 0; g < GDIM; g++) {
            float e = s_g[wl][g];
            ull wv = ((const ull*)(s_w1 + g * FDIM))[lane];
            acc = ffma2(pack2(e, e), wv, acc);
        }
        float2 a = unpack2(acc);
        s_act[wl][2 * lane]     = sspf(a.x);
        s_act[wl][2 * lane + 1] = sspf(a.y);
        __syncwarp();

        ull acc2 = pack2(s_b2[2 * lane], s_b2[2 * lane + 1]);
        for (int f = 0; f < FDIM; f++) {
            float tv = s_act[wl][f];
            ull wv = ((const ull*)(s_w2 + f * FDIM))[lane];
            acc2 = ffma2(pack2(tv, tv), wv, acc2);
        }
        float C = 0.5f * (cosf(dv * 3.14159265358979323846f / 10.0f) + 1.0f);
        float2 c2 = unpack2(acc2);
        g_tabh[(layer * TABN + ti) * 32 + lane] =
            __floats2half2_rn(c2.x * C, c2.y * C);
        __syncwarp();
    }
}

// ---------------- weight -> mma B-fragment converter --------------------
struct WConvDesc { const float* src; int ind; int outd; int dstoff; };
struct WConvPack { WConvDesc d[10]; };

__global__ void wconv_kernel(WConvPack p) {
    WConvDesc dd = p.d[blockIdx.y];
    int total = dd.ind * dd.outd / 4;
    int u = blockIdx.x * blockDim.x + threadIdx.x;
    if (u >= total) return;
    int lane = u & 31;
    int ot8  = dd.outd >> 3;
    int nt   = (u >> 5) % ot8;
    int ks   = (u >> 5) / ot8;
    int n  = nt * 8 + (lane >> 2);
    int k0 = ks * 16 + (lane & 3) * 2;
    const float* s = dd.src;
    __half2 lo = __floats2half2_rn(s[k0 * dd.outd + n], s[(k0 + 1) * dd.outd + n]);
    __half2 hi = __floats2half2_rn(s[(k0 + 8) * dd.outd + n], s[(k0 + 9) * dd.outd + n]);
    __half2* dst = (__half2*)(g_wfrag + dd.dstoff + u * 4);
    dst[0] = lo;
    dst[1] = hi;
}

// ---------------- zero helper ----------------
__global__ void zero_kernel(float4* __restrict__ p, int n4) {
    for (int i = blockIdx.x * blockDim.x + threadIdx.x; i < n4;
         i += gridDim.x * blockDim.x)
        p[i] = make_float4(0.f, 0.f, 0.f, 0.f);
}

// ---------------- one MMA stage (64-node tile) --------------------------
template <int IN, int OUT, bool ACT, bool RESID>
__device__ __forceinline__ void stage_mma(
    const __half* sIn, __half* sOut, int tile,
    float* gF, __half2* gH, const ull* wf, const float* bias_p) {
    constexpr int NG   = OUT / 32;
    constexpr int MT   = (NG == 4) ? 2 : 1;
    constexpr int KS   = IN / 16;
    constexpr int ISTR = IN + 8;
    constexpr int OSTR = OUT + 8;

    int t = threadIdx.x, lane = t & 31, w = t >> 5;
    int ng = w % NG, mg = w / NG;

    unsigned bf[4 * KS * 2];
#pragma unroll
    for (int nt = 0; nt < 4; nt++)
#pragma unroll
        for (int ks = 0; ks < KS; ks++) {
            ull v = __ldg(wf + (ks * (OUT / 8) + ng * 4 + nt) * 32 + lane);
            bf[(nt * KS + ks) * 2]     = (unsigned)(v & 0xffffffffu);
            bf[(nt * KS + ks) * 2 + 1] = (unsigned)(v >> 32);
        }
    float2 bs[4];
#pragma unroll
    for (int nt = 0; nt < 4; nt++) {
        int c = ng * 32 + nt * 8 + (lane & 3) * 2;
        bs[nt] = bias_p ? make_float2(__ldg(bias_p + c), __ldg(bias_p + c + 1))
                        : make_float2(0.f, 0.f);
    }

    int grp    = lane >> 3;
    int arow_l = (lane & 7) + ((grp & 1) << 3);
    int acolh  = (grp >> 1) << 3;

#pragma unroll
    for (int mt = 0; mt < MT; mt++) {
        int mrow = mg * (MT * 16) + mt * 16;
        float acc[4][4];
#pragma unroll
        for (int nt = 0; nt < 4; nt++) {
            acc[nt][0] = bs[nt].x; acc[nt][1] = bs[nt].y;
            acc[nt][2] = bs[nt].x; acc[nt][3] = bs[nt].y;
        }
        unsigned abase = smem_u32(sIn + (mrow + arow_l) * ISTR + acolh);
#pragma unroll
        for (int ks = 0; ks < KS; ks++) {
            unsigned a0, a1, a2, a3;
            asm volatile(
                "ldmatrix.sync.aligned.m8n8.x4.shared.b16 {%0,%1,%2,%3}, [%4];"
                : "=r"(a0), "=r"(a1), "=r"(a2), "=r"(a3)
                : "r"(abase + ks * 32));
#pragma unroll
            for (int nt = 0; nt < 4; nt++) {
                asm volatile(
                    "mma.sync.aligned.m16n8k16.row.col.f32.f16.f16.f32 "
                    "{%0,%1,%2,%3}, {%4,%5,%6,%7}, {%8,%9}, {%0,%1,%2,%3};"
                    : "+f"(acc[nt][0]), "+f"(acc[nt][1]),
                      "+f"(acc[nt][2]), "+f"(acc[nt][3])
                    : "r"(a0), "r"(a1), "r"(a2), "r"(a3),
                      "r"(bf[(nt * KS + ks) * 2]),
                      "r"(bf[(nt * KS + ks) * 2 + 1]));
            }
        }
        int rl = mrow + (lane >> 2);
        int r0 = tile * 64 + rl;
        int cb = ng * 32 + (lane & 3) * 2;
#pragma unroll
        for (int nt = 0; nt < 4; nt++) {
            int col = cb + nt * 8;
            float2 v0 = make_float2(acc[nt][0], acc[nt][1]);
            float2 v1 = make_float2(acc[nt][2], acc[nt][3]);
            if (ACT) {
                v0.x = sspf(v0.x); v0.y = sspf(v0.y);
                v1.x = sspf(v1.x); v1.y = sspf(v1.y);
            }
            if (RESID) {
                float2 p0 = *(const float2*)(gF + r0 * OUT + col);
                float2 p1 = *(const float2*)(gF + (r0 + 8) * OUT + col);
                v0.x += p0.x; v0.y += p0.y;
                v1.x += p1.x; v1.y += p1.y;
            }
            if (gF) {
                *(float2*)(gF + r0 * OUT + col)       = v0;
                *(float2*)(gF + (r0 + 8) * OUT + col) = v1;
            }
            if (sOut) {
                *(__half2*)(sOut + rl * OSTR + col)       = __floats2half2_rn(v0.x, v0.y);
                *(__half2*)(sOut + (rl + 8) * OSTR + col) = __floats2half2_rn(v1.x, v1.y);
            }
            if (gH) {
                gH[r0 * (OUT / 2) + col / 2]       = __floats2half2_rn(v0.x, v0.y);
                gH[(r0 + 8) * (OUT / 2) + col / 2] = __floats2half2_rn(v1.x, v1.y);
            }
        }
    }
}

// ---------------- init: h = emb[z], xth = h @ l1w[0] --------------------
__global__ void __launch_bounds__(256, 2) init_xth_kernel(
    const int* __restrict__ z, const float* __restrict__ emb,
    const ull* __restrict__ wfC) {
    __shared__ __half bufH[64 * 136];
    int t = threadIdx.x;
    for (int tile = blockIdx.x; tile < NTILES; tile += gridDim.x) {
        for (int i = t; i < 64 * 32; i += 256) {
            int row = i >> 5, c = i & 31;
            int n = tile * 64 + row;
            float4 v = make_float4(0.f, 0.f, 0.f, 0.f);
            if (n < NATOMS) v = ((const float4*)emb)[__ldg(z + n) * 32 + c];
            ((float4*)g_h)[n * 32 + c] = v;
            __half2* d = (__half2*)(bufH + row * 136 + c * 4);
            d[0] = __floats2half2_rn(v.x, v.y);
            d[1] = __floats2half2_rn(v.z, v.w);
        }
        __syncthreads();
        stage_mma<128, 64, false, false>(bufH, nullptr, tile, nullptr,
                                         g_xth, wfC, nullptr);
        __syncthreads();
    }
}

// ---------------- node phase ----------------
template <bool LAST>
__global__ void __launch_bounds__(256, 2) node_phase_kernel(
    const float* __restrict__ l2b_l, const float* __restrict__ lb_l,
    const ull* __restrict__ wfA, const ull* __restrict__ wfB,
    const ull* __restrict__ wfC,
    const float* __restrict__ ob1, const float* __restrict__ ow2,
    const float* __restrict__ ob2, const int* __restrict__ batch,
    float* __restrict__ out) {
    __shared__ __half bufA[64 * 72];
    __shared__ __half bufT[64 * 136];
    __shared__ __half bufH[64 * 136];

    int t = threadIdx.x, lane = t & 31, w = t >> 5;
    float2 w2v = LAST ? *(const float2*)(ow2 + lane * 2) : make_float2(0.f, 0.f);
    float ob2v = LAST ? __ldg(ob2) : 0.f;

    for (int tile = blockIdx.x; tile < NTILES; tile += gridDim.x) {
        const float4* src = (const float4*)(g_agg + tile * 64 * FDIM);
        for (int i = t; i < 64 * 16; i += 256) {
            int row = i >> 4, k4 = i & 15;
            float4 v = src[i];
            __half2* d = (__half2*)(bufA + row * 72 + k4 * 4);
            d[0] = __floats2half2_rn(v.x, v.y);
            d[1] = __floats2half2_rn(v.z, v.w);
        }
        __syncthreads();
        stage_mma<64, 128, true, false>(bufA, bufT, tile, nullptr, nullptr,
                                        wfA, l2b_l);
        __syncthreads();
        stage_mma<128, 128, false, true>(bufT, bufH, tile, g_h, nullptr,
                                         wfB, lb_l);
        __syncthreads();
        if (!LAST) {
            stage_mma<128, 64, false, false>(bufH, nullptr, tile, nullptr,
                                             g_xth, wfC, nullptr);
        } else {
            stage_mma<128, 64, true, false>(bufH, bufA, tile, nullptr,
                                            nullptr, wfC, ob1);
            __syncthreads();
#pragma unroll
            for (int i = 0; i < 8; i++) {
                int rl = w * 8 + i;
                int n  = tile * 64 + rl;
                if (n < NATOMS) {
                    float2 f = __half22float2(
                        *(const __half2*)(bufA + rl * 72 + lane * 2));
                    float s = f.x * w2v.x + f.y * w2v.y;
#pragma unroll
                    for (int off = 16; off; off >>= 1)
                        s += __shfl_down_sync(0xffffffffu, s, off);
                    if (lane == 0)
                        atomicAdd(out + __ldg(batch + n), s + ob2v);
                }
            }
        }
        __syncthreads();
    }
}

// ---------------- gather: smem table, packed records, half2 math --------
__global__ void __launch_bounds__(GT_THREADS) gather_smem_kernel(
    const __half2* __restrict__ tab) {
    extern __shared__ __align__(16) __half s_tab[];

    {
        const float4* src = (const float4*)tab;
        float4* dst = (float4*)s_tab;
        for (int i = threadIdx.x; i < TAB_BYTES / 16; i += GT_THREADS)
            dst[i] = src[i];
    }
    __syncthreads();

    int lane = threadIdx.x & 31;
    int hw   = lane >> 4;          // half-warp: which edge of the pair
    int c    = lane & 15;          // channel group (4 channels)
    int warp = threadIdx.x >> 5;
    int gw0  = blockIdx.x * (GT_THREADS / 32) + warp;
    int nw   = gridDim.x * (GT_THREADS / 32);
    const __half* xth = (const __half*)g_xth;

    for (int node = gw0; node < NPAD; node += nw) {
        int beg = g_rowptr[node];
        int end = g_rowptr[node + 1];
        float4 acc = make_float4(0.f, 0.f, 0.f, 0.f);

        for (int base = beg; base < end; base += 32) {
            int cnt = min(32, end - base);
            unsigned myrec = 0;
            if (lane < cnt) myrec = __ldg(&g_erec[base + lane]);

#pragma unroll 4
            for (int j = 0; j < cnt; j += 2) {
                int sl = j + hw;
                unsigned rec = __shfl_sync(0xffffffffu, myrec, sl);
                bool valid = sl < cnt;
                int s  = rec >> 16;
                int uq = rec & 0xffff;
                int i0 = uq >> 6;
                __half2 fr2 = __float2half2_rn((float)(uq & 63) * 0.015625f);

                uint2 t0 = *(const uint2*)(s_tab + i0 * 64 + c * 4);
                uint2 t1 = *(const uint2*)(s_tab + (i0 + 1) * 64 + c * 4);
                uint2 xv = *(const uint2*)(xth + s * 64 + c * 4);

                __half2 a0 = u_as_h2(t0.x), a1 = u_as_h2(t0.y);
                __half2 w0 = __hfma2(fr2, __hsub2(u_as_h2(t1.x), a0), a0);
                __half2 w1 = __hfma2(fr2, __hsub2(u_as_h2(t1.y), a1), a1);
                __half2 m0 = __hmul2(w0, u_as_h2(xv.x));
                __half2 m1 = __hmul2(w1, u_as_h2(xv.y));
                float2 f0 = __half22float2(m0);
                float2 f1 = __half22float2(m1);
                if (valid) {
                    acc.x += f0.x; acc.y += f0.y;
                    acc.z += f1.x; acc.w += f1.y;
                }
            }
        }
        acc.x += __shfl_xor_sync(0xffffffffu, acc.x, 16);
        acc.y += __shfl_xor_sync(0xffffffffu, acc.y, 16);
        acc.z += __shfl_xor_sync(0xffffffffu, acc.z, 16);
        acc.w += __shfl_xor_sync(0xffffffffu, acc.w, 16);
        if (hw == 0)
            ((float4*)g_agg)[node * 16 + c] = acc;
    }
}

extern "C" void kernel_launch(void* const* d_in, const int* in_sizes, int n_in,
                              void* d_out, int out_size) {
    const int*   z     = (const int*)  d_in[0];
    const float* pos   = (const float*)d_in[1];
    const int*   batch = (const int*)  d_in[2];
    const int*   eidx  = (const int*)  d_in[3];
    const float* emb   = (const float*)d_in[4];
    const float* mw1   = (const float*)d_in[5];
    const float* mb1   = (const float*)d_in[6];
    const float* mw2   = (const float*)d_in[7];
    const float* mb2   = (const float*)d_in[8];
    const float* l1w   = (const float*)d_in[9];
    const float* l2w   = (const float*)d_in[10];
    const float* l2b   = (const float*)d_in[11];
    const float* lw    = (const float*)d_in[12];
    const float* lb    = (const float*)d_in[13];
    const float* ow1   = (const float*)d_in[14];
    const float* ob1   = (const float*)d_in[15];
    const float* ow2   = (const float*)d_in[16];
    const float* ob2   = (const float*)d_in[17];
    float* out = (float*)d_out;

    float *pdeg;
    __half2 *ptabh;
    __half *pwf;
    cudaGetSymbolAddress((void**)&ptabh, g_tabh);
    cudaGetSymbolAddress((void**)&pdeg,  g_deg);
    cudaGetSymbolAddress((void**)&pwf,   g_wfrag);

    static bool attr_done = false;
    if (!attr_done) {
        cudaFuncSetAttribute(gather_smem_kernel,
                             cudaFuncAttributeMaxDynamicSharedMemorySize,
                             TAB_BYTES);
        attr_done = true;
    }

    // prologue
    zero_kernel<<<1, 64>>>((float4*)out, NGRAPH / 4);
    zero_kernel<<<64, 256>>>((float4*)pdeg, NPAD / 4);
    degree_kernel<<<(NEDGE + 255) / 256, 256>>>(eidx);
    part_sum_kernel<<<NCHUNK, SCAN_B>>>();
    spine_kernel<<<1, 128>>>();
    scan_write_kernel<<<NCHUNK, SCAN_B>>>();
    scatter_kernel<<<(NEDGE + 255) / 256, 256>>>(eidx, pos);
    {
        dim3 g(TABN / 8, NLAY);
        build_tab_kernel<<<g, 256>>>(mw1, mb1, mw2, mb2);
    }
    {
        WConvPack p;
        for (int l = 0; l < NLAY; l++) {
            p.d[l]     = { l1w + l * HDIM * FDIM, HDIM, FDIM, l * 32768 };
            p.d[3 + l] = { l2w + l * FDIM * HDIM, FDIM, HDIM, l * 32768 + 8192 };
            p.d[6 + l] = { lw  + l * HDIM * HDIM, HDIM, HDIM, l * 32768 + 16384 };
        }
        p.d[9] = { ow1, HDIM, FDIM, 98304 };
        dim3 g(16, 10);
        wconv_kernel<<<g, 256>>>(p);
    }

    const int NB = 296;     // node-phase / init grid (grid-stride, 2-3 tiles)
    const int GGB = 148;    // gather grid

    init_xth_kernel<<<NB, 256>>>(z, emb, (const ull*)pwf);

    for (int l = 0; l < NLAY; l++) {
        gather_smem_kernel<<<GGB, GT_THREADS, TAB_BYTES>>>(ptabh + l * TABN * 32);
        const ull* wfA = (const ull*)(pwf + l * 32768 + 8192);
        const ull* wfB = (const ull*)(pwf + l * 32768 + 16384);
        if (l < NLAY - 1) {
            const ull* wfC = (const ull*)(pwf + (l + 1) * 32768);
            node_phase_kernel<false><<<NB, 256>>>(
                l2b + l * HDIM, lb + l * HDIM, wfA, wfB, wfC,
                nullptr, nullptr, nullptr, nullptr, nullptr);
        } else {
            const ull* wfC = (const ull*)(pwf + 98304);
            node_phase_kernel<true><<<NB, 256>>>(
                l2b + l * HDIM, lb + l * HDIM, wfA, wfB, wfC,
                ob1, ow2, ob2, batch, out);
        }
    }
}

// round 13
// speedup vs baseline: 2.4976x; 1.0575x over previous
#include <cuda_runtime.h>
#include <cuda_fp16.h>
#include <math.h>

#define NATOMS 50000
#define NPAD   50048          // 64-node tiles (782 tiles)
#define NTILES (NPAD / 64)
#define NEDGE  1600000
#define HDIM   128
#define FDIM   64
#define GDIM   50
#define NLAY   3
#define NGRAPH 256
#define TABN   1024           // 1024 rows x 64ch fp16 = 128 KB (fits smem)
#define DMAXV  8.6603f
#define TSTEP  (DMAXV / (TABN - 1))
#define TINV   ((TABN - 1) / DMAXV)

#define SCAN_B 512
#define NCHUNK ((NPAD + SCAN_B - 1) / SCAN_B)   // 98

#define GT_THREADS 1024
#define TAB_BYTES (TABN * FDIM * 2)             // 131072

typedef unsigned long long ull;

// ---- scratch (device globals; no allocation allowed) ----
__device__ float    g_h    [NPAD * HDIM];
__device__ __half2  g_xth  [NPAD * FDIM / 2];
__device__ __half2  g_aggh [NPAD * FDIM / 2];
__device__ __half2  g_tabh [NLAY * TABN * FDIM / 2];
__device__ int      g_deg  [NPAD];
__device__ int      g_rowptr[NPAD + 1];
__device__ int      g_cursor[NPAD];
__device__ int      g_part [NCHUNK];
__device__ unsigned g_erec [NEDGE];    // src<<16 | u fixed-point (10.6)
__device__ __half   g_wfrag[106496];

__device__ __forceinline__ float sspf(float x) {
    float sp = fmaxf(x, 0.0f) + log1pf(__expf(-fabsf(x)));
    return sp - 0.69314718055994531f;
}
__device__ __forceinline__ __half2 u_as_h2(unsigned u) {
    return *reinterpret_cast<__half2*>(&u);
}
__device__ __forceinline__ unsigned h2_as_u(__half2 h) {
    return *reinterpret_cast<unsigned*>(&h);
}
__device__ __forceinline__ unsigned smem_u32(const void* p) {
    return (unsigned)__cvta_generic_to_shared(p);
}

// ---- packed f32x2 helpers ----
__device__ __forceinline__ ull ffma2(ull a, ull b, ull c) {
    ull d;
    asm("fma.rn.f32x2 %0, %1, %2, %3;" : "=l"(d) : "l"(a), "l"(b), "l"(c));
    return d;
}
__device__ __forceinline__ ull pack2(float x, float y) {
    ull r;
    asm("mov.b64 %0, {%1, %2};" : "=l"(r) : "f"(x), "f"(y));
    return r;
}
__device__ __forceinline__ float2 unpack2(ull v) {
    float2 r;
    asm("mov.b64 {%0, %1}, %2;" : "=f"(r.x), "=f"(r.y) : "l"(v));
    return r;
}

// ---------------- fused zero: out + deg ----------------
__global__ void zero2_kernel(float* __restrict__ out) {
    int i = blockIdx.x * blockDim.x + threadIdx.x;
    if (i < NPAD / 4) ((float4*)g_deg)[i] = make_float4(0.f, 0.f, 0.f, 0.f);
    if (i < NGRAPH) out[i] = 0.f;
}

// ---------------- degree count ----------------
__global__ void degree_kernel(const int* __restrict__ ei) {
    int e = blockIdx.x * blockDim.x + threadIdx.x;
    if (e >= NEDGE) return;
    atomicAdd(&g_deg[__ldg(ei + NEDGE + e)], 1);
}

// ---------------- CSR scan pieces ----------------
__global__ void __launch_bounds__(SCAN_B) part_sum_kernel() {
    __shared__ int sh[SCAN_B];
    int idx = blockIdx.x * SCAN_B + threadIdx.x;
    int v = (idx < NPAD) ? g_deg[idx] : 0;
    sh[threadIdx.x] = v;
    __syncthreads();
    for (int s = SCAN_B / 2; s > 0; s >>= 1) {
        if (threadIdx.x < s) sh[threadIdx.x] += sh[threadIdx.x + s];
        __syncthreads();
    }
    if (threadIdx.x == 0) g_part[blockIdx.x] = sh[0];
}

__global__ void spine_kernel() {
    __shared__ int swp[4];
    int t = threadIdx.x;
    int lane = t & 31, w = t >> 5;
    int v = (t < NCHUNK) ? g_part[t] : 0;
    int s = v;
#pragma unroll
    for (int off = 1; off < 32; off <<= 1) {
        int n = __shfl_up_sync(0xffffffffu, s, off);
        if (lane >= off) s += n;
    }
    if (lane == 31) swp[w] = s;
    __syncthreads();
    if (t < 4) {
        int x = swp[t];
#pragma unroll
        for (int off = 1; off < 4; off <<= 1) {
            int n = __shfl_up_sync(0xfu, x, off);
            if (t >= off) x += n;
        }
        swp[t] = x;
    }
    __syncthreads();
    int excl = s - v + (w > 0 ? swp[w - 1] : 0);
    if (t < NCHUNK) g_part[t] = excl;
    if (t == 0) g_rowptr[NPAD] = NEDGE;
}

__global__ void __launch_bounds__(SCAN_B) scan_write_kernel() {
    __shared__ int sh[SCAN_B];
    int idx = blockIdx.x * SCAN_B + threadIdx.x;
    int own = (idx < NPAD) ? g_deg[idx] : 0;
    sh[threadIdx.x] = own;
    __syncthreads();
    for (int s = 1; s < SCAN_B; s <<= 1) {
        int v = (threadIdx.x >= s) ? sh[threadIdx.x - s] : 0;
        __syncthreads();
        sh[threadIdx.x] += v;
        __syncthreads();
    }
    if (idx < NPAD) {
        int excl = g_part[blockIdx.x] + sh[threadIdx.x] - own;
        g_rowptr[idx] = excl;
        g_cursor[idx] = excl;
    }
}

// ---------------- CSR scatter: pack src(16b) | u(10.6 fixed) ------------
__global__ void scatter_kernel(const int* __restrict__ ei,
                               const float* __restrict__ pos) {
    int e = blockIdx.x * blockDim.x + threadIdx.x;
    if (e >= NEDGE) return;
    int s = __ldg(ei + e);
    int t = __ldg(ei + NEDGE + e);
    float dx = __ldg(pos + s * 3 + 0) - __ldg(pos + t * 3 + 0);
    float dy = __ldg(pos + s * 3 + 1) - __ldg(pos + t * 3 + 1);
    float dz = __ldg(pos + s * 3 + 2) - __ldg(pos + t * 3 + 2);
    float u = sqrtf(dx * dx + dy * dy + dz * dz) * TINV;
    int uq = min((int)(u * 64.0f), (TABN - 1) * 64 - 1);   // i0 <= TABN-2
    int slot = atomicAdd(&g_cursor[t], 1);
    g_erec[slot] = ((unsigned)s << 16) | (unsigned)uq;
}

// ---------------- filter lookup tables ----------------------------------
__global__ void __launch_bounds__(256) build_tab_kernel(
    const float* __restrict__ mw1, const float* __restrict__ mb1,
    const float* __restrict__ mw2, const float* __restrict__ mb2) {
    int layer = blockIdx.y;
    __shared__ float s_w1[GDIM * FDIM];
    __shared__ float s_w2[FDIM * FDIM];
    __shared__ float s_b1[FDIM], s_b2[FDIM];
    __shared__ float s_g[8][64];
    __shared__ float s_act[8][FDIM];

    int t = threadIdx.x;
    for (int i = t; i < GDIM * FDIM; i += 256)
        s_w1[i] = __ldg(mw1 + layer * GDIM * FDIM + i);
    for (int i = t; i < FDIM * FDIM; i += 256)
        s_w2[i] = __ldg(mw2 + layer * FDIM * FDIM + i);
    if (t < FDIM) {
        s_b1[t] = __ldg(mb1 + layer * FDIM + t);
        s_b2[t] = __ldg(mb2 + layer * FDIM + t);
    }
    __syncthreads();

    int wl = t >> 5, lane = t & 31;
    const float offstep = 10.0f / 49.0f;
    const float coeff   = -0.5f / (offstep * offstep);

    for (int ti = blockIdx.x * 8 + wl; ti < TABN; ti += gridDim.x * 8) {
        float dv = ti * TSTEP;
        for (int g = lane; g < GDIM; g += 32) {
            float x = dv - g * offstep;
            s_g[wl][g] = expf(coeff * x * x);
        }
        __syncwarp();

        ull acc = pack2(s_b1[2 * lane], s_b1[2 * lane + 1]);
        for (int g = 0; g < GDIM; g++) {
            float e = s_g[wl][g];
            ull wv = ((const ull*)(s_w1 + g * FDIM))[lane];
            acc = ffma2(pack2(e, e), wv, acc);
        }
        float2 a = unpack2(acc);
        s_act[wl][2 * lane]     = sspf(a.x);
        s_act[wl][2 * lane + 1] = sspf(a.y);
        __syncwarp();

        ull acc2 = pack2(s_b2[2 * lane], s_b2[2 * lane + 1]);
        for (int f = 0; f < FDIM; f++) {
            float tv = s_act[wl][f];
            ull wv = ((const ull*)(s_w2 + f * FDIM))[lane];
            acc2 = ffma2(pack2(tv, tv), wv, acc2);
        }
        float C = 0.5f * (cosf(dv * 3.14159265358979323846f / 10.0f) + 1.0f);
        float2 c2 = unpack2(acc2);
        g_tabh[(layer * TABN + ti) * 32 + lane] =
            __floats2half2_rn(c2.x * C, c2.y * C);
        __syncwarp();
    }
}

// ---------------- weight -> mma B-fragment converter --------------------
struct WConvDesc { const float* src; int ind; int outd; int dstoff; };
struct WConvPack { WConvDesc d[10]; };

__global__ void wconv_kernel(WConvPack p) {
    WConvDesc dd = p.d[blockIdx.y];
    int total = dd.ind * dd.outd / 4;
    int u = blockIdx.x * blockDim.x + threadIdx.x;
    if (u >= total) return;
    int lane = u & 31;
    int ot8  = dd.outd >> 3;
    int nt   = (u >> 5) % ot8;
    int ks   = (u >> 5) / ot8;
    int n  = nt * 8 + (lane >> 2);
    int k0 = ks * 16 + (lane & 3) * 2;
    const float* s = dd.src;
    __half2 lo = __floats2half2_rn(s[k0 * dd.outd + n], s[(k0 + 1) * dd.outd + n]);
    __half2 hi = __floats2half2_rn(s[(k0 + 8) * dd.outd + n], s[(k0 + 9) * dd.outd + n]);
    __half2* dst = (__half2*)(g_wfrag + dd.dstoff + u * 4);
    dst[0] = lo;
    dst[1] = hi;
}

// ---------------- one MMA stage (64-node tile) --------------------------
template <int IN, int OUT, bool ACT, bool RESID>
__device__ __forceinline__ void stage_mma(
    const __half* sIn, __half* sOut, int tile,
    float* gF, __half2* gH, const ull* wf, const float* bias_p) {
    constexpr int NG   = OUT / 32;
    constexpr int MT   = (NG == 4) ? 2 : 1;
    constexpr int KS   = IN / 16;
    constexpr int ISTR = IN + 8;
    constexpr int OSTR = OUT + 8;

    int t = threadIdx.x, lane = t & 31, w = t >> 5;
    int ng = w % NG, mg = w / NG;

    unsigned bf[4 * KS * 2];
#pragma unroll
    for (int nt = 0; nt < 4; nt++)
#pragma unroll
        for (int ks = 0; ks < KS; ks++) {
            ull v = __ldg(wf + (ks * (OUT / 8) + ng * 4 + nt) * 32 + lane);
            bf[(nt * KS + ks) * 2]     = (unsigned)(v & 0xffffffffu);
            bf[(nt * KS + ks) * 2 + 1] = (unsigned)(v >> 32);
        }
    float2 bs[4];
#pragma unroll
    for (int nt = 0; nt < 4; nt++) {
        int c = ng * 32 + nt * 8 + (lane & 3) * 2;
        bs[nt] = bias_p ? make_float2(__ldg(bias_p + c), __ldg(bias_p + c + 1))
                        : make_float2(0.f, 0.f);
    }

    int grp    = lane >> 3;
    int arow_l = (lane & 7) + ((grp & 1) << 3);
    int acolh  = (grp >> 1) << 3;

#pragma unroll
    for (int mt = 0; mt < MT; mt++) {
        int mrow = mg * (MT * 16) + mt * 16;
        float acc[4][4];
#pragma unroll
        for (int nt = 0; nt < 4; nt++) {
            acc[nt][0] = bs[nt].x; acc[nt][1] = bs[nt].y;
            acc[nt][2] = bs[nt].x; acc[nt][3] = bs[nt].y;
        }
        unsigned abase = smem_u32(sIn + (mrow + arow_l) * ISTR + acolh);
#pragma unroll
        for (int ks = 0; ks < KS; ks++) {
            unsigned a0, a1, a2, a3;
            asm volatile(
                "ldmatrix.sync.aligned.m8n8.x4.shared.b16 {%0,%1,%2,%3}, [%4];"
                : "=r"(a0), "=r"(a1), "=r"(a2), "=r"(a3)
                : "r"(abase + ks * 32));
#pragma unroll
            for (int nt = 0; nt < 4; nt++) {
                asm volatile(
                    "mma.sync.aligned.m16n8k16.row.col.f32.f16.f16.f32 "
                    "{%0,%1,%2,%3}, {%4,%5,%6,%7}, {%8,%9}, {%0,%1,%2,%3};"
                    : "+f"(acc[nt][0]), "+f"(acc[nt][1]),
                      "+f"(acc[nt][2]), "+f"(acc[nt][3])
                    : "r"(a0), "r"(a1), "r"(a2), "r"(a3),
                      "r"(bf[(nt * KS + ks) * 2]),
                      "r"(bf[(nt * KS + ks) * 2 + 1]));
            }
        }
        int rl = mrow + (lane >> 2);
        int r0 = tile * 64 + rl;
        int cb = ng * 32 + (lane & 3) * 2;
#pragma unroll
        for (int nt = 0; nt < 4; nt++) {
            int col = cb + nt * 8;
            float2 v0 = make_float2(acc[nt][0], acc[nt][1]);
            float2 v1 = make_float2(acc[nt][2], acc[nt][3]);
            if (ACT) {
                v0.x = sspf(v0.x); v0.y = sspf(v0.y);
                v1.x = sspf(v1.x); v1.y = sspf(v1.y);
            }
            if (RESID) {
                float2 p0 = *(const float2*)(gF + r0 * OUT + col);
                float2 p1 = *(const float2*)(gF + (r0 + 8) * OUT + col);
                v0.x += p0.x; v0.y += p0.y;
                v1.x += p1.x; v1.y += p1.y;
            }
            if (gF) {
                *(float2*)(gF + r0 * OUT + col)       = v0;
                *(float2*)(gF + (r0 + 8) * OUT + col) = v1;
            }
            if (sOut) {
                *(__half2*)(sOut + rl * OSTR + col)       = __floats2half2_rn(v0.x, v0.y);
                *(__half2*)(sOut + (rl + 8) * OSTR + col) = __floats2half2_rn(v1.x, v1.y);
            }
            if (gH) {
                gH[r0 * (OUT / 2) + col / 2]       = __floats2half2_rn(v0.x, v0.y);
                gH[(r0 + 8) * (OUT / 2) + col / 2] = __floats2half2_rn(v1.x, v1.y);
            }
        }
    }
}

// ---------------- init: h = emb[z], xth = h @ l1w[0] --------------------
__global__ void __launch_bounds__(256, 2) init_xth_kernel(
    const int* __restrict__ z, const float* __restrict__ emb,
    const ull* __restrict__ wfC) {
    __shared__ __half bufH[64 * 136];
    int t = threadIdx.x;
    for (int tile = blockIdx.x; tile < NTILES; tile += gridDim.x) {
        for (int i = t; i < 64 * 32; i += 256) {
            int row = i >> 5, c = i & 31;
            int n = tile * 64 + row;
            float4 v = make_float4(0.f, 0.f, 0.f, 0.f);
            if (n < NATOMS) v = ((const float4*)emb)[__ldg(z + n) * 32 + c];
            ((float4*)g_h)[n * 32 + c] = v;
            __half2* d = (__half2*)(bufH + row * 136 + c * 4);
            d[0] = __floats2half2_rn(v.x, v.y);
            d[1] = __floats2half2_rn(v.z, v.w);
        }
        __syncthreads();
        stage_mma<128, 64, false, false>(bufH, nullptr, tile, nullptr,
                                         g_xth, wfC, nullptr);
        __syncthreads();
    }
}

// ---------------- node phase ----------------
template <bool LAST>
__global__ void __launch_bounds__(256, 2) node_phase_kernel(
    const float* __restrict__ l2b_l, const float* __restrict__ lb_l,
    const ull* __restrict__ wfA, const ull* __restrict__ wfB,
    const ull* __restrict__ wfC,
    const float* __restrict__ ob1, const float* __restrict__ ow2,
    const float* __restrict__ ob2, const int* __restrict__ batch,
    float* __restrict__ out) {
    __shared__ __half bufA[64 * 72];
    __shared__ __half bufT[64 * 136];
    __shared__ __half bufH[64 * 136];

    int t = threadIdx.x, lane = t & 31, w = t >> 5;
    float2 w2v = LAST ? *(const float2*)(ow2 + lane * 2) : make_float2(0.f, 0.f);
    float ob2v = LAST ? __ldg(ob2) : 0.f;

    for (int tile = blockIdx.x; tile < NTILES; tile += gridDim.x) {
        // copy agg (fp16) -> bufA  (uint4 = 8 halfs)
        const uint4* src = (const uint4*)(g_aggh + tile * 64 * 32);
        for (int i = t; i < 64 * 8; i += 256) {
            int row = i >> 3, c8 = i & 7;
            *(uint4*)(bufA + row * 72 + c8 * 8) = src[i];
        }
        __syncthreads();
        stage_mma<64, 128, true, false>(bufA, bufT, tile, nullptr, nullptr,
                                        wfA, l2b_l);
        __syncthreads();
        stage_mma<128, 128, false, true>(bufT, bufH, tile, g_h, nullptr,
                                         wfB, lb_l);
        __syncthreads();
        if (!LAST) {
            stage_mma<128, 64, false, false>(bufH, nullptr, tile, nullptr,
                                             g_xth, wfC, nullptr);
        } else {
            stage_mma<128, 64, true, false>(bufH, bufA, tile, nullptr,
                                            nullptr, wfC, ob1);
            __syncthreads();
#pragma unroll
            for (int i = 0; i < 8; i++) {
                int rl = w * 8 + i;
                int n  = tile * 64 + rl;
                if (n < NATOMS) {
                    float2 f = __half22float2(
                        *(const __half2*)(bufA + rl * 72 + lane * 2));
                    float s = f.x * w2v.x + f.y * w2v.y;
#pragma unroll
                    for (int off = 16; off; off >>= 1)
                        s += __shfl_down_sync(0xffffffffu, s, off);
                    if (lane == 0)
                        atomicAdd(out + __ldg(batch + n), s + ob2v);
                }
            }
        }
        __syncthreads();
    }
}

// ---------------- gather: smem table, packed records, half2 math --------
__global__ void __launch_bounds__(GT_THREADS) gather_smem_kernel(
    const __half2* __restrict__ tab) {
    extern __shared__ __align__(16) __half s_tab[];

    {
        const float4* src = (const float4*)tab;
        float4* dst = (float4*)s_tab;
        for (int i = threadIdx.x; i < TAB_BYTES / 16; i += GT_THREADS)
            dst[i] = src[i];
    }
    __syncthreads();

    int lane = threadIdx.x & 31;
    int hw   = lane >> 4;
    int c    = lane & 15;
    int warp = threadIdx.x >> 5;
    int gw0  = blockIdx.x * (GT_THREADS / 32) + warp;
    int nw   = gridDim.x * (GT_THREADS / 32);
    const __half* xth = (const __half*)g_xth;

    for (int node = gw0; node < NPAD; node += nw) {
        int beg = g_rowptr[node];
        int end = g_rowptr[node + 1];
        float4 acc = make_float4(0.f, 0.f, 0.f, 0.f);

        for (int base = beg; base < end; base += 32) {
            int cnt = min(32, end - base);
            unsigned myrec = 0;
            if (lane < cnt) myrec = __ldg(&g_erec[base + lane]);

#pragma unroll 4
            for (int j = 0; j < cnt; j += 2) {
                int sl = j + hw;
                unsigned rec = __shfl_sync(0xffffffffu, myrec, sl);
                bool valid = sl < cnt;
                int s  = rec >> 16;
                int uq = rec & 0xffff;
                int i0 = uq >> 6;
                __half2 fr2 = __float2half2_rn((float)(uq & 63) * 0.015625f);

                uint2 t0 = *(const uint2*)(s_tab + i0 * 64 + c * 4);
                uint2 t1 = *(const uint2*)(s_tab + (i0 + 1) * 64 + c * 4);
                uint2 xv = *(const uint2*)(xth + s * 64 + c * 4);

                __half2 a0 = u_as_h2(t0.x), a1 = u_as_h2(t0.y);
                __half2 w0 = __hfma2(fr2, __hsub2(u_as_h2(t1.x), a0), a0);
                __half2 w1 = __hfma2(fr2, __hsub2(u_as_h2(t1.y), a1), a1);
                __half2 m0 = __hmul2(w0, u_as_h2(xv.x));
                __half2 m1 = __hmul2(w1, u_as_h2(xv.y));
                float2 f0 = __half22float2(m0);
                float2 f1 = __half22float2(m1);
                if (valid) {
                    acc.x += f0.x; acc.y += f0.y;
                    acc.z += f1.x; acc.w += f1.y;
                }
            }
        }
        acc.x += __shfl_xor_sync(0xffffffffu, acc.x, 16);
        acc.y += __shfl_xor_sync(0xffffffffu, acc.y, 16);
        acc.z += __shfl_xor_sync(0xffffffffu, acc.z, 16);
        acc.w += __shfl_xor_sync(0xffffffffu, acc.w, 16);
        if (hw == 0) {
            uint2 o;
            o.x = h2_as_u(__floats2half2_rn(acc.x, acc.y));
            o.y = h2_as_u(__floats2half2_rn(acc.z, acc.w));
            ((uint2*)g_aggh)[node * 16 + c] = o;
        }
    }
}

extern "C" void kernel_launch(void* const* d_in, const int* in_sizes, int n_in,
                              void* d_out, int out_size) {
    const int*   z     = (const int*)  d_in[0];
    const float* pos   = (const float*)d_in[1];
    const int*   batch = (const int*)  d_in[2];
    const int*   eidx  = (const int*)  d_in[3];
    const float* emb   = (const float*)d_in[4];
    const float* mw1   = (const float*)d_in[5];
    const float* mb1   = (const float*)d_in[6];
    const float* mw2   = (const float*)d_in[7];
    const float* mb2   = (const float*)d_in[8];
    const float* l1w   = (const float*)d_in[9];
    const float* l2w   = (const float*)d_in[10];
    const float* l2b   = (const float*)d_in[11];
    const float* lw    = (const float*)d_in[12];
    const float* lb    = (const float*)d_in[13];
    const float* ow1   = (const float*)d_in[14];
    const float* ob1   = (const float*)d_in[15];
    const float* ow2   = (const float*)d_in[16];
    const float* ob2   = (const float*)d_in[17];
    float* out = (float*)d_out;

    __half2 *ptabh;
    __half *pwf;
    cudaGetSymbolAddress((void**)&ptabh, g_tabh);
    cudaGetSymbolAddress((void**)&pwf,   g_wfrag);

    static cudaStream_t s1 = nullptr;
    static cudaEvent_t ev0 = nullptr, ev1 = nullptr;
    if (!s1) {
        cudaFuncSetAttribute(gather_smem_kernel,
                             cudaFuncAttributeMaxDynamicSharedMemorySize,
                             TAB_BYTES);
        cudaStreamCreateWithFlags(&s1, cudaStreamNonBlocking);
        cudaEventCreateWithFlags(&ev0, cudaEventDisableTiming);
        cudaEventCreateWithFlags(&ev1, cudaEventDisableTiming);
    }

    // ---- fork side stream: weights/tables/init (independent of CSR) ----
    cudaEventRecord(ev0, 0);
    cudaStreamWaitEvent(s1, ev0, 0);
    {
        WConvPack p;
        for (int l = 0; l < NLAY; l++) {
            p.d[l]     = { l1w + l * HDIM * FDIM, HDIM, FDIM, l * 32768 };
            p.d[3 + l] = { l2w + l * FDIM * HDIM, FDIM, HDIM, l * 32768 + 8192 };
            p.d[6 + l] = { lw  + l * HDIM * HDIM, HDIM, HDIM, l * 32768 + 16384 };
        }
        p.d[9] = { ow1, HDIM, FDIM, 98304 };
        dim3 g(16, 10);
        wconv_kernel<<<g, 256, 0, s1>>>(p);
    }
    {
        dim3 g(TABN / 8, NLAY);
        build_tab_kernel<<<g, 256, 0, s1>>>(mw1, mb1, mw2, mb2);
    }
    init_xth_kernel<<<296, 256, 0, s1>>>(z, emb, (const ull*)pwf);
    cudaEventRecord(ev1, s1);

    // ---- main stream: CSR build ----
    zero2_kernel<<<(NPAD / 4 + 255) / 256, 256>>>(out);
    degree_kernel<<<(NEDGE + 255) / 256, 256>>>(eidx);
    part_sum_kernel<<<NCHUNK, SCAN_B>>>();
    spine_kernel<<<1, 128>>>();
    scan_write_kernel<<<NCHUNK, SCAN_B>>>();
    scatter_kernel<<<(NEDGE + 255) / 256, 256>>>(eidx, pos);

    // join
    cudaStreamWaitEvent(0, ev1, 0);

    const int NB = 296;
    const int GGB = 148;

    for (int l = 0; l < NLAY; l++) {
        gather_smem_kernel<<<GGB, GT_THREADS, TAB_BYTES>>>(ptabh + l * TABN * 32);
        const ull* wfA = (const ull*)(pwf + l * 32768 + 8192);
        const ull* wfB = (const ull*)(pwf + l * 32768 + 16384);
        if (l < NLAY - 1) {
            const ull* wfC = (const ull*)(pwf + (l + 1) * 32768);
            node_phase_kernel<false><<<NB, 256>>>(
                l2b + l * HDIM, lb + l * HDIM, wfA, wfB, wfC,
                nullptr, nullptr, nullptr, nullptr, nullptr);
        } else {
            const ull* wfC = (const ull*)(pwf + 98304);
            node_phase_kernel<true><<<NB, 256>>>(
                l2b + l * HDIM, lb + l * HDIM, wfA, wfB, wfC,
                ob1, ow2, ob2, batch, out);
        }
    }
}

// round 15
// speedup vs baseline: 2.8066x; 1.1237x over previous
#include <cuda_runtime.h>
#include <cuda_fp16.h>
#include <math.h>

#define NATOMS 50000
#define NPAD   50048          // 64-node tiles (782 tiles)
#define NTILES (NPAD / 64)
#define NEDGE  1600000
#define HDIM   128
#define FDIM   64
#define GDIM   50
#define NLAY   3
#define NGRAPH 256
#define TABN   1024           // 1024 rows x 64ch fp16 = 128 KB (L2-resident)
#define DMAXV  8.6603f
#define TSTEP  (DMAXV / (TABN - 1))
#define TINV   ((TABN - 1) / DMAXV)

#define SCAN_B 512
#define NCHUNK ((NPAD + SCAN_B - 1) / SCAN_B)   // 98

typedef unsigned long long ull;

// ---- scratch (device globals; no allocation allowed) ----
__device__ float    g_h    [NPAD * HDIM];
__device__ __half2  g_xth  [NPAD * FDIM / 2];
__device__ __half2  g_aggh [NPAD * FDIM / 2];
__device__ __half2  g_tabh [NLAY * TABN * FDIM / 2];
__device__ int      g_deg  [NPAD];
__device__ int      g_rowptr[NPAD + 1];
__device__ int      g_cursor[NPAD];
__device__ int      g_part [NCHUNK];
__device__ unsigned g_erec [NEDGE];    // src<<16 | u fixed-point (10.6)
__device__ __half   g_wfrag[106496];

__device__ __forceinline__ float sspf(float x) {
    float sp = fmaxf(x, 0.0f) + log1pf(__expf(-fabsf(x)));
    return sp - 0.69314718055994531f;
}
__device__ __forceinline__ __half2 u_as_h2(unsigned u) {
    return *reinterpret_cast<__half2*>(&u);
}
__device__ __forceinline__ unsigned h2_as_u(__half2 h) {
    return *reinterpret_cast<unsigned*>(&h);
}
__device__ __forceinline__ unsigned smem_u32(const void* p) {
    return (unsigned)__cvta_generic_to_shared(p);
}

// ---- packed f32x2 helpers ----
__device__ __forceinline__ ull ffma2(ull a, ull b, ull c) {
    ull d;
    asm("fma.rn.f32x2 %0, %1, %2, %3;" : "=l"(d) : "l"(a), "l"(b), "l"(c));
    return d;
}
__device__ __forceinline__ ull pack2(float x, float y) {
    ull r;
    asm("mov.b64 %0, {%1, %2};" : "=l"(r) : "f"(x), "f"(y));
    return r;
}
__device__ __forceinline__ float2 unpack2(ull v) {
    float2 r;
    asm("mov.b64 {%0, %1}, %2;" : "=f"(r.x), "=f"(r.y) : "l"(v));
    return r;
}

// ---------------- fused zero: out + deg ----------------
__global__ void zero2_kernel(float* __restrict__ out) {
    int i = blockIdx.x * blockDim.x + threadIdx.x;
    if (i < NPAD / 4) ((float4*)g_deg)[i] = make_float4(0.f, 0.f, 0.f, 0.f);
    if (i < NGRAPH) out[i] = 0.f;
}

// ---------------- degree count ----------------
__global__ void degree_kernel(const int* __restrict__ ei) {
    int e = blockIdx.x * blockDim.x + threadIdx.x;
    if (e >= NEDGE) return;
    atomicAdd(&g_deg[__ldg(ei + NEDGE + e)], 1);
}

// ---------------- CSR scan pieces ----------------
__global__ void __launch_bounds__(SCAN_B) part_sum_kernel() {
    __shared__ int sh[SCAN_B];
    int idx = blockIdx.x * SCAN_B + threadIdx.x;
    int v = (idx < NPAD) ? g_deg[idx] : 0;
    sh[threadIdx.x] = v;
    __syncthreads();
    for (int s = SCAN_B / 2; s > 0; s >>= 1) {
        if (threadIdx.x < s) sh[threadIdx.x] += sh[threadIdx.x + s];
        __syncthreads();
    }
    if (threadIdx.x == 0) g_part[blockIdx.x] = sh[0];
}

__global__ void spine_kernel() {
    __shared__ int swp[4];
    int t = threadIdx.x;
    int lane = t & 31, w = t >> 5;
    int v = (t < NCHUNK) ? g_part[t] : 0;
    int s = v;
#pragma unroll
    for (int off = 1; off < 32; off <<= 1) {
        int n = __shfl_up_sync(0xffffffffu, s, off);
        if (lane >= off) s += n;
    }
    if (lane == 31) swp[w] = s;
    __syncthreads();
    if (t < 4) {
        int x = swp[t];
#pragma unroll
        for (int off = 1; off < 4; off <<= 1) {
            int n = __shfl_up_sync(0xfu, x, off);
            if (t >= off) x += n;
        }
        swp[t] = x;
    }
    __syncthreads();
    int excl = s - v + (w > 0 ? swp[w - 1] : 0);
    if (t < NCHUNK) g_part[t] = excl;
    if (t == 0) g_rowptr[NPAD] = NEDGE;
}

__global__ void __launch_bounds__(SCAN_B) scan_write_kernel() {
    __shared__ int sh[SCAN_B];
    int idx = blockIdx.x * SCAN_B + threadIdx.x;
    int own = (idx < NPAD) ? g_deg[idx] : 0;
    sh[threadIdx.x] = own;
    __syncthreads();
    for (int s = 1; s < SCAN_B; s <<= 1) {
        int v = (threadIdx.x >= s) ? sh[threadIdx.x - s] : 0;
        __syncthreads();
        sh[threadIdx.x] += v;
        __syncthreads();
    }
    if (idx < NPAD) {
        int excl = g_part[blockIdx.x] + sh[threadIdx.x] - own;
        g_rowptr[idx] = excl;
        g_cursor[idx] = excl;
    }
}

// ---------------- CSR scatter: pack src(16b) | u(10.6 fixed) ------------
__global__ void scatter_kernel(const int* __restrict__ ei,
                               const float* __restrict__ pos) {
    int e = blockIdx.x * blockDim.x + threadIdx.x;
    if (e >= NEDGE) return;
    int s = __ldg(ei + e);
    int t = __ldg(ei + NEDGE + e);
    float dx = __ldg(pos + s * 3 + 0) - __ldg(pos + t * 3 + 0);
    float dy = __ldg(pos + s * 3 + 1) - __ldg(pos + t * 3 + 1);
    float dz = __ldg(pos + s * 3 + 2) - __ldg(pos + t * 3 + 2);
    float u = sqrtf(dx * dx + dy * dy + dz * dz) * TINV;
    int uq = min((int)(u * 64.0f), (TABN - 1) * 64 - 1);   // i0 <= TABN-2
    int slot = atomicAdd(&g_cursor[t], 1);
    g_erec[slot] = ((unsigned)s << 16) | (unsigned)uq;
}

// ---------------- filter lookup tables ----------------------------------
__global__ void __launch_bounds__(256) build_tab_kernel(
    const float* __restrict__ mw1, const float* __restrict__ mb1,
    const float* __restrict__ mw2, const float* __restrict__ mb2) {
    int layer = blockIdx.y;
    __shared__ float s_w1[GDIM * FDIM];
    __shared__ float s_w2[FDIM * FDIM];
    __shared__ float s_b1[FDIM], s_b2[FDIM];
    __shared__ float s_g[8][64];
    __shared__ float s_act[8][FDIM];

    int t = threadIdx.x;
    for (int i = t; i < GDIM * FDIM; i += 256)
        s_w1[i] = __ldg(mw1 + layer * GDIM * FDIM + i);
    for (int i = t; i < FDIM * FDIM; i += 256)
        s_w2[i] = __ldg(mw2 + layer * FDIM * FDIM + i);
    if (t < FDIM) {
        s_b1[t] = __ldg(mb1 + layer * FDIM + t);
        s_b2[t] = __ldg(mb2 + layer * FDIM + t);
    }
    __syncthreads();

    int wl = t >> 5, lane = t & 31;
    const float offstep = 10.0f / 49.0f;
    const float coeff   = -0.5f / (offstep * offstep);

    for (int ti = blockIdx.x * 8 + wl; ti < TABN; ti += gridDim.x * 8) {
        float dv = ti * TSTEP;
        for (int g = lane; g < GDIM; g += 32) {
            float x = dv - g * offstep;
            s_g[wl][g] = expf(coeff * x * x);
        }
        __syncwarp();

        ull acc = pack2(s_b1[2 * lane], s_b1[2 * lane + 1]);
        for (int g = 0; g < GDIM; g++) {
            float e = s_g[wl][g];
            ull wv = ((const ull*)(s_w1 + g * FDIM))[lane];
            acc = ffma2(pack2(e, e), wv, acc);
        }
        float2 a = unpack2(acc);
        s_act[wl][2 * lane]     = sspf(a.x);
        s_act[wl][2 * lane + 1] = sspf(a.y);
        __syncwarp();

        ull acc2 = pack2(s_b2[2 * lane], s_b2[2 * lane + 1]);
        for (int f = 0; f < FDIM; f++) {
            float tv = s_act[wl][f];
            ull wv = ((const ull*)(s_w2 + f * FDIM))[lane];
            acc2 = ffma2(pack2(tv, tv), wv, acc2);
        }
        float C = 0.5f * (cosf(dv * 3.14159265358979323846f / 10.0f) + 1.0f);
        float2 c2 = unpack2(acc2);
        g_tabh[(layer * TABN + ti) * 32 + lane] =
            __floats2half2_rn(c2.x * C, c2.y * C);
        __syncwarp();
    }
}

// ---------------- weight -> mma B-fragment converter --------------------
struct WConvDesc { const float* src; int ind; int outd; int dstoff; };
struct WConvPack { WConvDesc d[10]; };

__global__ void wconv_kernel(WConvPack p) {
    WConvDesc dd = p.d[blockIdx.y];
    int total = dd.ind * dd.outd / 4;
    int u = blockIdx.x * blockDim.x + threadIdx.x;
    if (u >= total) return;
    int lane = u & 31;
    int ot8  = dd.outd >> 3;
    int nt   = (u >> 5) % ot8;
    int ks   = (u >> 5) / ot8;
    int n  = nt * 8 + (lane >> 2);
    int k0 = ks * 16 + (lane & 3) * 2;
    const float* s = dd.src;
    __half2 lo = __floats2half2_rn(s[k0 * dd.outd + n], s[(k0 + 1) * dd.outd + n]);
    __half2 hi = __floats2half2_rn(s[(k0 + 8) * dd.outd + n], s[(k0 + 9) * dd.outd + n]);
    __half2* dst = (__half2*)(g_wfrag + dd.dstoff + u * 4);
    dst[0] = lo;
    dst[1] = hi;
}

// ---------------- one MMA stage (64-node tile) --------------------------
template <int IN, int OUT, bool ACT, bool RESID>
__device__ __forceinline__ void stage_mma(
    const __half* sIn, __half* sOut, int tile,
    float* gF, __half2* gH, const ull* wf, const float* bias_p) {
    constexpr int NG   = OUT / 32;
    constexpr int MT   = (NG == 4) ? 2 : 1;
    constexpr int KS   = IN / 16;
    constexpr int ISTR = IN + 8;
    constexpr int OSTR = OUT + 8;

    int t = threadIdx.x, lane = t & 31, w = t >> 5;
    int ng = w % NG, mg = w / NG;

    unsigned bf[4 * KS * 2];
#pragma unroll
    for (int nt = 0; nt < 4; nt++)
#pragma unroll
        for (int ks = 0; ks < KS; ks++) {
            ull v = __ldg(wf + (ks * (OUT / 8) + ng * 4 + nt) * 32 + lane);
            bf[(nt * KS + ks) * 2]     = (unsigned)(v & 0xffffffffu);
            bf[(nt * KS + ks) * 2 + 1] = (unsigned)(v >> 32);
        }
    float2 bs[4];
#pragma unroll
    for (int nt = 0; nt < 4; nt++) {
        int c = ng * 32 + nt * 8 + (lane & 3) * 2;
        bs[nt] = bias_p ? make_float2(__ldg(bias_p + c), __ldg(bias_p + c + 1))
                        : make_float2(0.f, 0.f);
    }

    int grp    = lane >> 3;
    int arow_l = (lane & 7) + ((grp & 1) << 3);
    int acolh  = (grp >> 1) << 3;

#pragma unroll
    for (int mt = 0; mt < MT; mt++) {
        int mrow = mg * (MT * 16) + mt * 16;
        float acc[4][4];
#pragma unroll
        for (int nt = 0; nt < 4; nt++) {
            acc[nt][0] = bs[nt].x; acc[nt][1] = bs[nt].y;
            acc[nt][2] = bs[nt].x; acc[nt][3] = bs[nt].y;
        }
        unsigned abase = smem_u32(sIn + (mrow + arow_l) * ISTR + acolh);
#pragma unroll
        for (int ks = 0; ks < KS; ks++) {
            unsigned a0, a1, a2, a3;
            asm volatile(
                "ldmatrix.sync.aligned.m8n8.x4.shared.b16 {%0,%1,%2,%3}, [%4];"
                : "=r"(a0), "=r"(a1), "=r"(a2), "=r"(a3)
                : "r"(abase + ks * 32));
#pragma unroll
            for (int nt = 0; nt < 4; nt++) {
                asm volatile(
                    "mma.sync.aligned.m16n8k16.row.col.f32.f16.f16.f32 "
                    "{%0,%1,%2,%3}, {%4,%5,%6,%7}, {%8,%9}, {%0,%1,%2,%3};"
                    : "+f"(acc[nt][0]), "+f"(acc[nt][1]),
                      "+f"(acc[nt][2]), "+f"(acc[nt][3])
                    : "r"(a0), "r"(a1), "r"(a2), "r"(a3),
                      "r"(bf[(nt * KS + ks) * 2]),
                      "r"(bf[(nt * KS + ks) * 2 + 1]));
            }
        }
        int rl = mrow + (lane >> 2);
        int r0 = tile * 64 + rl;
        int cb = ng * 32 + (lane & 3) * 2;
#pragma unroll
        for (int nt = 0; nt < 4; nt++) {
            int col = cb + nt * 8;
            float2 v0 = make_float2(acc[nt][0], acc[nt][1]);
            float2 v1 = make_float2(acc[nt][2], acc[nt][3]);
            if (ACT) {
                v0.x = sspf(v0.x); v0.y = sspf(v0.y);
                v1.x = sspf(v1.x); v1.y = sspf(v1.y);
            }
            if (RESID) {
                float2 p0 = *(const float2*)(gF + r0 * OUT + col);
                float2 p1 = *(const float2*)(gF + (r0 + 8) * OUT + col);
                v0.x += p0.x; v0.y += p0.y;
                v1.x += p1.x; v1.y += p1.y;
            }
            if (gF) {
                *(float2*)(gF + r0 * OUT + col)       = v0;
                *(float2*)(gF + (r0 + 8) * OUT + col) = v1;
            }
            if (sOut) {
                *(__half2*)(sOut + rl * OSTR + col)       = __floats2half2_rn(v0.x, v0.y);
                *(__half2*)(sOut + (rl + 8) * OSTR + col) = __floats2half2_rn(v1.x, v1.y);
            }
            if (gH) {
                gH[r0 * (OUT / 2) + col / 2]       = __floats2half2_rn(v0.x, v0.y);
                gH[(r0 + 8) * (OUT / 2) + col / 2] = __floats2half2_rn(v1.x, v1.y);
            }
        }
    }
}

// ---------------- init: h = emb[z], xth = h @ l1w[0] --------------------
__global__ void __launch_bounds__(256, 2) init_xth_kernel(
    const int* __restrict__ z, const float* __restrict__ emb,
    const ull* __restrict__ wfC) {
    __shared__ __half bufH[64 * 136];
    int t = threadIdx.x;
    for (int tile = blockIdx.x; tile < NTILES; tile += gridDim.x) {
        for (int i = t; i < 64 * 32; i += 256) {
            int row = i >> 5, c = i & 31;
            int n = tile * 64 + row;
            float4 v = make_float4(0.f, 0.f, 0.f, 0.f);
            if (n < NATOMS) v = ((const float4*)emb)[__ldg(z + n) * 32 + c];
            ((float4*)g_h)[n * 32 + c] = v;
            __half2* d = (__half2*)(bufH + row * 136 + c * 4);
            d[0] = __floats2half2_rn(v.x, v.y);
            d[1] = __floats2half2_rn(v.z, v.w);
        }
        __syncthreads();
        stage_mma<128, 64, false, false>(bufH, nullptr, tile, nullptr,
                                         g_xth, wfC, nullptr);
        __syncthreads();
    }
}

// ---------------- node phase ----------------
template <bool LAST>
__global__ void __launch_bounds__(256, 2) node_phase_kernel(
    const float* __restrict__ l2b_l, const float* __restrict__ lb_l,
    const ull* __restrict__ wfA, const ull* __restrict__ wfB,
    const ull* __restrict__ wfC,
    const float* __restrict__ ob1, const float* __restrict__ ow2,
    const float* __restrict__ ob2, const int* __restrict__ batch,
    float* __restrict__ out) {
    __shared__ __half bufA[64 * 72];
    __shared__ __half bufT[64 * 136];
    __shared__ __half bufH[64 * 136];

    int t = threadIdx.x, lane = t & 31, w = t >> 5;
    float2 w2v = LAST ? *(const float2*)(ow2 + lane * 2) : make_float2(0.f, 0.f);
    float ob2v = LAST ? __ldg(ob2) : 0.f;

    for (int tile = blockIdx.x; tile < NTILES; tile += gridDim.x) {
        // copy agg (fp16) -> bufA  (uint4 = 8 halfs)
        const uint4* src = (const uint4*)(g_aggh + tile * 64 * 32);
        for (int i = t; i < 64 * 8; i += 256) {
            int row = i >> 3, c8 = i & 7;
            *(uint4*)(bufA + row * 72 + c8 * 8) = src[i];
        }
        __syncthreads();
        stage_mma<64, 128, true, false>(bufA, bufT, tile, nullptr, nullptr,
                                        wfA, l2b_l);
        __syncthreads();
        stage_mma<128, 128, false, true>(bufT, bufH, tile, g_h, nullptr,
                                         wfB, lb_l);
        __syncthreads();
        if (!LAST) {
            stage_mma<128, 64, false, false>(bufH, nullptr, tile, nullptr,
                                             g_xth, wfC, nullptr);
        } else {
            stage_mma<128, 64, true, false>(bufH, bufA, tile, nullptr,
                                            nullptr, wfC, ob1);
            __syncthreads();
#pragma unroll
            for (int i = 0; i < 8; i++) {
                int rl = w * 8 + i;
                int n  = tile * 64 + rl;
                if (n < NATOMS) {
                    float2 f = __half22float2(
                        *(const __half2*)(bufA + rl * 72 + lane * 2));
                    float s = f.x * w2v.x + f.y * w2v.y;
#pragma unroll
                    for (int off = 16; off; off >>= 1)
                        s += __shfl_down_sync(0xffffffffu, s, off);
                    if (lane == 0)
                        atomicAdd(out + __ldg(batch + n), s + ob2v);
                }
            }
        }
        __syncthreads();
    }
}

// ---------------- gather: L2 table, full occupancy, warp per node -------
__global__ void __launch_bounds__(512) gather_kernel(
    const __half* __restrict__ tab) {
    int lane = threadIdx.x & 31;
    int hw   = lane >> 4;          // half-warp: which edge of the pair
    int c    = lane & 15;          // channel group (4 channels)
    int node = blockIdx.x * 16 + (threadIdx.x >> 5);
    if (node >= NPAD) return;
    const __half* xth = (const __half*)g_xth;

    int beg = g_rowptr[node];
    int end = g_rowptr[node + 1];
    float4 acc = make_float4(0.f, 0.f, 0.f, 0.f);

    for (int base = beg; base < end; base += 32) {
        int cnt = min(32, end - base);
        unsigned myrec = 0;
        if (lane < cnt) myrec = __ldg(&g_erec[base + lane]);

#pragma unroll 4
        for (int j = 0; j < cnt; j += 2) {
            int sl = j + hw;
            unsigned rec = __shfl_sync(0xffffffffu, myrec, sl);
            bool valid = sl < cnt;
            int s  = rec >> 16;
            int uq = rec & 0xffff;
            int i0 = uq >> 6;
            __half2 fr2 = __float2half2_rn((float)(uq & 63) * 0.015625f);

            uint2 t0 = __ldg((const uint2*)(tab + i0 * 64) + c);
            uint2 t1 = __ldg((const uint2*)(tab + (i0 + 1) * 64) + c);
            uint2 xv = __ldg((const uint2*)(xth + s * 64) + c);

            __half2 a0 = u_as_h2(t0.x), a1 = u_as_h2(t0.y);
            __half2 w0 = __hfma2(fr2, __hsub2(u_as_h2(t1.x), a0), a0);
            __half2 w1 = __hfma2(fr2, __hsub2(u_as_h2(t1.y), a1), a1);
            __half2 m0 = __hmul2(w0, u_as_h2(xv.x));
            __half2 m1 = __hmul2(w1, u_as_h2(xv.y));
            float2 f0 = __half22float2(m0);
            float2 f1 = __half22float2(m1);
            if (valid) {
                acc.x += f0.x; acc.y += f0.y;
                acc.z += f1.x; acc.w += f1.y;
            }
        }
    }
    acc.x += __shfl_xor_sync(0xffffffffu, acc.x, 16);
    acc.y += __shfl_xor_sync(0xffffffffu, acc.y, 16);
    acc.z += __shfl_xor_sync(0xffffffffu, acc.z, 16);
    acc.w += __shfl_xor_sync(0xffffffffu, acc.w, 16);
    if (hw == 0) {
        uint2 o;
        o.x = h2_as_u(__floats2half2_rn(acc.x, acc.y));
        o.y = h2_as_u(__floats2half2_rn(acc.z, acc.w));
        ((uint2*)g_aggh)[node * 16 + c] = o;
    }
}

extern "C" void kernel_launch(void* const* d_in, const int* in_sizes, int n_in,
                              void* d_out, int out_size) {
    const int*   z     = (const int*)  d_in[0];
    const float* pos   = (const float*)d_in[1];
    const int*   batch = (const int*)  d_in[2];
    const int*   eidx  = (const int*)  d_in[3];
    const float* emb   = (const float*)d_in[4];
    const float* mw1   = (const float*)d_in[5];
    const float* mb1   = (const float*)d_in[6];
    const float* mw2   = (const float*)d_in[7];
    const float* mb2   = (const float*)d_in[8];
    const float* l1w   = (const float*)d_in[9];
    const float* l2w   = (const float*)d_in[10];
    const float* l2b   = (const float*)d_in[11];
    const float* lw    = (const float*)d_in[12];
    const float* lb    = (const float*)d_in[13];
    const float* ow1   = (const float*)d_in[14];
    const float* ob1   = (const float*)d_in[15];
    const float* ow2   = (const float*)d_in[16];
    const float* ob2   = (const float*)d_in[17];
    float* out = (float*)d_out;

    __half2 *ptabh;
    __half *pwf;
    cudaGetSymbolAddress((void**)&ptabh, g_tabh);
    cudaGetSymbolAddress((void**)&pwf,   g_wfrag);

    static cudaStream_t s1 = nullptr;
    static cudaEvent_t ev0 = nullptr, ev1 = nullptr;
    if (!s1) {
        cudaStreamCreateWithFlags(&s1, cudaStreamNonBlocking);
        cudaEventCreateWithFlags(&ev0, cudaEventDisableTiming);
        cudaEventCreateWithFlags(&ev1, cudaEventDisableTiming);
    }

    // ---- fork side stream: weights/tables/init (independent of CSR) ----
    cudaEventRecord(ev0, 0);
    cudaStreamWaitEvent(s1, ev0, 0);
    {
        WConvPack p;
        for (int l = 0; l < NLAY; l++) {
            p.d[l]     = { l1w + l * HDIM * FDIM, HDIM, FDIM, l * 32768 };
            p.d[3 + l] = { l2w + l * FDIM * HDIM, FDIM, HDIM, l * 32768 + 8192 };
            p.d[6 + l] = { lw  + l * HDIM * HDIM, HDIM, HDIM, l * 32768 + 16384 };
        }
        p.d[9] = { ow1, HDIM, FDIM, 98304 };
        dim3 g(16, 10);
        wconv_kernel<<<g, 256, 0, s1>>>(p);
    }
    {
        dim3 g(TABN / 8, NLAY);
        build_tab_kernel<<<g, 256, 0, s1>>>(mw1, mb1, mw2, mb2);
    }
    init_xth_kernel<<<296, 256, 0, s1>>>(z, emb, (const ull*)pwf);
    cudaEventRecord(ev1, s1);

    // ---- main stream: CSR build ----
    zero2_kernel<<<(NPAD / 4 + 255) / 256, 256>>>(out);
    degree_kernel<<<(NEDGE + 255) / 256, 256>>>(eidx);
    part_sum_kernel<<<NCHUNK, SCAN_B>>>();
    spine_kernel<<<1, 128>>>();
    scan_write_kernel<<<NCHUNK, SCAN_B>>>();
    scatter_kernel<<<(NEDGE + 255) / 256, 256>>>(eidx, pos);

    // join
    cudaStreamWaitEvent(0, ev1, 0);

    const int NB = 296;
    const int GGB = (NPAD + 15) / 16;   // 3128 blocks x 512 thr (full occ)

    for (int l = 0; l < NLAY; l++) {
        gather_kernel<<<GGB, 512>>>((const __half*)(ptabh + l * TABN * 32));
        const ull* wfA = (const ull*)(pwf + l * 32768 + 8192);
        const ull* wfB = (const ull*)(pwf + l * 32768 + 16384);
        if (l < NLAY - 1) {
            const ull* wfC = (const ull*)(pwf + (l + 1) * 32768);
            node_phase_kernel<false><<<NB, 256>>>(
                l2b + l * HDIM, lb + l * HDIM, wfA, wfB, wfC,
                nullptr, nullptr, nullptr, nullptr, nullptr);
        } else {
            const ull* wfC = (const ull*)(pwf + 98304);
            node_phase_kernel<true><<<NB, 256>>>(
                l2b + l * HDIM, lb + l * HDIM, wfA, wfB, wfC,
                ob1, ow2, ob2, batch, out);
        }
    }
}

// round 16
// speedup vs baseline: 2.9299x; 1.0439x over previous
#include <cuda_runtime.h>
#include <cuda_fp16.h>
#include <math.h>

#define NATOMS 50000
#define NPAD   50048          // 64-node tiles (782 tiles)
#define NTILES (NPAD / 64)
#define NEDGE  1600000
#define HDIM   128
#define FDIM   64
#define GDIM   50
#define NLAY   3
#define NGRAPH 256
#define TABN   1024           // 1024 rows x 64ch fp16 = 128 KB (L2-resident)
#define DMAXV  8.6603f
#define TSTEP  (DMAXV / (TABN - 1))
#define TINV   ((TABN - 1) / DMAXV)

#define SCAN_B 512
#define NCHUNK ((NPAD + SCAN_B - 1) / SCAN_B)   // 98

typedef unsigned long long ull;

// ---- scratch (device globals; no allocation allowed) ----
__device__ float    g_h    [NPAD * HDIM];
__device__ __half2  g_xth  [NPAD * FDIM / 2];
__device__ __half2  g_aggh [NPAD * FDIM / 2];
__device__ __half2  g_tabh [NLAY * TABN * FDIM / 2];
__device__ int      g_deg  [NPAD];
__device__ int      g_rowptr[NPAD + 1];
__device__ int      g_cursor[NPAD];
__device__ int      g_part [NCHUNK];
__device__ unsigned g_erec [NEDGE];    // src<<16 | u fixed-point (10.6)
__device__ __half   g_wfrag[106496];

__device__ __forceinline__ float sspf(float x) {
    float sp = fmaxf(x, 0.0f) + log1pf(__expf(-fabsf(x)));
    return sp - 0.69314718055994531f;
}
__device__ __forceinline__ __half2 u_as_h2(unsigned u) {
    return *reinterpret_cast<__half2*>(&u);
}
__device__ __forceinline__ unsigned h2_as_u(__half2 h) {
    return *reinterpret_cast<unsigned*>(&h);
}
__device__ __forceinline__ unsigned smem_u32(const void* p) {
    return (unsigned)__cvta_generic_to_shared(p);
}

// ---- packed f32x2 helpers ----
__device__ __forceinline__ ull ffma2(ull a, ull b, ull c) {
    ull d;
    asm("fma.rn.f32x2 %0, %1, %2, %3;" : "=l"(d) : "l"(a), "l"(b), "l"(c));
    return d;
}
__device__ __forceinline__ ull pack2(float x, float y) {
    ull r;
    asm("mov.b64 %0, {%1, %2};" : "=l"(r) : "f"(x), "f"(y));
    return r;
}
__device__ __forceinline__ float2 unpack2(ull v) {
    float2 r;
    asm("mov.b64 {%0, %1}, %2;" : "=f"(r.x), "=f"(r.y) : "l"(v));
    return r;
}

// ---------------- fused zero: out + deg ----------------
__global__ void zero2_kernel(float* __restrict__ out) {
    int i = blockIdx.x * blockDim.x + threadIdx.x;
    if (i < NPAD / 4) ((float4*)g_deg)[i] = make_float4(0.f, 0.f, 0.f, 0.f);
    if (i < NGRAPH) out[i] = 0.f;
}

// ---------------- degree count (4 edges/thread) ----------------
__global__ void degree_kernel(const int* __restrict__ ei) {
    int i = blockIdx.x * blockDim.x + threadIdx.x;
    if (i >= NEDGE / 4) return;
    int4 t = __ldg((const int4*)(ei + NEDGE) + i);
    atomicAdd(&g_deg[t.x], 1);
    atomicAdd(&g_deg[t.y], 1);
    atomicAdd(&g_deg[t.z], 1);
    atomicAdd(&g_deg[t.w], 1);
}

// ---------------- CSR scan pieces ----------------
__global__ void __launch_bounds__(SCAN_B) part_sum_kernel() {
    __shared__ int sh[SCAN_B];
    int idx = blockIdx.x * SCAN_B + threadIdx.x;
    int v = (idx < NPAD) ? g_deg[idx] : 0;
    sh[threadIdx.x] = v;
    __syncthreads();
    for (int s = SCAN_B / 2; s > 0; s >>= 1) {
        if (threadIdx.x < s) sh[threadIdx.x] += sh[threadIdx.x + s];
        __syncthreads();
    }
    if (threadIdx.x == 0) g_part[blockIdx.x] = sh[0];
}

__global__ void spine_kernel() {
    __shared__ int swp[4];
    int t = threadIdx.x;
    int lane = t & 31, w = t >> 5;
    int v = (t < NCHUNK) ? g_part[t] : 0;
    int s = v;
#pragma unroll
    for (int off = 1; off < 32; off <<= 1) {
        int n = __shfl_up_sync(0xffffffffu, s, off);
        if (lane >= off) s += n;
    }
    if (lane == 31) swp[w] = s;
    __syncthreads();
    if (t < 4) {
        int x = swp[t];
#pragma unroll
        for (int off = 1; off < 4; off <<= 1) {
            int n = __shfl_up_sync(0xfu, x, off);
            if (t >= off) x += n;
        }
        swp[t] = x;
    }
    __syncthreads();
    int excl = s - v + (w > 0 ? swp[w - 1] : 0);
    if (t < NCHUNK) g_part[t] = excl;
    if (t == 0) g_rowptr[NPAD] = NEDGE;
}

__global__ void __launch_bounds__(SCAN_B) scan_write_kernel() {
    __shared__ int sh[SCAN_B];
    int idx = blockIdx.x * SCAN_B + threadIdx.x;
    int own = (idx < NPAD) ? g_deg[idx] : 0;
    sh[threadIdx.x] = own;
    __syncthreads();
    for (int s = 1; s < SCAN_B; s <<= 1) {
        int v = (threadIdx.x >= s) ? sh[threadIdx.x - s] : 0;
        __syncthreads();
        sh[threadIdx.x] += v;
        __syncthreads();
    }
    if (idx < NPAD) {
        int excl = g_part[blockIdx.x] + sh[threadIdx.x] - own;
        g_rowptr[idx] = excl;
        g_cursor[idx] = excl;
    }
}

// ---------------- CSR scatter: pack src(16b) | u(10.6 fixed) ------------
__global__ void scatter_kernel(const int* __restrict__ ei,
                               const float* __restrict__ pos) {
    int e = blockIdx.x * blockDim.x + threadIdx.x;
    if (e >= NEDGE) return;
    int s = __ldg(ei + e);
    int t = __ldg(ei + NEDGE + e);
    float dx = __ldg(pos + s * 3 + 0) - __ldg(pos + t * 3 + 0);
    float dy = __ldg(pos + s * 3 + 1) - __ldg(pos + t * 3 + 1);
    float dz = __ldg(pos + s * 3 + 2) - __ldg(pos + t * 3 + 2);
    float u = sqrtf(dx * dx + dy * dy + dz * dz) * TINV;
    int uq = min((int)(u * 64.0f), (TABN - 1) * 64 - 1);   // i0 <= TABN-2
    int slot = atomicAdd(&g_cursor[t], 1);
    g_erec[slot] = ((unsigned)s << 16) | (unsigned)uq;
}

// ---------------- filter lookup tables ----------------------------------
__global__ void __launch_bounds__(256) build_tab_kernel(
    const float* __restrict__ mw1, const float* __restrict__ mb1,
    const float* __restrict__ mw2, const float* __restrict__ mb2) {
    int layer = blockIdx.y;
    __shared__ float s_w1[GDIM * FDIM];
    __shared__ float s_w2[FDIM * FDIM];
    __shared__ float s_b1[FDIM], s_b2[FDIM];
    __shared__ float s_g[8][64];
    __shared__ float s_act[8][FDIM];

    int t = threadIdx.x;
    for (int i = t; i < GDIM * FDIM; i += 256)
        s_w1[i] = __ldg(mw1 + layer * GDIM * FDIM + i);
    for (int i = t; i < FDIM * FDIM; i += 256)
        s_w2[i] = __ldg(mw2 + layer * FDIM * FDIM + i);
    if (t < FDIM) {
        s_b1[t] = __ldg(mb1 + layer * FDIM + t);
        s_b2[t] = __ldg(mb2 + layer * FDIM + t);
    }
    __syncthreads();

    int wl = t >> 5, lane = t & 31;
    const float offstep = 10.0f / 49.0f;
    const float coeff   = -0.5f / (offstep * offstep);

    for (int ti = blockIdx.x * 8 + wl; ti < TABN; ti += gridDim.x * 8) {
        float dv = ti * TSTEP;
        for (int g = lane; g < GDIM; g += 32) {
            float x = dv - g * offstep;
            s_g[wl][g] = expf(coeff * x * x);
        }
        __syncwarp();

        ull acc = pack2(s_b1[2 * lane], s_b1[2 * lane + 1]);
        for (int g = 0; g < GDIM; g++) {
            float e = s_g[wl][g];
            ull wv = ((const ull*)(s_w1 + g * FDIM))[lane];
            acc = ffma2(pack2(e, e), wv, acc);
        }
        float2 a = unpack2(acc);
        s_act[wl][2 * lane]     = sspf(a.x);
        s_act[wl][2 * lane + 1] = sspf(a.y);
        __syncwarp();

        ull acc2 = pack2(s_b2[2 * lane], s_b2[2 * lane + 1]);
        for (int f = 0; f < FDIM; f++) {
            float tv = s_act[wl][f];
            ull wv = ((const ull*)(s_w2 + f * FDIM))[lane];
            acc2 = ffma2(pack2(tv, tv), wv, acc2);
        }
        float C = 0.5f * (cosf(dv * 3.14159265358979323846f / 10.0f) + 1.0f);
        float2 c2 = unpack2(acc2);
        g_tabh[(layer * TABN + ti) * 32 + lane] =
            __floats2half2_rn(c2.x * C, c2.y * C);
        __syncwarp();
    }
}

// ---------------- weight -> mma B-fragment converter --------------------
struct WConvDesc { const float* src; int ind; int outd; int dstoff; };
struct WConvPack { WConvDesc d[10]; };

__global__ void wconv_kernel(WConvPack p) {
    WConvDesc dd = p.d[blockIdx.y];
    int total = dd.ind * dd.outd / 4;
    int u = blockIdx.x * blockDim.x + threadIdx.x;
    if (u >= total) return;
    int lane = u & 31;
    int ot8  = dd.outd >> 3;
    int nt   = (u >> 5) % ot8;
    int ks   = (u >> 5) / ot8;
    int n  = nt * 8 + (lane >> 2);
    int k0 = ks * 16 + (lane & 3) * 2;
    const float* s = dd.src;
    __half2 lo = __floats2half2_rn(s[k0 * dd.outd + n], s[(k0 + 1) * dd.outd + n]);
    __half2 hi = __floats2half2_rn(s[(k0 + 8) * dd.outd + n], s[(k0 + 9) * dd.outd + n]);
    __half2* dst = (__half2*)(g_wfrag + dd.dstoff + u * 4);
    dst[0] = lo;
    dst[1] = hi;
}

// ---------------- one MMA stage (64-node tile) --------------------------
template <int IN, int OUT, bool ACT, bool RESID>
__device__ __forceinline__ void stage_mma(
    const __half* sIn, __half* sOut, int tile,
    float* gF, __half2* gH, const ull* wf, const float* bias_p) {
    constexpr int NG   = OUT / 32;
    constexpr int MT   = (NG == 4) ? 2 : 1;
    constexpr int KS   = IN / 16;
    constexpr int ISTR = IN + 8;
    constexpr int OSTR = OUT + 8;

    int t = threadIdx.x, lane = t & 31, w = t >> 5;
    int ng = w % NG, mg = w / NG;

    unsigned bf[4 * KS * 2];
#pragma unroll
    for (int nt = 0; nt < 4; nt++)
#pragma unroll
        for (int ks = 0; ks < KS; ks++) {
            ull v = __ldg(wf + (ks * (OUT / 8) + ng * 4 + nt) * 32 + lane);
            bf[(nt * KS + ks) * 2]     = (unsigned)(v & 0xffffffffu);
            bf[(nt * KS + ks) * 2 + 1] = (unsigned)(v >> 32);
        }
    float2 bs[4];
#pragma unroll
    for (int nt = 0; nt < 4; nt++) {
        int c = ng * 32 + nt * 8 + (lane & 3) * 2;
        bs[nt] = bias_p ? make_float2(__ldg(bias_p + c), __ldg(bias_p + c + 1))
                        : make_float2(0.f, 0.f);
    }

    int grp    = lane >> 3;
    int arow_l = (lane & 7) + ((grp & 1) << 3);
    int acolh  = (grp >> 1) << 3;

#pragma unroll
    for (int mt = 0; mt < MT; mt++) {
        int mrow = mg * (MT * 16) + mt * 16;
        float acc[4][4];
#pragma unroll
        for (int nt = 0; nt < 4; nt++) {
            acc[nt][0] = bs[nt].x; acc[nt][1] = bs[nt].y;
            acc[nt][2] = bs[nt].x; acc[nt][3] = bs[nt].y;
        }
        unsigned abase = smem_u32(sIn + (mrow + arow_l) * ISTR + acolh);
#pragma unroll
        for (int ks = 0; ks < KS; ks++) {
            unsigned a0, a1, a2, a3;
            asm volatile(
                "ldmatrix.sync.aligned.m8n8.x4.shared.b16 {%0,%1,%2,%3}, [%4];"
                : "=r"(a0), "=r"(a1), "=r"(a2), "=r"(a3)
                : "r"(abase + ks * 32));
#pragma unroll
            for (int nt = 0; nt < 4; nt++) {
                asm volatile(
                    "mma.sync.aligned.m16n8k16.row.col.f32.f16.f16.f32 "
                    "{%0,%1,%2,%3}, {%4,%5,%6,%7}, {%8,%9}, {%0,%1,%2,%3};"
                    : "+f"(acc[nt][0]), "+f"(acc[nt][1]),
                      "+f"(acc[nt][2]), "+f"(acc[nt][3])
                    : "r"(a0), "r"(a1), "r"(a2), "r"(a3),
                      "r"(bf[(nt * KS + ks) * 2]),
                      "r"(bf[(nt * KS + ks) * 2 + 1]));
            }
        }
        int rl = mrow + (lane >> 2);
        int r0 = tile * 64 + rl;
        int cb = ng * 32 + (lane & 3) * 2;
#pragma unroll
        for (int nt = 0; nt < 4; nt++) {
            int col = cb + nt * 8;
            float2 v0 = make_float2(acc[nt][0], acc[nt][1]);
            float2 v1 = make_float2(acc[nt][2], acc[nt][3]);
            if (ACT) {
                v0.x = sspf(v0.x); v0.y = sspf(v0.y);
                v1.x = sspf(v1.x); v1.y = sspf(v1.y);
            }
            if (RESID) {
                float2 p0 = *(const float2*)(gF + r0 * OUT + col);
                float2 p1 = *(const float2*)(gF + (r0 + 8) * OUT + col);
                v0.x += p0.x; v0.y += p0.y;
                v1.x += p1.x; v1.y += p1.y;
            }
            if (gF) {
                *(float2*)(gF + r0 * OUT + col)       = v0;
                *(float2*)(gF + (r0 + 8) * OUT + col) = v1;
            }
            if (sOut) {
                *(__half2*)(sOut + rl * OSTR + col)       = __floats2half2_rn(v0.x, v0.y);
                *(__half2*)(sOut + (rl + 8) * OSTR + col) = __floats2half2_rn(v1.x, v1.y);
            }
            if (gH) {
                gH[r0 * (OUT / 2) + col / 2]       = __floats2half2_rn(v0.x, v0.y);
                gH[(r0 + 8) * (OUT / 2) + col / 2] = __floats2half2_rn(v1.x, v1.y);
            }
        }
    }
}

// ---------------- init: h = emb[z], xth = h @ l1w[0] --------------------
__global__ void __launch_bounds__(256, 2) init_xth_kernel(
    const int* __restrict__ z, const float* __restrict__ emb,
    const ull* __restrict__ wfC) {
    __shared__ __half bufH[64 * 136];
    int t = threadIdx.x;
    for (int tile = blockIdx.x; tile < NTILES; tile += gridDim.x) {
        for (int i = t; i < 64 * 32; i += 256) {
            int row = i >> 5, c = i & 31;
            int n = tile * 64 + row;
            float4 v = make_float4(0.f, 0.f, 0.f, 0.f);
            if (n < NATOMS) v = ((const float4*)emb)[__ldg(z + n) * 32 + c];
            ((float4*)g_h)[n * 32 + c] = v;
            __half2* d = (__half2*)(bufH + row * 136 + c * 4);
            d[0] = __floats2half2_rn(v.x, v.y);
            d[1] = __floats2half2_rn(v.z, v.w);
        }
        __syncthreads();
        stage_mma<128, 64, false, false>(bufH, nullptr, tile, nullptr,
                                         g_xth, wfC, nullptr);
        __syncthreads();
    }
}

// ---------------- node phase ----------------
template <bool LAST>
__global__ void __launch_bounds__(256, 2) node_phase_kernel(
    const float* __restrict__ l2b_l, const float* __restrict__ lb_l,
    const ull* __restrict__ wfA, const ull* __restrict__ wfB,
    const ull* __restrict__ wfC,
    const float* __restrict__ ob1, const float* __restrict__ ow2,
    const float* __restrict__ ob2, const int* __restrict__ batch,
    float* __restrict__ out) {
    __shared__ __half bufA[64 * 72];
    __shared__ __half bufT[64 * 136];
    __shared__ __half bufH[64 * 136];

    int t = threadIdx.x, lane = t & 31, w = t >> 5;
    float2 w2v = LAST ? *(const float2*)(ow2 + lane * 2) : make_float2(0.f, 0.f);
    float ob2v = LAST ? __ldg(ob2) : 0.f;

    for (int tile = blockIdx.x; tile < NTILES; tile += gridDim.x) {
        const uint4* src = (const uint4*)(g_aggh + tile * 64 * 32);
        for (int i = t; i < 64 * 8; i += 256) {
            int row = i >> 3, c8 = i & 7;
            *(uint4*)(bufA + row * 72 + c8 * 8) = src[i];
        }
        __syncthreads();
        stage_mma<64, 128, true, false>(bufA, bufT, tile, nullptr, nullptr,
                                        wfA, l2b_l);
        __syncthreads();
        stage_mma<128, 128, false, true>(bufT, bufH, tile, g_h, nullptr,
                                         wfB, lb_l);
        __syncthreads();
        if (!LAST) {
            stage_mma<128, 64, false, false>(bufH, nullptr, tile, nullptr,
                                             g_xth, wfC, nullptr);
        } else {
            stage_mma<128, 64, true, false>(bufH, bufA, tile, nullptr,
                                            nullptr, wfC, ob1);
            __syncthreads();
#pragma unroll
            for (int i = 0; i < 8; i++) {
                int rl = w * 8 + i;
                int n  = tile * 64 + rl;
                if (n < NATOMS) {
                    float2 f = __half22float2(
                        *(const __half2*)(bufA + rl * 72 + lane * 2));
                    float s = f.x * w2v.x + f.y * w2v.y;
#pragma unroll
                    for (int off = 16; off; off >>= 1)
                        s += __shfl_down_sync(0xffffffffu, s, off);
                    if (lane == 0)
                        atomicAdd(out + __ldg(batch + n), s + ob2v);
                }
            }
        }
        __syncthreads();
    }
}

// ---------------- gather: 4 edges/iter, 8 lanes/edge, uint4 loads -------
__global__ void __launch_bounds__(512) gather_kernel(
    const __half* __restrict__ tab) {
    int lane = threadIdx.x & 31;
    int eg   = lane >> 3;          // edge group 0..3
    int c    = lane & 7;           // channel octet (8 channels = 16 B)
    int node = blockIdx.x * 16 + (threadIdx.x >> 5);
    if (node >= NPAD) return;
    const __half* xth = (const __half*)g_xth;

    int beg = g_rowptr[node];
    int end = g_rowptr[node + 1];
    float acc[8];
#pragma unroll
    for (int i = 0; i < 8; i++) acc[i] = 0.f;

    for (int base = beg; base < end; base += 32) {
        int cnt = min(32, end - base);
        unsigned myrec = 0;
        if (lane < cnt) myrec = __ldg(&g_erec[base + lane]);

#pragma unroll 2
        for (int j = 0; j < cnt; j += 4) {
            int sl = j + eg;
            unsigned rec = __shfl_sync(0xffffffffu, myrec, sl);
            bool valid = sl < cnt;
            int s  = rec >> 16;
            int uq = rec & 0xffff;
            int i0 = uq >> 6;
            __half2 fr2 = __float2half2_rn((float)(uq & 63) * 0.015625f);

            uint4 t0 = __ldg((const uint4*)(tab + i0 * 64) + c);
            uint4 t1 = __ldg((const uint4*)(tab + (i0 + 1) * 64) + c);
            uint4 xv = __ldg((const uint4*)(xth + s * 64) + c);

            __half2 a0 = u_as_h2(t0.x), a1 = u_as_h2(t0.y);
            __half2 a2 = u_as_h2(t0.z), a3 = u_as_h2(t0.w);
            __half2 m0 = __hmul2(__hfma2(fr2, __hsub2(u_as_h2(t1.x), a0), a0),
                                 u_as_h2(xv.x));
            __half2 m1 = __hmul2(__hfma2(fr2, __hsub2(u_as_h2(t1.y), a1), a1),
                                 u_as_h2(xv.y));
            __half2 m2 = __hmul2(__hfma2(fr2, __hsub2(u_as_h2(t1.z), a2), a2),
                                 u_as_h2(xv.z));
            __half2 m3 = __hmul2(__hfma2(fr2, __hsub2(u_as_h2(t1.w), a3), a3),
                                 u_as_h2(xv.w));
            float2 f0 = __half22float2(m0);
            float2 f1 = __half22float2(m1);
            float2 f2 = __half22float2(m2);
            float2 f3 = __half22float2(m3);
            if (valid) {
                acc[0] += f0.x; acc[1] += f0.y;
                acc[2] += f1.x; acc[3] += f1.y;
                acc[4] += f2.x; acc[5] += f2.y;
                acc[6] += f3.x; acc[7] += f3.y;
            }
        }
    }
    // combine 4 edge groups (same channels, different edges)
#pragma unroll
    for (int i = 0; i < 8; i++) {
        acc[i] += __shfl_xor_sync(0xffffffffu, acc[i], 8);
        acc[i] += __shfl_xor_sync(0xffffffffu, acc[i], 16);
    }
    if (eg == 0) {
        uint4 o;
        o.x = h2_as_u(__floats2half2_rn(acc[0], acc[1]));
        o.y = h2_as_u(__floats2half2_rn(acc[2], acc[3]));
        o.z = h2_as_u(__floats2half2_rn(acc[4], acc[5]));
        o.w = h2_as_u(__floats2half2_rn(acc[6], acc[7]));
        ((uint4*)g_aggh)[node * 8 + c] = o;
    }
}

extern "C" void kernel_launch(void* const* d_in, const int* in_sizes, int n_in,
                              void* d_out, int out_size) {
    const int*   z     = (const int*)  d_in[0];
    const float* pos   = (const float*)d_in[1];
    const int*   batch = (const int*)  d_in[2];
    const int*   eidx  = (const int*)  d_in[3];
    const float* emb   = (const float*)d_in[4];
    const float* mw1   = (const float*)d_in[5];
    const float* mb1   = (const float*)d_in[6];
    const float* mw2   = (const float*)d_in[7];
    const float* mb2   = (const float*)d_in[8];
    const float* l1w   = (const float*)d_in[9];
    const float* l2w   = (const float*)d_in[10];
    const float* l2b   = (const float*)d_in[11];
    const float* lw    = (const float*)d_in[12];
    const float* lb    = (const float*)d_in[13];
    const float* ow1   = (const float*)d_in[14];
    const float* ob1   = (const float*)d_in[15];
    const float* ow2   = (const float*)d_in[16];
    const float* ob2   = (const float*)d_in[17];
    float* out = (float*)d_out;

    __half2 *ptabh;
    __half *pwf;
    cudaGetSymbolAddress((void**)&ptabh, g_tabh);
    cudaGetSymbolAddress((void**)&pwf,   g_wfrag);

    static cudaStream_t s1 = nullptr;
    static cudaEvent_t ev0 = nullptr, ev1 = nullptr;
    if (!s1) {
        cudaStreamCreateWithFlags(&s1, cudaStreamNonBlocking);
        cudaEventCreateWithFlags(&ev0, cudaEventDisableTiming);
        cudaEventCreateWithFlags(&ev1, cudaEventDisableTiming);
    }

    // ---- fork side stream: weights/tables/init (independent of CSR) ----
    cudaEventRecord(ev0, 0);
    cudaStreamWaitEvent(s1, ev0, 0);
    {
        WConvPack p;
        for (int l = 0; l < NLAY; l++) {
            p.d[l]     = { l1w + l * HDIM * FDIM, HDIM, FDIM, l * 32768 };
            p.d[3 + l] = { l2w + l * FDIM * HDIM, FDIM, HDIM, l * 32768 + 8192 };
            p.d[6 + l] = { lw  + l * HDIM * HDIM, HDIM, HDIM, l * 32768 + 16384 };
        }
        p.d[9] = { ow1, HDIM, FDIM, 98304 };
        dim3 g(16, 10);
        wconv_kernel<<<g, 256, 0, s1>>>(p);
    }
    {
        dim3 g(TABN / 8, NLAY);
        build_tab_kernel<<<g, 256, 0, s1>>>(mw1, mb1, mw2, mb2);
    }
    init_xth_kernel<<<296, 256, 0, s1>>>(z, emb, (const ull*)pwf);
    cudaEventRecord(ev1, s1);

    // ---- main stream: CSR build ----
    zero2_kernel<<<(NPAD / 4 + 255) / 256, 256>>>(out);
    degree_kernel<<<(NEDGE / 4 + 255) / 256, 256>>>(eidx);
    part_sum_kernel<<<NCHUNK, SCAN_B>>>();
    spine_kernel<<<1, 128>>>();
    scan_write_kernel<<<NCHUNK, SCAN_B>>>();
    scatter_kernel<<<(NEDGE + 255) / 256, 256>>>(eidx, pos);

    // join
    cudaStreamWaitEvent(0, ev1, 0);

    const int NB = 296;
    const int GGB = (NPAD + 15) / 16;   // 3128 blocks x 512 thr (full occ)

    for (int l = 0; l < NLAY; l++) {
        gather_kernel<<<GGB, 512>>>((const __half*)(ptabh + l * TABN * 32));
        const ull* wfA = (const ull*)(pwf + l * 32768 + 8192);
        const ull* wfB = (const ull*)(pwf + l * 32768 + 16384);
        if (l < NLAY - 1) {
            const ull* wfC = (const ull*)(pwf + (l + 1) * 32768);
            node_phase_kernel<false><<<NB, 256>>>(
                l2b + l * HDIM, lb + l * HDIM, wfA, wfB, wfC,
                nullptr, nullptr, nullptr, nullptr, nullptr);
        } else {
            const ull* wfC = (const ull*)(pwf + 98304);
            node_phase_kernel<true><<<NB, 256>>>(
                l2b + l * HDIM, lb + l * HDIM, wfA, wfB, wfC,
                ob1, ow2, ob2, batch, out);
        }
    }
}